// round 1
// baseline (speedup 1.0000x reference)
#include <cuda_runtime.h>
#include <math.h>
#include <stdint.h>

#define B_   2
#define N_   1536
#define DIM_ 1536
#define H_   8
#define D_   64
#define P_   3071      // 2N-1
#define QT_  24        // N/64 tiles

// ---------------- device scratch (static allocation — no cudaMalloc) ----------------
__device__ float g_q[B_*H_*N_*D_];        // q * scale, [b][h][i][d]
__device__ float g_k[B_*H_*N_*D_];
__device__ float g_v[B_*H_*N_*D_];
__device__ float g_relk[H_*P_*D_];        // [h][p][d]
__device__ float g_att[B_*N_*H_*D_];      // [b][i][h*64+d]
__device__ unsigned char g_tact[B_*QT_*QT_];
__device__ int g_mtype;                   // 0=uint8 bool, 1=int32, 2=float32

// ---------------- mask dtype probe ----------------
__global__ void probe_kernel(const unsigned char* lm) {
    unsigned int w = *(const unsigned int*)lm;  // local_mask[0][0..] : first two elems are true
    int t;
    if ((w & 0xFFu) == 1u && ((w >> 8) & 0xFFu) == 1u) t = 0;   // packed bytes 01 01 ..
    else if (w == 1u) t = 1;                                     // int32 1
    else t = 2;                                                  // float32 1.0f (0x3F800000)
    g_mtype = t;
}

__device__ __forceinline__ bool rd_mask(const unsigned char* p, long idx, int mt) {
    if (mt == 0) return p[idx] != 0;
    if (mt == 1) return ((const int*)p)[idx] != 0;
    return ((const float*)p)[idx] != 0.0f;
}

// ---------------- tile-activity precompute ----------------
__global__ void tact_kernel(const unsigned char* __restrict__ lm,
                            const unsigned char* __restrict__ isg)
{
    int t  = blockIdx.x;
    int jt = t % QT_;
    int qt = (t / QT_) % QT_;
    int b  = t / (QT_*QT_);
    int i0 = qt*64, j0 = jt*64;
    int mt = g_mtype;
    int pred = 0;
    for (int idx = threadIdx.x; idx < 64*64; idx += blockDim.x) {
        int r = idx >> 6, c = idx & 63;
        pred |= rd_mask(lm, (long)(i0+r)*N_ + j0 + c, mt) ? 1 : 0;
    }
    for (int idx = threadIdx.x; idx < 64; idx += blockDim.x) {
        pred |= rd_mask(isg, (long)b*N_ + i0 + idx, mt) ? 1 : 0;
        pred |= rd_mask(isg, (long)b*N_ + j0 + idx, mt) ? 1 : 0;
    }
    int any = __syncthreads_or(pred);
    if (threadIdx.x == 0) g_tact[t] = (unsigned char)(any ? 1 : 0);
}

// ---------------- generic 64x64-tile fp32 GEMM ----------------
// mode 0/1/2: C = A@B scattered into g_q/g_k/g_v per-head layout (alpha = q scale)
// mode 3    : C scattered into g_relk [h][p][d]
// mode 4    : A = g_att (ignores A arg); C = A@Wo + bias -> Cout row-major [M x Bw]
__global__ __launch_bounds__(256)
void gemm_kernel(const float* __restrict__ A, const float* __restrict__ Bm,
                 const float* __restrict__ bias, float* __restrict__ Cout,
                 int M, int K, int Bw, int mode, float alpha)
{
    __shared__ float sA[16][65];
    __shared__ float sB[16][64];
    const int tx = threadIdx.x & 15, ty = threadIdx.x >> 4;
    const int m0 = blockIdx.x * 64, n0 = blockIdx.y * 64;
    const float* Ap = (mode == 4) ? (const float*)g_att : A;

    float acc[4][4];
    #pragma unroll
    for (int r = 0; r < 4; r++)
        #pragma unroll
        for (int c = 0; c < 4; c++) acc[r][c] = 0.f;

    for (int k0 = 0; k0 < K; k0 += 16) {
        #pragma unroll
        for (int l = 0; l < 4; l++) {
            int idx = threadIdx.x + l*256;
            int kk = idx & 15, m = idx >> 4;
            int gm = m0 + m;
            sA[kk][m] = (gm < M) ? Ap[(long)gm*K + k0 + kk] : 0.f;
        }
        #pragma unroll
        for (int l = 0; l < 4; l++) {
            int idx = threadIdx.x + l*256;
            int nc = idx & 63, kk = idx >> 6;
            sB[kk][nc] = Bm[(long)(k0+kk)*Bw + n0 + nc];
        }
        __syncthreads();
        #pragma unroll
        for (int kk = 0; kk < 16; kk++) {
            float a[4], b[4];
            #pragma unroll
            for (int r = 0; r < 4; r++) a[r] = sA[kk][ty + 16*r];
            #pragma unroll
            for (int c = 0; c < 4; c++) b[c] = sB[kk][tx + 16*c];
            #pragma unroll
            for (int r = 0; r < 4; r++)
                #pragma unroll
                for (int c = 0; c < 4; c++) acc[r][c] += a[r]*b[c];
        }
        __syncthreads();
    }

    #pragma unroll
    for (int r = 0; r < 4; r++) {
        int row = m0 + ty + 16*r;
        if (row >= M) continue;
        #pragma unroll
        for (int c = 0; c < 4; c++) {
            int col = n0 + tx + 16*c;
            float v = acc[r][c] * alpha;
            if (mode <= 2) {
                int b = row / N_, i = row - b*N_;
                int h = col >> 6, d = col & 63;
                float* dst = (mode == 0) ? g_q : (mode == 1) ? g_k : g_v;
                dst[(((long)(b*H_ + h))*N_ + i)*D_ + d] = v;
            } else if (mode == 3) {
                int h = col >> 6, d = col & 63;
                g_relk[((long)h*P_ + row)*D_ + d] = v;
            } else {
                Cout[(long)row*Bw + col] = v + bias[col];
            }
        }
    }
}

// ---------------- fused masked flash attention with relative-shift gather ----------------
// grid (QT_, B_*H_), 256 threads. 64 query rows per block, 64-key tiles, online softmax.
#define ATTN_SMEM ((64*65*3 + 64*64 + 127*65 + 64)*4 + 64*64)

__global__ __launch_bounds__(256)
void attn_kernel(const float* __restrict__ cb, const float* __restrict__ pb,
                 const unsigned char* __restrict__ lm, const unsigned char* __restrict__ isg)
{
    extern __shared__ float sm[];
    float* sQc  = sm;                       // 64*65  (q*scale + content bias)
    float* sK   = sQc + 64*65;              // 64*65
    float* sV   = sK  + 64*65;              // 64*64
    float* sR   = sV  + 64*64;              // 127*65 rel_k band
    float* sP   = sR  + 127*65;             // 64*65  probs staging
    float* sDlt = sP  + 64*65;              // 64     (pb - cb)
    unsigned char* sM = (unsigned char*)(sDlt + 64);   // 64*64 mask bytes
    __shared__ unsigned char sCg[64];

    const int qt = blockIdx.x;
    const int bh = blockIdx.y;
    const int b  = bh >> 3;
    const int h  = bh & 7;
    const int i0 = qt * 64;
    const int tid = threadIdx.x;
    const int tx = tid & 15, ty = tid >> 4;
    const int mt = g_mtype;

    const float* qb = g_q + ((long)(b*H_ + h))*N_*D_;
    const float* kb = g_k + ((long)(b*H_ + h))*N_*D_;
    const float* vb = g_v + ((long)(b*H_ + h))*N_*D_;
    const float* rb = g_relk + (long)h*P_*D_;

    for (int idx = tid; idx < 64*64; idx += 256) {
        int r = idx >> 6, d = idx & 63;
        sQc[r*65 + d] = qb[(long)(i0 + r)*D_ + d] + cb[h*D_ + d];
    }
    if (tid < 64) sDlt[tid] = pb[h*D_ + tid] - cb[h*D_ + tid];

    float o[4][4];
    float mrow[4], lrow[4];
    bool rowg[4];
    #pragma unroll
    for (int r = 0; r < 4; r++) {
        mrow[r] = -1e30f; lrow[r] = 0.f;
        rowg[r] = rd_mask(isg, (long)b*N_ + i0 + ty + 16*r, mt);
        #pragma unroll
        for (int c = 0; c < 4; c++) o[r][c] = 0.f;
    }

    const unsigned char* tact = &g_tact[(b*QT_ + qt)*QT_];

    for (int jt = 0; jt < QT_; jt++) {
        if (!tact[jt]) continue;           // uniform across block
        const int j0 = jt*64;
        __syncthreads();
        for (int idx = tid; idx < 64*64; idx += 256) {
            int r = idx >> 6, d = idx & 63;
            sK[r*65 + d] = kb[(long)(j0 + r)*D_ + d];
            sV[r*64 + d] = vb[(long)(j0 + r)*D_ + d];
        }
        const int p0 = j0 - i0 + (N_ - 1) - 63;   // rel band base; pp = c - r + 63
        for (int idx = tid; idx < 127*64; idx += 256) {
            int pp = idx >> 6, d = idx & 63;
            sR[pp*65 + d] = rb[(long)(p0 + pp)*D_ + d];
        }
        for (int idx = tid; idx < 64*64; idx += 256) {
            int r = idx >> 6, c = idx & 63;
            sM[idx] = rd_mask(lm, (long)(i0 + r)*N_ + j0 + c, mt) ? 1 : 0;
        }
        if (tid < 64) sCg[tid] = rd_mask(isg, (long)b*N_ + j0 + tid, mt) ? 1 : 0;
        __syncthreads();

        float lg[4][4];
        #pragma unroll
        for (int r = 0; r < 4; r++)
            #pragma unroll
            for (int c = 0; c < 4; c++) lg[r][c] = 0.f;

        const int rbase = tx - ty + 63;    // pp for (r,c): rbase + 16*(c-r)
        #pragma unroll 4
        for (int d = 0; d < 64; d++) {
            float a[4], bb[4], rr7[7];
            #pragma unroll
            for (int r = 0; r < 4; r++) a[r] = sQc[(ty + 16*r)*65 + d];
            float dlt = sDlt[d];
            #pragma unroll
            for (int c = 0; c < 4; c++) bb[c] = sK[(tx + 16*c)*65 + d];
            #pragma unroll
            for (int s = 0; s < 7; s++) rr7[s] = sR[(rbase + 16*(s-3))*65 + d];
            #pragma unroll
            for (int r = 0; r < 4; r++) {
                float ap = a[r] + dlt;
                #pragma unroll
                for (int c = 0; c < 4; c++)
                    lg[r][c] += a[r]*bb[c] + ap*rr7[c - r + 3];
            }
        }

        // mask + online softmax (rows of a ty-group live in one half-warp)
        #pragma unroll
        for (int r = 0; r < 4; r++) {
            int row = ty + 16*r;
            float tmax = -1e30f;
            #pragma unroll
            for (int c = 0; c < 4; c++) {
                int col = tx + 16*c;
                bool act = rowg[r] || sCg[col] || sM[row*64 + col];
                if (!act) lg[r][c] = -1e30f;
                tmax = fmaxf(tmax, lg[r][c]);
            }
            #pragma unroll
            for (int off = 8; off >= 1; off >>= 1)
                tmax = fmaxf(tmax, __shfl_xor_sync(0xffffffffu, tmax, off));
            float nm   = fmaxf(mrow[r], tmax);
            float corr = __expf(mrow[r] - nm);
            mrow[r] = nm;
            float ps = 0.f;
            #pragma unroll
            for (int c = 0; c < 4; c++) {
                float p = (lg[r][c] <= -1e29f) ? 0.f : __expf(lg[r][c] - nm);
                lg[r][c] = p; ps += p;
            }
            #pragma unroll
            for (int off = 8; off >= 1; off >>= 1)
                ps += __shfl_xor_sync(0xffffffffu, ps, off);
            lrow[r] = lrow[r]*corr + ps;
            #pragma unroll
            for (int c = 0; c < 4; c++) o[r][c] *= corr;
            #pragma unroll
            for (int c = 0; c < 4; c++) sP[row*65 + tx + 16*c] = lg[r][c];
        }
        __syncwarp();   // sP rows are produced+consumed within the same half-warp group

        #pragma unroll 4
        for (int c64 = 0; c64 < 64; c64++) {
            float pv[4], vv[4];
            #pragma unroll
            for (int r = 0; r < 4; r++) pv[r] = sP[(ty + 16*r)*65 + c64];
            #pragma unroll
            for (int c = 0; c < 4; c++) vv[c] = sV[c64*64 + tx + 16*c];
            #pragma unroll
            for (int r = 0; r < 4; r++)
                #pragma unroll
                for (int c = 0; c < 4; c++) o[r][c] += pv[r]*vv[c];
        }
    }

    #pragma unroll
    for (int r = 0; r < 4; r++) {
        float inv = 1.0f / lrow[r];
        #pragma unroll
        for (int c = 0; c < 4; c++)
            g_att[((long)b*N_ + i0 + ty + 16*r)*(H_*D_) + h*D_ + tx + 16*c] = o[r][c]*inv;
    }
}

// ---------------- launcher ----------------
extern "C" void kernel_launch(void* const* d_in, const int* in_sizes, int n_in,
                              void* d_out, int out_size)
{
    const float* x    = (const float*)d_in[0];
    const float* Wq   = (const float*)d_in[1];
    const float* Wk   = (const float*)d_in[2];
    const float* Wv   = (const float*)d_in[3];
    const float* Wrel = (const float*)d_in[4];
    const float* cb   = (const float*)d_in[5];   // rel_content_bias [1,8,1,64]
    const float* pb   = (const float*)d_in[6];   // rel_pos_bias
    const float* Wo   = (const float*)d_in[7];
    const float* bo   = (const float*)d_in[8];
    const float* pos  = (const float*)d_in[9];   // pos_embed [3071,192]
    const unsigned char* lmu = (const unsigned char*)d_in[10];
    const unsigned char* isg = (const unsigned char*)d_in[11];
    float* out = (float*)d_out;

    cudaFuncSetAttribute(attn_kernel, cudaFuncAttributeMaxDynamicSharedMemorySize, ATTN_SMEM);

    probe_kernel<<<1, 1>>>(lmu);

    // QKV projections: [3072,1536] @ [1536,512] each; q scaled by dk^-0.5
    gemm_kernel<<<dim3(48, 8), 256>>>(x,   Wq,   nullptr, nullptr, B_*N_, DIM_, 512, 0, 0.125f);
    gemm_kernel<<<dim3(48, 8), 256>>>(x,   Wk,   nullptr, nullptr, B_*N_, DIM_, 512, 1, 1.0f);
    gemm_kernel<<<dim3(48, 8), 256>>>(x,   Wv,   nullptr, nullptr, B_*N_, DIM_, 512, 2, 1.0f);
    // rel_k: [3071,192] @ [192,512]
    gemm_kernel<<<dim3(48, 8), 256>>>(pos, Wrel, nullptr, nullptr, P_, 192, 512, 3, 1.0f);

    tact_kernel<<<B_*QT_*QT_, 128>>>(lmu, isg);

    attn_kernel<<<dim3(QT_, B_*H_), 256, ATTN_SMEM>>>(cb, pb, lmu, isg);

    // output projection: [3072,512] @ [512,1536] + bo
    gemm_kernel<<<dim3(48, 24), 256>>>(nullptr, Wo, bo, out, B_*N_, H_*D_, 1536, 4, 1.0f);
}

// round 2
// speedup vs baseline: 1.2383x; 1.2383x over previous
#include <cuda_runtime.h>
#include <math.h>
#include <stdint.h>

#define B_   2
#define N_   1536
#define DIM_ 1536
#define H_   8
#define D_   64
#define P_   3071      // 2N-1
#define QT_  24        // N/64 tiles

// ---------------- device scratch (static allocation — no cudaMalloc) ----------------
__device__ float g_q[B_*H_*N_*D_];        // q * scale, [b][h][i][d]
__device__ float g_k[B_*H_*N_*D_];
__device__ float g_v[B_*H_*N_*D_];
__device__ float g_relk[H_*P_*D_];        // [h][p][d]
__device__ float g_att[B_*N_*H_*D_];      // [b][i][h*64+d]
__device__ unsigned char g_tact[B_*QT_*QT_];
__device__ int g_mtype;                   // 0=uint8 bool, 1=int32, 2=float32

// ---------------- mask dtype probe ----------------
__global__ void probe_kernel(const unsigned char* lm) {
    unsigned int w = *(const unsigned int*)lm;  // local_mask[0][0..] : first two elems are true
    int t;
    if ((w & 0xFFu) == 1u && ((w >> 8) & 0xFFu) == 1u) t = 0;   // packed bytes 01 01 ..
    else if (w == 1u) t = 1;                                     // int32 1
    else t = 2;                                                  // float32 1.0f
    g_mtype = t;
}

__device__ __forceinline__ bool rd_mask(const unsigned char* p, long idx, int mt) {
    if (mt == 0) return p[idx] != 0;
    if (mt == 1) return ((const int*)p)[idx] != 0;
    return ((const float*)p)[idx] != 0.0f;
}

// ---------------- tile-activity precompute ----------------
__global__ void tact_kernel(const unsigned char* __restrict__ lm,
                            const unsigned char* __restrict__ isg)
{
    int t  = blockIdx.x;
    int jt = t % QT_;
    int qt = (t / QT_) % QT_;
    int b  = t / (QT_*QT_);
    int i0 = qt*64, j0 = jt*64;
    int mt = g_mtype;
    int pred = 0;
    for (int idx = threadIdx.x; idx < 64*64; idx += blockDim.x) {
        int r = idx >> 6, c = idx & 63;
        pred |= rd_mask(lm, (long)(i0+r)*N_ + j0 + c, mt) ? 1 : 0;
    }
    for (int idx = threadIdx.x; idx < 64; idx += blockDim.x) {
        pred |= rd_mask(isg, (long)b*N_ + i0 + idx, mt) ? 1 : 0;
        pred |= rd_mask(isg, (long)b*N_ + j0 + idx, mt) ? 1 : 0;
    }
    int any = __syncthreads_or(pred);
    if (threadIdx.x == 0) g_tact[t] = (unsigned char)(any ? 1 : 0);
}

// ---------------- 128x128x16 double-buffered fp32 GEMM, 8x8 per thread ----------------
// mode 0: fused QKV: A=x [M,K], B selected from {Wq,Wk,Wv} by column block (each [K,512]);
//         C scattered into g_q/g_k/g_v per-head layout; q scaled by 0.125.
// mode 3: A=pos_embed [3071,192], B=Wrel [192,512]; C scattered to g_relk [h][p][d].
// mode 4: A=g_att [M,512], B=Wo [512,1536]; C = A@B + bias -> Cout row-major.
#define BM 128
#define BN 128
#define BK 16

__global__ __launch_bounds__(256)
void gemm128(const float* __restrict__ A, const float* __restrict__ B0,
             const float* __restrict__ B1, const float* __restrict__ B2,
             const float* __restrict__ bias, float* __restrict__ Cout,
             int M, int K, int mode)
{
    __shared__ float sA[2][BK][BM];
    __shared__ float sB[2][BK][BN];

    const int tid = threadIdx.x;
    const int m0 = blockIdx.x * BM;
    const int n0 = blockIdx.y * BN;

    // B matrix selection + strides
    const float* Bm;
    int Bs;        // row stride of B
    int nb;        // starting column within B
    if (mode == 0) {
        int sel = n0 >> 9;
        Bm = (sel == 0) ? B0 : (sel == 1) ? B1 : B2;
        Bs = 512; nb = n0 & 511;
    } else if (mode == 3) {
        Bm = B0; Bs = 512; nb = n0;
    } else {
        Bm = B0; Bs = 1536; nb = n0;
    }
    const float* Ap = (mode == 4) ? (const float*)g_att : A;

    // loader index maps
    const int ar  = tid & 63;          // A row within tile (and ar+64)
    const int ac4 = tid >> 6;          // A float4 col group: cols 4*ac4..
    const int br  = tid >> 5;          // B k-row (and br+8)
    const int bc4 = tid & 31;          // B float4 col group

    // compute fragment maps
    const int tx = tid & 15, ty = tid >> 4;

    float acc[8][8];
    #pragma unroll
    for (int r = 0; r < 8; r++)
        #pragma unroll
        for (int c = 0; c < 8; c++) acc[r][c] = 0.f;

    const int nk = K / BK;
    const long arow0 = (long)(m0 + ar);
    const long arow1 = (long)(m0 + ar + 64);
    const bool g0 = (m0 + ar)      < M;
    const bool g1 = (m0 + ar + 64) < M;

    // prologue: tile 0 -> buffer 0
    {
        float4 pa0 = g0 ? *(const float4*)&Ap[arow0*K + 4*ac4] : make_float4(0,0,0,0);
        float4 pa1 = g1 ? *(const float4*)&Ap[arow1*K + 4*ac4] : make_float4(0,0,0,0);
        float4 pb0 = *(const float4*)&Bm[(long)br*Bs      + nb + 4*bc4];
        float4 pb1 = *(const float4*)&Bm[(long)(br+8)*Bs  + nb + 4*bc4];
        sA[0][4*ac4+0][ar]    = pa0.x; sA[0][4*ac4+1][ar]    = pa0.y;
        sA[0][4*ac4+2][ar]    = pa0.z; sA[0][4*ac4+3][ar]    = pa0.w;
        sA[0][4*ac4+0][ar+64] = pa1.x; sA[0][4*ac4+1][ar+64] = pa1.y;
        sA[0][4*ac4+2][ar+64] = pa1.z; sA[0][4*ac4+3][ar+64] = pa1.w;
        *(float4*)&sB[0][br  ][4*bc4] = pb0;
        *(float4*)&sB[0][br+8][4*bc4] = pb1;
    }
    __syncthreads();

    for (int kt = 0; kt < nk; kt++) {
        const int cur = kt & 1;
        float4 pa0, pa1, pb0, pb1;
        const bool more = (kt + 1 < nk);
        if (more) {
            const int k0 = (kt + 1) * BK;
            pa0 = g0 ? *(const float4*)&Ap[arow0*K + k0 + 4*ac4] : make_float4(0,0,0,0);
            pa1 = g1 ? *(const float4*)&Ap[arow1*K + k0 + 4*ac4] : make_float4(0,0,0,0);
            pb0 = *(const float4*)&Bm[(long)(k0+br)*Bs     + nb + 4*bc4];
            pb1 = *(const float4*)&Bm[(long)(k0+br+8)*Bs   + nb + 4*bc4];
        }

        #pragma unroll
        for (int kk = 0; kk < BK; kk++) {
            float a[8], b[8];
            *(float4*)&a[0] = *(float4*)&sA[cur][kk][ty*4];
            *(float4*)&a[4] = *(float4*)&sA[cur][kk][64 + ty*4];
            *(float4*)&b[0] = *(float4*)&sB[cur][kk][tx*4];
            *(float4*)&b[4] = *(float4*)&sB[cur][kk][64 + tx*4];
            #pragma unroll
            for (int r = 0; r < 8; r++)
                #pragma unroll
                for (int c = 0; c < 8; c++) acc[r][c] += a[r]*b[c];
        }

        if (more) {
            const int nxt = cur ^ 1;
            sA[nxt][4*ac4+0][ar]    = pa0.x; sA[nxt][4*ac4+1][ar]    = pa0.y;
            sA[nxt][4*ac4+2][ar]    = pa0.z; sA[nxt][4*ac4+3][ar]    = pa0.w;
            sA[nxt][4*ac4+0][ar+64] = pa1.x; sA[nxt][4*ac4+1][ar+64] = pa1.y;
            sA[nxt][4*ac4+2][ar+64] = pa1.z; sA[nxt][4*ac4+3][ar+64] = pa1.w;
            *(float4*)&sB[nxt][br  ][4*bc4] = pb0;
            *(float4*)&sB[nxt][br+8][4*bc4] = pb1;
            __syncthreads();
        }
    }

    // epilogue
    #pragma unroll
    for (int rr = 0; rr < 8; rr++) {
        const int lrow = (rr < 4) ? (ty*4 + rr) : (64 + ty*4 + rr - 4);
        const int row = m0 + lrow;
        if (row >= M) continue;
        #pragma unroll
        for (int cg = 0; cg < 2; cg++) {
            const int lc = cg ? (64 + tx*4) : (tx*4);
            float4 v = make_float4(acc[rr][cg*4+0], acc[rr][cg*4+1],
                                   acc[rr][cg*4+2], acc[rr][cg*4+3]);
            if (mode == 0) {
                const int gc  = n0 + lc;
                const int sel = gc >> 9;
                const int pc  = gc & 511;
                const int h = pc >> 6, d = pc & 63;
                float* dst = (sel == 0) ? g_q : (sel == 1) ? g_k : g_v;
                if (sel == 0) { v.x *= 0.125f; v.y *= 0.125f; v.z *= 0.125f; v.w *= 0.125f; }
                const int bb = row / N_;
                const int ii = row - bb*N_;
                *(float4*)&dst[(((long)(bb*H_ + h))*N_ + ii)*D_ + d] = v;
            } else if (mode == 3) {
                const int pc = n0 + lc;
                const int h = pc >> 6, d = pc & 63;
                *(float4*)&g_relk[((long)h*P_ + row)*D_ + d] = v;
            } else {
                const float4 bv = *(const float4*)&bias[n0 + lc];
                v.x += bv.x; v.y += bv.y; v.z += bv.z; v.w += bv.w;
                *(float4*)&Cout[(long)row*1536 + n0 + lc] = v;
            }
        }
    }
}

// ---------------- fused masked flash attention with relative-shift gather ----------------
// grid (QT_, B_*H_), 256 threads. 64 query rows per block, 64-key tiles, online softmax.
#define ATTN_SMEM ((64*65*3 + 64*64 + 127*65 + 64)*4 + 64*64)

__global__ __launch_bounds__(256)
void attn_kernel(const float* __restrict__ cb, const float* __restrict__ pb,
                 const unsigned char* __restrict__ lm, const unsigned char* __restrict__ isg)
{
    extern __shared__ float sm[];
    float* sQc  = sm;                       // 64*65  (q*scale + content bias)
    float* sK   = sQc + 64*65;              // 64*65
    float* sV   = sK  + 64*65;              // 64*64
    float* sR   = sV  + 64*64;              // 127*65 rel_k band
    float* sP   = sR  + 127*65;             // 64*65  probs staging
    float* sDlt = sP  + 64*65;              // 64     (pb - cb)
    unsigned char* sM = (unsigned char*)(sDlt + 64);   // 64*64 mask bytes
    __shared__ unsigned char sCg[64];

    const int qt = blockIdx.x;
    const int bh = blockIdx.y;
    const int b  = bh >> 3;
    const int h  = bh & 7;
    const int i0 = qt * 64;
    const int tid = threadIdx.x;
    const int tx = tid & 15, ty = tid >> 4;
    const int mt = g_mtype;

    const float* qb = g_q + ((long)(b*H_ + h))*N_*D_;
    const float* kb = g_k + ((long)(b*H_ + h))*N_*D_;
    const float* vb = g_v + ((long)(b*H_ + h))*N_*D_;
    const float* rb = g_relk + (long)h*P_*D_;

    for (int idx = tid; idx < 64*64; idx += 256) {
        int r = idx >> 6, d = idx & 63;
        sQc[r*65 + d] = qb[(long)(i0 + r)*D_ + d] + cb[h*D_ + d];
    }
    if (tid < 64) sDlt[tid] = pb[h*D_ + tid] - cb[h*D_ + tid];

    float o[4][4];
    float mrow[4], lrow[4];
    bool rowg[4];
    #pragma unroll
    for (int r = 0; r < 4; r++) {
        mrow[r] = -1e30f; lrow[r] = 0.f;
        rowg[r] = rd_mask(isg, (long)b*N_ + i0 + ty + 16*r, mt);
        #pragma unroll
        for (int c = 0; c < 4; c++) o[r][c] = 0.f;
    }

    const unsigned char* tact = &g_tact[(b*QT_ + qt)*QT_];

    for (int jt = 0; jt < QT_; jt++) {
        if (!tact[jt]) continue;           // uniform across block
        const int j0 = jt*64;
        __syncthreads();
        for (int idx = tid; idx < 64*64; idx += 256) {
            int r = idx >> 6, d = idx & 63;
            sK[r*65 + d] = kb[(long)(j0 + r)*D_ + d];
            sV[r*64 + d] = vb[(long)(j0 + r)*D_ + d];
        }
        const int p0 = j0 - i0 + (N_ - 1) - 63;   // rel band base; pp = c - r + 63
        for (int idx = tid; idx < 127*64; idx += 256) {
            int pp = idx >> 6, d = idx & 63;
            sR[pp*65 + d] = rb[(long)(p0 + pp)*D_ + d];
        }
        for (int idx = tid; idx < 64*64; idx += 256) {
            int r = idx >> 6, c = idx & 63;
            sM[idx] = rd_mask(lm, (long)(i0 + r)*N_ + j0 + c, mt) ? 1 : 0;
        }
        if (tid < 64) sCg[tid] = rd_mask(isg, (long)b*N_ + j0 + tid, mt) ? 1 : 0;
        __syncthreads();

        float lg[4][4];
        #pragma unroll
        for (int r = 0; r < 4; r++)
            #pragma unroll
            for (int c = 0; c < 4; c++) lg[r][c] = 0.f;

        const int rbase = tx - ty + 63;    // pp for (r,c): rbase + 16*(c-r)
        #pragma unroll 4
        for (int d = 0; d < 64; d++) {
            float a[4], bb[4], rr7[7];
            #pragma unroll
            for (int r = 0; r < 4; r++) a[r] = sQc[(ty + 16*r)*65 + d];
            float dlt = sDlt[d];
            #pragma unroll
            for (int c = 0; c < 4; c++) bb[c] = sK[(tx + 16*c)*65 + d];
            #pragma unroll
            for (int s = 0; s < 7; s++) rr7[s] = sR[(rbase + 16*(s-3))*65 + d];
            #pragma unroll
            for (int r = 0; r < 4; r++) {
                float ap = a[r] + dlt;
                #pragma unroll
                for (int c = 0; c < 4; c++)
                    lg[r][c] += a[r]*bb[c] + ap*rr7[c - r + 3];
            }
        }

        // mask + online softmax (rows of a ty-group live in one half-warp)
        #pragma unroll
        for (int r = 0; r < 4; r++) {
            int row = ty + 16*r;
            float tmax = -1e30f;
            #pragma unroll
            for (int c = 0; c < 4; c++) {
                int col = tx + 16*c;
                bool act = rowg[r] || sCg[col] || sM[row*64 + col];
                if (!act) lg[r][c] = -1e30f;
                tmax = fmaxf(tmax, lg[r][c]);
            }
            #pragma unroll
            for (int off = 8; off >= 1; off >>= 1)
                tmax = fmaxf(tmax, __shfl_xor_sync(0xffffffffu, tmax, off));
            float nm   = fmaxf(mrow[r], tmax);
            float corr = __expf(mrow[r] - nm);
            mrow[r] = nm;
            float ps = 0.f;
            #pragma unroll
            for (int c = 0; c < 4; c++) {
                float p = (lg[r][c] <= -1e29f) ? 0.f : __expf(lg[r][c] - nm);
                lg[r][c] = p; ps += p;
            }
            #pragma unroll
            for (int off = 8; off >= 1; off >>= 1)
                ps += __shfl_xor_sync(0xffffffffu, ps, off);
            lrow[r] = lrow[r]*corr + ps;
            #pragma unroll
            for (int c = 0; c < 4; c++) o[r][c] *= corr;
            #pragma unroll
            for (int c = 0; c < 4; c++) sP[row*65 + tx + 16*c] = lg[r][c];
        }
        __syncwarp();   // sP rows are produced+consumed within the same half-warp group

        #pragma unroll 4
        for (int c64 = 0; c64 < 64; c64++) {
            float pv[4], vv[4];
            #pragma unroll
            for (int r = 0; r < 4; r++) pv[r] = sP[(ty + 16*r)*65 + c64];
            #pragma unroll
            for (int c = 0; c < 4; c++) vv[c] = sV[c64*64 + tx + 16*c];
            #pragma unroll
            for (int r = 0; r < 4; r++)
                #pragma unroll
                for (int c = 0; c < 4; c++) o[r][c] += pv[r]*vv[c];
        }
    }

    #pragma unroll
    for (int r = 0; r < 4; r++) {
        float inv = 1.0f / lrow[r];
        #pragma unroll
        for (int c = 0; c < 4; c++)
            g_att[((long)b*N_ + i0 + ty + 16*r)*(H_*D_) + h*D_ + tx + 16*c] = o[r][c]*inv;
    }
}

// ---------------- launcher ----------------
extern "C" void kernel_launch(void* const* d_in, const int* in_sizes, int n_in,
                              void* d_out, int out_size)
{
    const float* x    = (const float*)d_in[0];
    const float* Wq   = (const float*)d_in[1];
    const float* Wk   = (const float*)d_in[2];
    const float* Wv   = (const float*)d_in[3];
    const float* Wrel = (const float*)d_in[4];
    const float* cb   = (const float*)d_in[5];   // rel_content_bias [1,8,1,64]
    const float* pb   = (const float*)d_in[6];   // rel_pos_bias
    const float* Wo   = (const float*)d_in[7];
    const float* bo   = (const float*)d_in[8];
    const float* pos  = (const float*)d_in[9];   // pos_embed [3071,192]
    const unsigned char* lmu = (const unsigned char*)d_in[10];
    const unsigned char* isg = (const unsigned char*)d_in[11];
    float* out = (float*)d_out;

    cudaFuncSetAttribute(attn_kernel, cudaFuncAttributeMaxDynamicSharedMemorySize, ATTN_SMEM);

    probe_kernel<<<1, 1>>>(lmu);

    // fused QKV projection: [3072,1536] @ {Wq|Wk|Wv} -> 1536 cols total
    gemm128<<<dim3(24, 12), 256>>>(x, Wq, Wk, Wv, nullptr, nullptr, B_*N_, DIM_, 0);
    // rel_k: [3071,192] @ [192,512]
    gemm128<<<dim3(24, 4), 256>>>(pos, Wrel, nullptr, nullptr, nullptr, nullptr, P_, 192, 3);

    tact_kernel<<<B_*QT_*QT_, 128>>>(lmu, isg);

    attn_kernel<<<dim3(QT_, B_*H_), 256, ATTN_SMEM>>>(cb, pb, lmu, isg);

    // output projection: [3072,512] @ [512,1536] + bo
    gemm128<<<dim3(24, 12), 256>>>(nullptr, Wo, nullptr, nullptr, bo, out, B_*N_, 512, 4);
}

// round 4
// speedup vs baseline: 1.7048x; 1.3767x over previous
#include <cuda_runtime.h>
#include <cuda_bf16.h>
#include <math.h>
#include <stdint.h>

#define B_   2
#define N_   1536
#define DIM_ 1536
#define H_   8
#define D_   64
#define P_   3071      // 2N-1
#define QT_  24        // N/64 tiles

// ---------------- device scratch (static allocation — no cudaMalloc) ----------------
__device__ float g_q[B_*H_*N_*D_];        // q * scale, [b][h][i][d]
__device__ float g_k[B_*H_*N_*D_];
__device__ float g_v[B_*H_*N_*D_];
__device__ float g_relk[H_*P_*D_];        // [h][p][d]
__device__ float g_att[B_*N_*H_*D_];      // [b][i][h*64+d]
__device__ unsigned char g_tact[B_*QT_*QT_];
__device__ int g_mtype;                   // 0=uint8 bool, 1=int32, 2=float32

// bf16 split-precision staging
__device__ __nv_bfloat16 g_xh[B_*N_*DIM_];        // x hi  [3072][1536]
__device__ __nv_bfloat16 g_xl[B_*N_*DIM_];        // x lo
__device__ __nv_bfloat16 g_wh[1536*DIM_];         // QKV weights transposed [n=1536][k=1536] hi
__device__ __nv_bfloat16 g_wl[1536*DIM_];
__device__ __nv_bfloat16 g_woh[1536*512];         // Wo transposed [1536][512] hi
__device__ __nv_bfloat16 g_wol[1536*512];
__device__ __nv_bfloat16 g_ah[B_*N_*H_*D_];       // attention out hi [3072][512]
__device__ __nv_bfloat16 g_al[B_*N_*H_*D_];

// ---------------- small helpers ----------------
__device__ __forceinline__ uint32_t smem_to_u32(const void* p) {
    uint32_t a;
    asm("{ .reg .u64 t; cvta.to.shared.u64 t, %1; cvt.u32.u64 %0, t; }" : "=r"(a) : "l"(p));
    return a;
}
__device__ __forceinline__ void cp_async16(uint32_t saddr, const void* g) {
    asm volatile("cp.async.cg.shared.global [%0], [%1], 16;" :: "r"(saddr), "l"(g));
}
#define CP_COMMIT() asm volatile("cp.async.commit_group;" ::: "memory")
#define CP_WAIT0()  asm volatile("cp.async.wait_group 0;" ::: "memory")

__device__ __forceinline__ void mma_bf16(float* c, const uint32_t* a, const uint32_t* b) {
    asm volatile("mma.sync.aligned.m16n8k16.row.col.f32.bf16.bf16.f32 "
        "{%0,%1,%2,%3}, {%4,%5,%6,%7}, {%8,%9}, {%0,%1,%2,%3};"
        : "+f"(c[0]), "+f"(c[1]), "+f"(c[2]), "+f"(c[3])
        : "r"(a[0]), "r"(a[1]), "r"(a[2]), "r"(a[3]), "r"(b[0]), "r"(b[1]));
}
__device__ __forceinline__ uint32_t lds32(uint32_t addr) {
    uint32_t v;
    asm volatile("ld.shared.b32 %0, [%1];" : "=r"(v) : "r"(addr));
    return v;
}

// ---------------- mask dtype probe ----------------
__global__ void probe_kernel(const unsigned char* lm) {
    unsigned int w = *(const unsigned int*)lm;
    int t;
    if ((w & 0xFFu) == 1u && ((w >> 8) & 0xFFu) == 1u) t = 0;
    else if (w == 1u) t = 1;
    else t = 2;
    g_mtype = t;
}

__device__ __forceinline__ bool rd_mask(const unsigned char* p, long idx, int mt) {
    if (mt == 0) return p[idx] != 0;
    if (mt == 1) return ((const int*)p)[idx] != 0;
    return ((const float*)p)[idx] != 0.0f;
}

// ---------------- split-precision conversion kernels ----------------
__global__ void convA_kernel(const float* __restrict__ s, __nv_bfloat16* __restrict__ h,
                             __nv_bfloat16* __restrict__ l, int n4)
{
    int i = blockIdx.x*blockDim.x + threadIdx.x;
    if (i >= n4) return;
    float4 v = ((const float4*)s)[i];
    float a[4] = {v.x, v.y, v.z, v.w};
    __nv_bfloat16 hh[4], ll[4];
    #pragma unroll
    for (int j = 0; j < 4; j++) {
        hh[j] = __float2bfloat16(a[j]);
        ll[j] = __float2bfloat16(a[j] - __bfloat162float(hh[j]));
    }
    ((__nv_bfloat162*)h)[i*2+0] = __nv_bfloat162(hh[0], hh[1]);
    ((__nv_bfloat162*)h)[i*2+1] = __nv_bfloat162(hh[2], hh[3]);
    ((__nv_bfloat162*)l)[i*2+0] = __nv_bfloat162(ll[0], ll[1]);
    ((__nv_bfloat162*)l)[i*2+1] = __nv_bfloat162(ll[2], ll[3]);
}

// transpose+convert: src [R][C] f32 -> dst [C][R] bf16 hi/lo.  R,C multiples of 32.
__global__ void convT_kernel(const float* __restrict__ src, __nv_bfloat16* __restrict__ dh,
                             __nv_bfloat16* __restrict__ dl, int R, int C)
{
    __shared__ float t[32][33];
    int c0 = blockIdx.x*32, r0 = blockIdx.y*32;
    int tx = threadIdx.x & 31, ty = threadIdx.x >> 5;
    #pragma unroll
    for (int i = 0; i < 4; i++)
        t[ty + i*8][tx] = src[(long)(r0 + ty + i*8)*C + c0 + tx];
    __syncthreads();
    #pragma unroll
    for (int i = 0; i < 4; i++) {
        int c = c0 + ty + i*8, r = r0 + tx;
        float v = t[tx][ty + i*8];
        __nv_bfloat16 hv = __float2bfloat16(v);
        dh[(long)c*R + r] = hv;
        dl[(long)c*R + r] = __float2bfloat16(v - __bfloat162float(hv));
    }
}

// ---------------- tile-activity precompute ----------------
__global__ void tact_kernel(const unsigned char* __restrict__ lm,
                            const unsigned char* __restrict__ isg)
{
    int t  = blockIdx.x;
    int jt = t % QT_;
    int qt = (t / QT_) % QT_;
    int b  = t / (QT_*QT_);
    int i0 = qt*64, j0 = jt*64;
    int mt = g_mtype;
    int pred = 0;
    for (int idx = threadIdx.x; idx < 64*64; idx += blockDim.x) {
        int r = idx >> 6, c = idx & 63;
        pred |= rd_mask(lm, (long)(i0+r)*N_ + j0 + c, mt) ? 1 : 0;
    }
    for (int idx = threadIdx.x; idx < 64; idx += blockDim.x) {
        pred |= rd_mask(isg, (long)b*N_ + i0 + idx, mt) ? 1 : 0;
        pred |= rd_mask(isg, (long)b*N_ + j0 + idx, mt) ? 1 : 0;
    }
    int any = __syncthreads_or(pred);
    if (threadIdx.x == 0) g_tact[t] = (unsigned char)(any ? 1 : 0);
}

// ---------------- warp-MMA bf16 split-precision GEMM ----------------
// D[128x128] = A[128xK] @ B[128xK]^T  via (Ah,Bh)+(Ah,Bl)+(Al,Bh), fp32 accum.
// mode 0: scatter to g_q/g_k/g_v (q scaled); mode 1: Cout = D + bias.
// smem: per stage 4 tiles of [128][40] bf16 (40 = 32 data + 8 pad; 80B row stride).
#define TPAD   40
#define TBYTES (128*TPAD*2)          // 10240 per tile
#define STAGE  (4*TBYTES)            // 40960 per stage
#define WG_SMEM (2*STAGE)            // 81920

__global__ __launch_bounds__(256)
void wmma_gemm(const __nv_bfloat16* __restrict__ Ah, const __nv_bfloat16* __restrict__ Al,
               const __nv_bfloat16* __restrict__ Bh, const __nv_bfloat16* __restrict__ Bl,
               const float* __restrict__ bias, float* __restrict__ Cout, int K, int mode)
{
    extern __shared__ char smem[];
    const uint32_t sb = smem_to_u32(smem);
    const int tid = threadIdx.x;
    const int lane = tid & 31;
    const int wid = tid >> 5;
    const int warp_m = wid >> 2;          // 0..1  (64-row slab)
    const int warp_n = wid & 3;           // 0..3  (32-col slab)
    const int grp = lane >> 2;            // 0..7
    const int tig = lane & 3;             // 0..3
    const int m0 = blockIdx.x * 128, n0 = blockIdx.y * 128;

    const char* srcs[4] = {(const char*)Ah, (const char*)Al, (const char*)Bh, (const char*)Bl};
    const int rb[4] = {m0, m0, n0, n0};
    const long rowB = (long)K * 2;        // bytes per row

    // loader map: 2048 uint4 per stage, 8 per thread
    // i -> tile t = i>>9, r = (i>>2)&127, c = i&3
    auto issue_stage = [&](int kt, int st) {
        const uint32_t sbase = sb + st*STAGE;
        #pragma unroll
        for (int l = 0; l < 8; l++) {
            int i = tid + l*256;
            int t = i >> 9, r = (i >> 2) & 127, c = i & 3;
            const char* g = srcs[t] + (long)(rb[t] + r)*rowB + kt*64 + c*16;
            cp_async16(sbase + t*TBYTES + r*80 + c*16, g);
        }
        CP_COMMIT();
    };

    float acc[4][4][4];
    #pragma unroll
    for (int i = 0; i < 4; i++)
        #pragma unroll
        for (int j = 0; j < 4; j++)
            #pragma unroll
            for (int e = 0; e < 4; e++) acc[i][j][e] = 0.f;

    const int nk = K / 32;
    issue_stage(0, 0);

    for (int kt = 0; kt < nk; kt++) {
        CP_WAIT0();
        __syncthreads();
        if (kt + 1 < nk) issue_stage(kt + 1, (kt + 1) & 1);

        const uint32_t stg = sb + (kt & 1)*STAGE;
        const uint32_t aoffh = stg + 0*TBYTES;
        const uint32_t aoffl = stg + 1*TBYTES;
        const uint32_t boffh = stg + 2*TBYTES;
        const uint32_t boffl = stg + 3*TBYTES;

        #pragma unroll
        for (int ks = 0; ks < 2; ks++) {
            const uint32_t kb = ks*32 + tig*4;    // byte offset within row
            uint32_t bh[4][2], bl[4][2];
            #pragma unroll
            for (int j = 0; j < 4; j++) {
                uint32_t ro = (uint32_t)(warp_n*32 + j*8 + grp)*80 + kb;
                bh[j][0] = lds32(boffh + ro);      bh[j][1] = lds32(boffh + ro + 16);
                bl[j][0] = lds32(boffl + ro);      bl[j][1] = lds32(boffl + ro + 16);
            }
            #pragma unroll
            for (int i = 0; i < 4; i++) {
                uint32_t ro = (uint32_t)(warp_m*64 + i*16 + grp)*80 + kb;
                uint32_t ah[4], al[4];
                ah[0] = lds32(aoffh + ro);        ah[1] = lds32(aoffh + ro + 640);
                ah[2] = lds32(aoffh + ro + 16);   ah[3] = lds32(aoffh + ro + 656);
                al[0] = lds32(aoffl + ro);        al[1] = lds32(aoffl + ro + 640);
                al[2] = lds32(aoffl + ro + 16);   al[3] = lds32(aoffl + ro + 656);
                #pragma unroll
                for (int j = 0; j < 4; j++) {
                    mma_bf16(acc[i][j], ah, bh[j]);
                    mma_bf16(acc[i][j], ah, bl[j]);
                    mma_bf16(acc[i][j], al, bh[j]);
                }
            }
        }
        __syncthreads();
    }

    // epilogue: c0:(grp, 2tig) c1:(grp, 2tig+1) c2:(grp+8, 2tig) c3:(grp+8, 2tig+1)
    #pragma unroll
    for (int i = 0; i < 4; i++) {
        #pragma unroll
        for (int j = 0; j < 4; j++) {
            const int r0 = m0 + warp_m*64 + i*16 + grp;
            const int c0 = n0 + warp_n*32 + j*8 + 2*tig;
            #pragma unroll
            for (int half = 0; half < 2; half++) {
                const int row = r0 + half*8;
                const float v0 = acc[i][j][half*2 + 0];
                const float v1 = acc[i][j][half*2 + 1];
                if (mode == 1) {
                    Cout[(long)row*1536 + c0]     = v0 + bias[c0];
                    Cout[(long)row*1536 + c0 + 1] = v1 + bias[c0 + 1];
                } else {
                    const int sel = c0 >> 9, pc = c0 & 511;
                    const int h = pc >> 6, d = pc & 63;
                    float* dst = (sel == 0) ? g_q : (sel == 1) ? g_k : g_v;
                    const float sc = (sel == 0) ? 0.125f : 1.0f;
                    const int bb = (row >= N_) ? 1 : 0;
                    const int ii = row - bb*N_;
                    float* p = &dst[(((long)(bb*H_ + h))*N_ + ii)*D_ + d];
                    p[0] = v0*sc; p[1] = v1*sc;
                }
            }
        }
    }
}

// ---------------- fp32 SIMT GEMM (rel_k projection, K=192) ----------------
#define BM 128
#define BN 128
#define BK 16
__global__ __launch_bounds__(256)
void gemm128(const float* __restrict__ A, const float* __restrict__ B0,
             int M, int K)
{
    __shared__ float sA[2][BK][BM];
    __shared__ float sB[2][BK][BN];
    const int tid = threadIdx.x;
    const int m0 = blockIdx.x * BM;
    const int n0 = blockIdx.y * BN;
    const float* Bm = B0;
    const int Bs = 512, nb = n0;

    const int ar  = tid & 63;
    const int ac4 = tid >> 6;
    const int br  = tid >> 5;
    const int bc4 = tid & 31;
    const int tx = tid & 15, ty = tid >> 4;

    float acc[8][8];
    #pragma unroll
    for (int r = 0; r < 8; r++)
        #pragma unroll
        for (int c = 0; c < 8; c++) acc[r][c] = 0.f;

    const int nk = K / BK;
    const long arow0 = (long)(m0 + ar);
    const long arow1 = (long)(m0 + ar + 64);
    const bool g0 = (m0 + ar)      < M;
    const bool g1 = (m0 + ar + 64) < M;

    {
        float4 pa0 = g0 ? *(const float4*)&A[arow0*K + 4*ac4] : make_float4(0,0,0,0);
        float4 pa1 = g1 ? *(const float4*)&A[arow1*K + 4*ac4] : make_float4(0,0,0,0);
        float4 pb0 = *(const float4*)&Bm[(long)br*Bs      + nb + 4*bc4];
        float4 pb1 = *(const float4*)&Bm[(long)(br+8)*Bs  + nb + 4*bc4];
        sA[0][4*ac4+0][ar]    = pa0.x; sA[0][4*ac4+1][ar]    = pa0.y;
        sA[0][4*ac4+2][ar]    = pa0.z; sA[0][4*ac4+3][ar]    = pa0.w;
        sA[0][4*ac4+0][ar+64] = pa1.x; sA[0][4*ac4+1][ar+64] = pa1.y;
        sA[0][4*ac4+2][ar+64] = pa1.z; sA[0][4*ac4+3][ar+64] = pa1.w;
        *(float4*)&sB[0][br  ][4*bc4] = pb0;
        *(float4*)&sB[0][br+8][4*bc4] = pb1;
    }
    __syncthreads();

    for (int kt = 0; kt < nk; kt++) {
        const int cur = kt & 1;
        float4 pa0, pa1, pb0, pb1;
        const bool more = (kt + 1 < nk);
        if (more) {
            const int k0 = (kt + 1) * BK;
            pa0 = g0 ? *(const float4*)&A[arow0*K + k0 + 4*ac4] : make_float4(0,0,0,0);
            pa1 = g1 ? *(const float4*)&A[arow1*K + k0 + 4*ac4] : make_float4(0,0,0,0);
            pb0 = *(const float4*)&Bm[(long)(k0+br)*Bs     + nb + 4*bc4];
            pb1 = *(const float4*)&Bm[(long)(k0+br+8)*Bs   + nb + 4*bc4];
        }
        #pragma unroll
        for (int kk = 0; kk < BK; kk++) {
            float a[8], b[8];
            *(float4*)&a[0] = *(float4*)&sA[cur][kk][ty*4];
            *(float4*)&a[4] = *(float4*)&sA[cur][kk][64 + ty*4];
            *(float4*)&b[0] = *(float4*)&sB[cur][kk][tx*4];
            *(float4*)&b[4] = *(float4*)&sB[cur][kk][64 + tx*4];
            #pragma unroll
            for (int r = 0; r < 8; r++)
                #pragma unroll
                for (int c = 0; c < 8; c++) acc[r][c] += a[r]*b[c];
        }
        if (more) {
            const int nxt = cur ^ 1;
            sA[nxt][4*ac4+0][ar]    = pa0.x; sA[nxt][4*ac4+1][ar]    = pa0.y;
            sA[nxt][4*ac4+2][ar]    = pa0.z; sA[nxt][4*ac4+3][ar]    = pa0.w;
            sA[nxt][4*ac4+0][ar+64] = pa1.x; sA[nxt][4*ac4+1][ar+64] = pa1.y;
            sA[nxt][4*ac4+2][ar+64] = pa1.z; sA[nxt][4*ac4+3][ar+64] = pa1.w;
            *(float4*)&sB[nxt][br  ][4*bc4] = pb0;
            *(float4*)&sB[nxt][br+8][4*bc4] = pb1;
            __syncthreads();
        }
    }

    #pragma unroll
    for (int rr = 0; rr < 8; rr++) {
        const int lrow = (rr < 4) ? (ty*4 + rr) : (64 + ty*4 + rr - 4);
        const int row = m0 + lrow;
        if (row >= M) continue;
        #pragma unroll
        for (int cg = 0; cg < 2; cg++) {
            const int lc = cg ? (64 + tx*4) : (tx*4);
            float4 v = make_float4(acc[rr][cg*4+0], acc[rr][cg*4+1],
                                   acc[rr][cg*4+2], acc[rr][cg*4+3]);
            const int pc = n0 + lc;
            const int h = pc >> 6, d = pc & 63;
            *(float4*)&g_relk[((long)h*P_ + row)*D_ + d] = v;
        }
    }
}

// ---------------- fused masked flash attention with relative-shift gather ----------------
#define ATTN_SMEM ((64*65*3 + 64*64 + 127*65 + 64)*4 + 64*64)

__global__ __launch_bounds__(256)
void attn_kernel(const float* __restrict__ cb, const float* __restrict__ pb,
                 const unsigned char* __restrict__ lm, const unsigned char* __restrict__ isg)
{
    extern __shared__ float sm[];
    float* sQc  = sm;
    float* sK   = sQc + 64*65;
    float* sV   = sK  + 64*65;
    float* sR   = sV  + 64*64;
    float* sP   = sR  + 127*65;
    float* sDlt = sP  + 64*65;
    unsigned char* sM = (unsigned char*)(sDlt + 64);
    __shared__ unsigned char sCg[64];

    const int qt = blockIdx.x;
    const int bh = blockIdx.y;
    const int b  = bh >> 3;
    const int h  = bh & 7;
    const int i0 = qt * 64;
    const int tid = threadIdx.x;
    const int tx = tid & 15, ty = tid >> 4;
    const int mt = g_mtype;

    const float* qb = g_q + ((long)(b*H_ + h))*N_*D_;
    const float* kb = g_k + ((long)(b*H_ + h))*N_*D_;
    const float* vb = g_v + ((long)(b*H_ + h))*N_*D_;
    const float* rb = g_relk + (long)h*P_*D_;

    for (int idx = tid; idx < 64*64; idx += 256) {
        int r = idx >> 6, d = idx & 63;
        sQc[r*65 + d] = qb[(long)(i0 + r)*D_ + d] + cb[h*D_ + d];
    }
    if (tid < 64) sDlt[tid] = pb[h*D_ + tid] - cb[h*D_ + tid];

    float o[4][4];
    float mrow[4], lrow[4];
    bool rowg[4];
    #pragma unroll
    for (int r = 0; r < 4; r++) {
        mrow[r] = -1e30f; lrow[r] = 0.f;
        rowg[r] = rd_mask(isg, (long)b*N_ + i0 + ty + 16*r, mt);
        #pragma unroll
        for (int c = 0; c < 4; c++) o[r][c] = 0.f;
    }

    const unsigned char* tact = &g_tact[(b*QT_ + qt)*QT_];

    for (int jt = 0; jt < QT_; jt++) {
        if (!tact[jt]) continue;
        const int j0 = jt*64;
        __syncthreads();
        for (int idx = tid; idx < 64*64; idx += 256) {
            int r = idx >> 6, d = idx & 63;
            sK[r*65 + d] = kb[(long)(j0 + r)*D_ + d];
            sV[r*64 + d] = vb[(long)(j0 + r)*D_ + d];
        }
        const int p0 = j0 - i0 + (N_ - 1) - 63;
        for (int idx = tid; idx < 127*64; idx += 256) {
            int pp = idx >> 6, d = idx & 63;
            sR[pp*65 + d] = rb[(long)(p0 + pp)*D_ + d];
        }
        for (int idx = tid; idx < 64*64; idx += 256) {
            int r = idx >> 6, c = idx & 63;
            sM[idx] = rd_mask(lm, (long)(i0 + r)*N_ + j0 + c, mt) ? 1 : 0;
        }
        if (tid < 64) sCg[tid] = rd_mask(isg, (long)b*N_ + j0 + tid, mt) ? 1 : 0;
        __syncthreads();

        float lg[4][4];
        #pragma unroll
        for (int r = 0; r < 4; r++)
            #pragma unroll
            for (int c = 0; c < 4; c++) lg[r][c] = 0.f;

        const int rbase = tx - ty + 63;
        #pragma unroll 4
        for (int d = 0; d < 64; d++) {
            float a[4], bb[4], rr7[7];
            #pragma unroll
            for (int r = 0; r < 4; r++) a[r] = sQc[(ty + 16*r)*65 + d];
            float dlt = sDlt[d];
            #pragma unroll
            for (int c = 0; c < 4; c++) bb[c] = sK[(tx + 16*c)*65 + d];
            #pragma unroll
            for (int s = 0; s < 7; s++) rr7[s] = sR[(rbase + 16*(s-3))*65 + d];
            #pragma unroll
            for (int r = 0; r < 4; r++) {
                float ap = a[r] + dlt;
                #pragma unroll
                for (int c = 0; c < 4; c++)
                    lg[r][c] += a[r]*bb[c] + ap*rr7[c - r + 3];
            }
        }

        #pragma unroll
        for (int r = 0; r < 4; r++) {
            int row = ty + 16*r;
            float tmax = -1e30f;
            #pragma unroll
            for (int c = 0; c < 4; c++) {
                int col = tx + 16*c;
                bool act = rowg[r] || sCg[col] || sM[row*64 + col];
                if (!act) lg[r][c] = -1e30f;
                tmax = fmaxf(tmax, lg[r][c]);
            }
            #pragma unroll
            for (int off = 8; off >= 1; off >>= 1)
                tmax = fmaxf(tmax, __shfl_xor_sync(0xffffffffu, tmax, off));
            float nm   = fmaxf(mrow[r], tmax);
            float corr = __expf(mrow[r] - nm);
            mrow[r] = nm;
            float ps = 0.f;
            #pragma unroll
            for (int c = 0; c < 4; c++) {
                float p = (lg[r][c] <= -1e29f) ? 0.f : __expf(lg[r][c] - nm);
                lg[r][c] = p; ps += p;
            }
            #pragma unroll
            for (int off = 8; off >= 1; off >>= 1)
                ps += __shfl_xor_sync(0xffffffffu, ps, off);
            lrow[r] = lrow[r]*corr + ps;
            #pragma unroll
            for (int c = 0; c < 4; c++) o[r][c] *= corr;
            #pragma unroll
            for (int c = 0; c < 4; c++) sP[row*65 + tx + 16*c] = lg[r][c];
        }
        __syncwarp();

        #pragma unroll 4
        for (int c64 = 0; c64 < 64; c64++) {
            float pv[4], vv[4];
            #pragma unroll
            for (int r = 0; r < 4; r++) pv[r] = sP[(ty + 16*r)*65 + c64];
            #pragma unroll
            for (int c = 0; c < 4; c++) vv[c] = sV[c64*64 + tx + 16*c];
            #pragma unroll
            for (int r = 0; r < 4; r++)
                #pragma unroll
                for (int c = 0; c < 4; c++) o[r][c] += pv[r]*vv[c];
        }
    }

    #pragma unroll
    for (int r = 0; r < 4; r++) {
        float inv = 1.0f / lrow[r];
        #pragma unroll
        for (int c = 0; c < 4; c++)
            g_att[((long)b*N_ + i0 + ty + 16*r)*(H_*D_) + h*D_ + tx + 16*c] = o[r][c]*inv;
    }
}

// ---------------- launcher ----------------
extern "C" void kernel_launch(void* const* d_in, const int* in_sizes, int n_in,
                              void* d_out, int out_size)
{
    const float* x    = (const float*)d_in[0];
    const float* Wq   = (const float*)d_in[1];
    const float* Wk   = (const float*)d_in[2];
    const float* Wv   = (const float*)d_in[3];
    const float* Wrel = (const float*)d_in[4];
    const float* cb   = (const float*)d_in[5];
    const float* pb   = (const float*)d_in[6];
    const float* Wo   = (const float*)d_in[7];
    const float* bo   = (const float*)d_in[8];
    const float* pos  = (const float*)d_in[9];
    const unsigned char* lmu = (const unsigned char*)d_in[10];
    const unsigned char* isg = (const unsigned char*)d_in[11];
    float* out = (float*)d_out;

    cudaFuncSetAttribute(attn_kernel, cudaFuncAttributeMaxDynamicSharedMemorySize, ATTN_SMEM);
    cudaFuncSetAttribute(wmma_gemm, cudaFuncAttributeMaxDynamicSharedMemorySize, WG_SMEM);

    __nv_bfloat16 *xh_p, *xl_p, *wh_p, *wl_p, *woh_p, *wol_p, *ah_p, *al_p;
    cudaGetSymbolAddress((void**)&xh_p,  g_xh);
    cudaGetSymbolAddress((void**)&xl_p,  g_xl);
    cudaGetSymbolAddress((void**)&wh_p,  g_wh);
    cudaGetSymbolAddress((void**)&wl_p,  g_wl);
    cudaGetSymbolAddress((void**)&woh_p, g_woh);
    cudaGetSymbolAddress((void**)&wol_p, g_wol);
    cudaGetSymbolAddress((void**)&ah_p,  g_ah);
    cudaGetSymbolAddress((void**)&al_p,  g_al);
    float* att_p;
    cudaGetSymbolAddress((void**)&att_p, g_att);

    probe_kernel<<<1, 1>>>(lmu);

    // split-precision conversions
    convA_kernel<<<(B_*N_*DIM_/4 + 255)/256, 256>>>(x, xh_p, xl_p, B_*N_*DIM_/4);
    convT_kernel<<<dim3(512/32, DIM_/32), 256>>>(Wq, wh_p,              wl_p,              DIM_, 512);
    convT_kernel<<<dim3(512/32, DIM_/32), 256>>>(Wk, wh_p + 512L*DIM_,  wl_p + 512L*DIM_,  DIM_, 512);
    convT_kernel<<<dim3(512/32, DIM_/32), 256>>>(Wv, wh_p + 1024L*DIM_, wl_p + 1024L*DIM_, DIM_, 512);
    convT_kernel<<<dim3(1536/32, 512/32), 256>>>(Wo, woh_p, wol_p, 512, 1536);

    // QKV projection on tensor cores: [3072 x 1536] @ [1536 x 1536]
    wmma_gemm<<<dim3(24, 12), 256, WG_SMEM>>>(xh_p, xl_p, wh_p, wl_p,
                                              nullptr, nullptr, DIM_, 0);

    // rel_k projection (fp32 SIMT): [3071 x 192] @ [192 x 512]
    gemm128<<<dim3(24, 4), 256>>>(pos, Wrel, P_, 192);

    tact_kernel<<<B_*QT_*QT_, 128>>>(lmu, isg);

    attn_kernel<<<dim3(QT_, B_*H_), 256, ATTN_SMEM>>>(cb, pb, lmu, isg);

    // attention output -> bf16 hi/lo, then output projection on tensor cores
    convA_kernel<<<(B_*N_*H_*D_/4 + 255)/256, 256>>>(att_p, ah_p, al_p, B_*N_*H_*D_/4);
    wmma_gemm<<<dim3(24, 12), 256, WG_SMEM>>>(ah_p, al_p, woh_p, wol_p,
                                              bo, out, 512, 1);
}

// round 5
// speedup vs baseline: 3.5540x; 2.0847x over previous
#include <cuda_runtime.h>
#include <cuda_bf16.h>
#include <math.h>
#include <stdint.h>

#define B_   2
#define N_   1536
#define DIM_ 1536
#define H_   8
#define D_   64
#define P_   3071      // 2N-1
#define QT_  24        // N/64 tiles

// ---------------- device scratch (static allocation — no cudaMalloc) ----------------
__device__ float g_relk[H_*P_*D_];                // fp32 rel_k (for srel)
__device__ float g_srel[H_*P_];                   // S[h][p] = (pb-cb)·relk[p]
__device__ unsigned char g_tact[B_*QT_*QT_];
__device__ unsigned long long g_mbits[B_*QT_*QT_*64];
__device__ int g_mtype;

// bf16 split-precision staging
__device__ __nv_bfloat16 g_xh[B_*N_*DIM_];        // x hi  [3072][1536]
__device__ __nv_bfloat16 g_xl[B_*N_*DIM_];
__device__ __nv_bfloat16 g_wh[1536*DIM_];         // QKV weights [n][k] hi
__device__ __nv_bfloat16 g_wl[1536*DIM_];
__device__ __nv_bfloat16 g_woh[1536*512];         // Wo [n][k] hi
__device__ __nv_bfloat16 g_wol[1536*512];
__device__ __nv_bfloat16 g_ah[B_*N_*H_*D_];       // attention out hi [3072][512]
__device__ __nv_bfloat16 g_al[B_*N_*H_*D_];
// attention operands (written by GEMM epilogues)
__device__ __nv_bfloat16 g_qh[B_*H_*N_*D_];       // (q*scale + cb) hi, [(bh)][i][d]
__device__ __nv_bfloat16 g_ql[B_*H_*N_*D_];
__device__ __nv_bfloat16 g_kh[B_*H_*N_*D_];
__device__ __nv_bfloat16 g_kl[B_*H_*N_*D_];
__device__ __nv_bfloat16 g_vth[B_*H_*D_*N_];      // V^T: [(bh)][d][j]
__device__ __nv_bfloat16 g_vtl[B_*H_*D_*N_];
__device__ __nv_bfloat16 g_rh[H_*P_*D_];          // rel_k hi [h][p][d]
__device__ __nv_bfloat16 g_rl[H_*P_*D_];

// ---------------- helpers ----------------
__device__ __forceinline__ uint32_t smem_to_u32(const void* p) {
    uint32_t a;
    asm("{ .reg .u64 t; cvta.to.shared.u64 t, %1; cvt.u32.u64 %0, t; }" : "=r"(a) : "l"(p));
    return a;
}
__device__ __forceinline__ void cp_async16(uint32_t saddr, const void* g) {
    asm volatile("cp.async.cg.shared.global [%0], [%1], 16;" :: "r"(saddr), "l"(g));
}
#define CP_COMMIT() asm volatile("cp.async.commit_group;" ::: "memory")
#define CP_WAIT0()  asm volatile("cp.async.wait_group 0;" ::: "memory")

__device__ __forceinline__ void mma_bf16(float* c, const uint32_t* a, const uint32_t* b) {
    asm volatile("mma.sync.aligned.m16n8k16.row.col.f32.bf16.bf16.f32 "
        "{%0,%1,%2,%3}, {%4,%5,%6,%7}, {%8,%9}, {%0,%1,%2,%3};"
        : "+f"(c[0]), "+f"(c[1]), "+f"(c[2]), "+f"(c[3])
        : "r"(a[0]), "r"(a[1]), "r"(a[2]), "r"(a[3]), "r"(b[0]), "r"(b[1]));
}
__device__ __forceinline__ uint32_t lds32(uint32_t addr) {
    uint32_t v;
    asm volatile("ld.shared.b32 %0, [%1];" : "=r"(v) : "r"(addr));
    return v;
}
__device__ __forceinline__ uint32_t pack_hi(float f0, float f1) {
    __nv_bfloat162 h = __floats2bfloat162_rn(f0, f1);
    return *(uint32_t*)&h;
}
__device__ __forceinline__ void split2(float f0, float f1, uint32_t& hi, uint32_t& lo) {
    __nv_bfloat16 h0 = __float2bfloat16(f0), h1 = __float2bfloat16(f1);
    __nv_bfloat162 hh(h0, h1);
    hi = *(uint32_t*)&hh;
    __nv_bfloat16 l0 = __float2bfloat16(f0 - __bfloat162float(h0));
    __nv_bfloat16 l1 = __float2bfloat16(f1 - __bfloat162float(h1));
    __nv_bfloat162 ll(l0, l1);
    lo = *(uint32_t*)&ll;
}

// ---------------- mask dtype probe ----------------
__global__ void probe_kernel(const unsigned char* lm) {
    unsigned int w = *(const unsigned int*)lm;
    int t;
    if ((w & 0xFFu) == 1u && ((w >> 8) & 0xFFu) == 1u) t = 0;
    else if (w == 1u) t = 1;
    else t = 2;
    g_mtype = t;
}
__device__ __forceinline__ bool rd_mask(const unsigned char* p, long idx, int mt) {
    if (mt == 0) return p[idx] != 0;
    if (mt == 1) return ((const int*)p)[idx] != 0;
    return ((const float*)p)[idx] != 0.0f;
}

// ---------------- split-precision conversion kernels ----------------
__global__ void convA_kernel(const float* __restrict__ s, __nv_bfloat16* __restrict__ h,
                             __nv_bfloat16* __restrict__ l, int n4)
{
    int i = blockIdx.x*blockDim.x + threadIdx.x;
    if (i >= n4) return;
    float4 v = ((const float4*)s)[i];
    float a[4] = {v.x, v.y, v.z, v.w};
    __nv_bfloat16 hh[4], ll[4];
    #pragma unroll
    for (int j = 0; j < 4; j++) {
        hh[j] = __float2bfloat16(a[j]);
        ll[j] = __float2bfloat16(a[j] - __bfloat162float(hh[j]));
    }
    ((__nv_bfloat162*)h)[i*2+0] = __nv_bfloat162(hh[0], hh[1]);
    ((__nv_bfloat162*)h)[i*2+1] = __nv_bfloat162(hh[2], hh[3]);
    ((__nv_bfloat162*)l)[i*2+0] = __nv_bfloat162(ll[0], ll[1]);
    ((__nv_bfloat162*)l)[i*2+1] = __nv_bfloat162(ll[2], ll[3]);
}

__global__ void convT_kernel(const float* __restrict__ src, __nv_bfloat16* __restrict__ dh,
                             __nv_bfloat16* __restrict__ dl, int R, int C)
{
    __shared__ float t[32][33];
    int c0 = blockIdx.x*32, r0 = blockIdx.y*32;
    int tx = threadIdx.x & 31, ty = threadIdx.x >> 5;
    #pragma unroll
    for (int i = 0; i < 4; i++)
        t[ty + i*8][tx] = src[(long)(r0 + ty + i*8)*C + c0 + tx];
    __syncthreads();
    #pragma unroll
    for (int i = 0; i < 4; i++) {
        int c = c0 + ty + i*8, r = r0 + tx;
        float v = t[tx][ty + i*8];
        __nv_bfloat16 hv = __float2bfloat16(v);
        dh[(long)c*R + r] = hv;
        dl[(long)c*R + r] = __float2bfloat16(v - __bfloat162float(hv));
    }
}

// ---------------- mask pack + tile-activity ----------------
__global__ void tact_kernel(const unsigned char* __restrict__ lm,
                            const unsigned char* __restrict__ isg)
{
    int t  = blockIdx.x;
    int jt = t % QT_;
    int qt = (t / QT_) % QT_;
    int b  = t / (QT_*QT_);
    int i0 = qt*64, j0 = jt*64;
    int mt = g_mtype;
    int r = threadIdx.x;   // 64 threads
    bool rg = rd_mask(isg, (long)b*N_ + i0 + r, mt);
    unsigned long long bits = 0ull;
    for (int c = 0; c < 64; c++) {
        bool a = rg || rd_mask(isg, (long)b*N_ + j0 + c, mt)
                    || rd_mask(lm, (long)(i0+r)*N_ + j0 + c, mt);
        bits |= (unsigned long long)(a ? 1 : 0) << c;
    }
    g_mbits[(long)t*64 + r] = bits;
    int any = __syncthreads_or(bits != 0ull);
    if (r == 0) g_tact[t] = (unsigned char)(any ? 1 : 0);
}

// ---------------- S[h][p] = (pb-cb)·relk[p] ----------------
__global__ void srel_kernel(const float* __restrict__ cb, const float* __restrict__ pb)
{
    int p = blockIdx.x*256 + threadIdx.x;
    int h = blockIdx.y;
    if (p >= P_) return;
    const float* r = g_relk + ((long)h*P_ + p)*D_;
    float s = 0.f;
    #pragma unroll 8
    for (int d = 0; d < D_; d++) s += (pb[h*D_ + d] - cb[h*D_ + d]) * r[d];
    g_srel[(long)h*P_ + p] = s;
}

// ---------------- warp-MMA bf16 split-precision GEMM ----------------
#define TPAD   40
#define TBYTES (128*TPAD*2)
#define STAGE  (4*TBYTES)
#define WG_SMEM (2*STAGE)

__global__ __launch_bounds__(256)
void wmma_gemm(const __nv_bfloat16* __restrict__ Ah, const __nv_bfloat16* __restrict__ Al,
               const __nv_bfloat16* __restrict__ Bh, const __nv_bfloat16* __restrict__ Bl,
               const float* __restrict__ bias, float* __restrict__ Cout, int K, int mode)
{
    extern __shared__ char smem[];
    const uint32_t sb = smem_to_u32(smem);
    const int tid = threadIdx.x;
    const int lane = tid & 31;
    const int wid = tid >> 5;
    const int warp_m = wid >> 2;
    const int warp_n = wid & 3;
    const int grp = lane >> 2;
    const int tig = lane & 3;
    const int m0 = blockIdx.x * 128, n0 = blockIdx.y * 128;

    const char* srcs[4] = {(const char*)Ah, (const char*)Al, (const char*)Bh, (const char*)Bl};
    const int rb[4] = {m0, m0, n0, n0};
    const long rowB = (long)K * 2;

    auto issue_stage = [&](int kt, int st) {
        const uint32_t sbase = sb + st*STAGE;
        #pragma unroll
        for (int l = 0; l < 8; l++) {
            int i = tid + l*256;
            int t = i >> 9, r = (i >> 2) & 127, c = i & 3;
            const char* g = srcs[t] + (long)(rb[t] + r)*rowB + kt*64 + c*16;
            cp_async16(sbase + t*TBYTES + r*80 + c*16, g);
        }
        CP_COMMIT();
    };

    float acc[4][4][4];
    #pragma unroll
    for (int i = 0; i < 4; i++)
        #pragma unroll
        for (int j = 0; j < 4; j++)
            #pragma unroll
            for (int e = 0; e < 4; e++) acc[i][j][e] = 0.f;

    const int nk = K / 32;
    issue_stage(0, 0);

    for (int kt = 0; kt < nk; kt++) {
        CP_WAIT0();
        __syncthreads();
        if (kt + 1 < nk) issue_stage(kt + 1, (kt + 1) & 1);

        const uint32_t stg = sb + (kt & 1)*STAGE;
        const uint32_t aoffh = stg + 0*TBYTES;
        const uint32_t aoffl = stg + 1*TBYTES;
        const uint32_t boffh = stg + 2*TBYTES;
        const uint32_t boffl = stg + 3*TBYTES;

        #pragma unroll
        for (int ks = 0; ks < 2; ks++) {
            const uint32_t kb = ks*32 + tig*4;
            uint32_t bh[4][2], bl[4][2];
            #pragma unroll
            for (int j = 0; j < 4; j++) {
                uint32_t ro = (uint32_t)(warp_n*32 + j*8 + grp)*80 + kb;
                bh[j][0] = lds32(boffh + ro);      bh[j][1] = lds32(boffh + ro + 16);
                bl[j][0] = lds32(boffl + ro);      bl[j][1] = lds32(boffl + ro + 16);
            }
            #pragma unroll
            for (int i = 0; i < 4; i++) {
                uint32_t ro = (uint32_t)(warp_m*64 + i*16 + grp)*80 + kb;
                uint32_t ah[4], al[4];
                ah[0] = lds32(aoffh + ro);        ah[1] = lds32(aoffh + ro + 640);
                ah[2] = lds32(aoffh + ro + 16);   ah[3] = lds32(aoffh + ro + 656);
                al[0] = lds32(aoffl + ro);        al[1] = lds32(aoffl + ro + 640);
                al[2] = lds32(aoffl + ro + 16);   al[3] = lds32(aoffl + ro + 656);
                #pragma unroll
                for (int j = 0; j < 4; j++) {
                    mma_bf16(acc[i][j], ah, bh[j]);
                    mma_bf16(acc[i][j], ah, bl[j]);
                    mma_bf16(acc[i][j], al, bh[j]);
                }
            }
        }
        __syncthreads();
    }

    // epilogue
    #pragma unroll
    for (int i = 0; i < 4; i++) {
        #pragma unroll
        for (int j = 0; j < 4; j++) {
            const int r0 = m0 + warp_m*64 + i*16 + grp;
            const int c0 = n0 + warp_n*32 + j*8 + 2*tig;
            #pragma unroll
            for (int half = 0; half < 2; half++) {
                const int row = r0 + half*8;
                float v0 = acc[i][j][half*2 + 0];
                float v1 = acc[i][j][half*2 + 1];
                if (mode == 1) {
                    Cout[(long)row*1536 + c0]     = v0 + bias[c0];
                    Cout[(long)row*1536 + c0 + 1] = v1 + bias[c0 + 1];
                } else {
                    const int sel = c0 >> 9, pc = c0 & 511;
                    const int h = pc >> 6, d = pc & 63;
                    const int bb = (row >= N_) ? 1 : 0;
                    const int ii = row - bb*N_;
                    const int bhd = bb*H_ + h;
                    if (sel == 0) {
                        // q: scale + content bias folded
                        float f0 = v0*0.125f + bias[pc];
                        float f1 = v1*0.125f + bias[pc + 1];
                        uint32_t hi, lo; split2(f0, f1, hi, lo);
                        long idx = ((long)bhd*N_ + ii)*D_ + d;
                        *(uint32_t*)&g_qh[idx] = hi;
                        *(uint32_t*)&g_ql[idx] = lo;
                    } else if (sel == 1) {
                        uint32_t hi, lo; split2(v0, v1, hi, lo);
                        long idx = ((long)bhd*N_ + ii)*D_ + d;
                        *(uint32_t*)&g_kh[idx] = hi;
                        *(uint32_t*)&g_kl[idx] = lo;
                    } else {
                        // v transposed: [(bh)][d][j]
                        __nv_bfloat16 h0 = __float2bfloat16(v0);
                        __nv_bfloat16 h1 = __float2bfloat16(v1);
                        long i0x = ((long)bhd*D_ + d)*N_ + ii;
                        long i1x = ((long)bhd*D_ + d + 1)*N_ + ii;
                        g_vth[i0x] = h0;
                        g_vth[i1x] = h1;
                        g_vtl[i0x] = __float2bfloat16(v0 - __bfloat162float(h0));
                        g_vtl[i1x] = __float2bfloat16(v1 - __bfloat162float(h1));
                    }
                }
            }
        }
    }
}

// ---------------- fp32 SIMT GEMM (rel_k projection, K=192) ----------------
#define BM 128
#define BN 128
#define BK 16
__global__ __launch_bounds__(256)
void gemm128(const float* __restrict__ A, const float* __restrict__ B0,
             int M, int K)
{
    __shared__ float sA[2][BK][BM];
    __shared__ float sB[2][BK][BN];
    const int tid = threadIdx.x;
    const int m0 = blockIdx.x * BM;
    const int n0 = blockIdx.y * BN;
    const float* Bm = B0;
    const int Bs = 512, nb = n0;

    const int ar  = tid & 63;
    const int ac4 = tid >> 6;
    const int br  = tid >> 5;
    const int bc4 = tid & 31;
    const int tx = tid & 15, ty = tid >> 4;

    float acc[8][8];
    #pragma unroll
    for (int r = 0; r < 8; r++)
        #pragma unroll
        for (int c = 0; c < 8; c++) acc[r][c] = 0.f;

    const int nk = K / BK;
    const long arow0 = (long)(m0 + ar);
    const long arow1 = (long)(m0 + ar + 64);
    const bool g0 = (m0 + ar)      < M;
    const bool g1 = (m0 + ar + 64) < M;

    {
        float4 pa0 = g0 ? *(const float4*)&A[arow0*K + 4*ac4] : make_float4(0,0,0,0);
        float4 pa1 = g1 ? *(const float4*)&A[arow1*K + 4*ac4] : make_float4(0,0,0,0);
        float4 pb0 = *(const float4*)&Bm[(long)br*Bs      + nb + 4*bc4];
        float4 pb1 = *(const float4*)&Bm[(long)(br+8)*Bs  + nb + 4*bc4];
        sA[0][4*ac4+0][ar]    = pa0.x; sA[0][4*ac4+1][ar]    = pa0.y;
        sA[0][4*ac4+2][ar]    = pa0.z; sA[0][4*ac4+3][ar]    = pa0.w;
        sA[0][4*ac4+0][ar+64] = pa1.x; sA[0][4*ac4+1][ar+64] = pa1.y;
        sA[0][4*ac4+2][ar+64] = pa1.z; sA[0][4*ac4+3][ar+64] = pa1.w;
        *(float4*)&sB[0][br  ][4*bc4] = pb0;
        *(float4*)&sB[0][br+8][4*bc4] = pb1;
    }
    __syncthreads();

    for (int kt = 0; kt < nk; kt++) {
        const int cur = kt & 1;
        float4 pa0, pa1, pb0, pb1;
        const bool more = (kt + 1 < nk);
        if (more) {
            const int k0 = (kt + 1) * BK;
            pa0 = g0 ? *(const float4*)&A[arow0*K + k0 + 4*ac4] : make_float4(0,0,0,0);
            pa1 = g1 ? *(const float4*)&A[arow1*K + k0 + 4*ac4] : make_float4(0,0,0,0);
            pb0 = *(const float4*)&Bm[(long)(k0+br)*Bs     + nb + 4*bc4];
            pb1 = *(const float4*)&Bm[(long)(k0+br+8)*Bs   + nb + 4*bc4];
        }
        #pragma unroll
        for (int kk = 0; kk < BK; kk++) {
            float a[8], b[8];
            *(float4*)&a[0] = *(float4*)&sA[cur][kk][ty*4];
            *(float4*)&a[4] = *(float4*)&sA[cur][kk][64 + ty*4];
            *(float4*)&b[0] = *(float4*)&sB[cur][kk][tx*4];
            *(float4*)&b[4] = *(float4*)&sB[cur][kk][64 + tx*4];
            #pragma unroll
            for (int r = 0; r < 8; r++)
                #pragma unroll
                for (int c = 0; c < 8; c++) acc[r][c] += a[r]*b[c];
        }
        if (more) {
            const int nxt = cur ^ 1;
            sA[nxt][4*ac4+0][ar]    = pa0.x; sA[nxt][4*ac4+1][ar]    = pa0.y;
            sA[nxt][4*ac4+2][ar]    = pa0.z; sA[nxt][4*ac4+3][ar]    = pa0.w;
            sA[nxt][4*ac4+0][ar+64] = pa1.x; sA[nxt][4*ac4+1][ar+64] = pa1.y;
            sA[nxt][4*ac4+2][ar+64] = pa1.z; sA[nxt][4*ac4+3][ar+64] = pa1.w;
            *(float4*)&sB[nxt][br  ][4*bc4] = pb0;
            *(float4*)&sB[nxt][br+8][4*bc4] = pb1;
            __syncthreads();
        }
    }

    #pragma unroll
    for (int rr = 0; rr < 8; rr++) {
        const int lrow = (rr < 4) ? (ty*4 + rr) : (64 + ty*4 + rr - 4);
        const int row = m0 + lrow;
        if (row >= M) continue;
        #pragma unroll
        for (int cg = 0; cg < 2; cg++) {
            const int lc = cg ? (64 + tx*4) : (tx*4);
            float4 v = make_float4(acc[rr][cg*4+0], acc[rr][cg*4+1],
                                   acc[rr][cg*4+2], acc[rr][cg*4+3]);
            const int pc = n0 + lc;
            const int h = pc >> 6, d = pc & 63;
            long base = ((long)h*P_ + row)*D_ + d;
            *(float4*)&g_relk[base] = v;
            uint32_t hi0, lo0, hi1, lo1;
            split2(v.x, v.y, hi0, lo0);
            split2(v.z, v.w, hi1, lo1);
            *(uint32_t*)&g_rh[base]     = hi0;
            *(uint32_t*)&g_rh[base + 2] = hi1;
            *(uint32_t*)&g_rl[base]     = lo0;
            *(uint32_t*)&g_rl[base + 2] = lo1;
        }
    }
}

// ---------------- mma.sync flash attention with rel-shift GEMM+gather ----------------
// grid (24, 16), 128 threads (4 warps, 16 q-rows each).
#define AK_H   0u
#define AK_L   9216u
#define AVT_H  18432u
#define AVT_L  27648u
#define AR_H   36864u
#define AR_L   55296u
#define AG     73728u      // 64 x 132 fp32
#define AS     107520u     // 128 fp32
#define ATTN2_SMEM 108032

__global__ __launch_bounds__(128)
void attn_mma()
{
    extern __shared__ char sm2[];
    const uint32_t sb = smem_to_u32(sm2);
    float* sG = (float*)(sm2 + AG);
    float* sS = (float*)(sm2 + AS);

    const int tid = threadIdx.x;
    const int lane = tid & 31;
    const int w = tid >> 5;
    const int grp = lane >> 2;
    const int tig = lane & 3;
    const int qt = blockIdx.x;
    const int bh = blockIdx.y;
    const int b = bh >> 3, h = bh & 7;
    const int i0 = qt * 64;

    // ---- Q fragments (persistent) ----
    const __nv_bfloat16* qbh = g_qh + (long)bh*N_*D_;
    const __nv_bfloat16* qbl = g_ql + (long)bh*N_*D_;
    const int rq0 = i0 + w*16 + grp, rq1 = rq0 + 8;
    uint32_t qfh[4][4], qfl[4][4];
    #pragma unroll
    for (int kf = 0; kf < 4; kf++) {
        qfh[kf][0] = *(const uint32_t*)(qbh + (long)rq0*D_ + kf*16 + 2*tig);
        qfh[kf][1] = *(const uint32_t*)(qbh + (long)rq1*D_ + kf*16 + 2*tig);
        qfh[kf][2] = *(const uint32_t*)(qbh + (long)rq0*D_ + kf*16 + 8 + 2*tig);
        qfh[kf][3] = *(const uint32_t*)(qbh + (long)rq1*D_ + kf*16 + 8 + 2*tig);
        qfl[kf][0] = *(const uint32_t*)(qbl + (long)rq0*D_ + kf*16 + 2*tig);
        qfl[kf][1] = *(const uint32_t*)(qbl + (long)rq1*D_ + kf*16 + 2*tig);
        qfl[kf][2] = *(const uint32_t*)(qbl + (long)rq0*D_ + kf*16 + 8 + 2*tig);
        qfl[kf][3] = *(const uint32_t*)(qbl + (long)rq1*D_ + kf*16 + 8 + 2*tig);
    }

    float o[8][4];
    #pragma unroll
    for (int nf = 0; nf < 8; nf++)
        #pragma unroll
        for (int e = 0; e < 4; e++) o[nf][e] = 0.f;
    float mrow[2] = {-1e30f, -1e30f};
    float lrow[2] = {0.f, 0.f};

    const unsigned char* tact = &g_tact[(b*QT_ + qt)*QT_];
    const long kbase  = (long)bh*N_*D_;
    const long vbase  = (long)bh*D_*N_;
    const long rbase  = (long)h*P_*D_;

    for (int jt = 0; jt < QT_; jt++) {
        if (!tact[jt]) continue;
        const int j0 = jt*64;
        const int p0 = j0 - i0 + (N_ - 1) - 63;

        __syncthreads();
        // ---- stage tiles via cp.async ----
        #pragma unroll
        for (int l = 0; l < 4; l++) {
            int i = tid + l*128;
            int r = i >> 3, c = i & 7;
            long krow = (kbase + (long)(j0 + r)*D_)*2;
            long vrow = (vbase + (long)r*N_ + j0)*2;
            cp_async16(sb + AK_H  + r*144 + c*16, (const char*)g_kh  + krow + c*16);
            cp_async16(sb + AK_L  + r*144 + c*16, (const char*)g_kl  + krow + c*16);
            cp_async16(sb + AVT_H + r*144 + c*16, (const char*)g_vth + vrow + c*16);
            cp_async16(sb + AVT_L + r*144 + c*16, (const char*)g_vtl + vrow + c*16);
        }
        #pragma unroll
        for (int l = 0; l < 8; l++) {
            int i = tid + l*128;
            int r = i >> 3, c = i & 7;
            int pr = p0 + r; if (pr > P_ - 1) pr = P_ - 1;
            long rrow = (rbase + (long)pr*D_)*2;
            cp_async16(sb + AR_H + r*144 + c*16, (const char*)g_rh + rrow + c*16);
            cp_async16(sb + AR_L + r*144 + c*16, (const char*)g_rl + rrow + c*16);
        }
        CP_COMMIT();

        // S band + mask words (regular loads, overlap with cp.async)
        sS[tid] = (tid < 127) ? g_srel[(long)h*P_ + p0 + tid] : 0.f;
        const unsigned long long* mb = g_mbits + ((long)(b*QT_ + qt)*QT_ + jt)*64;
        unsigned long long mw0 = mb[w*16 + grp];
        unsigned long long mw1 = mb[w*16 + grp + 8];

        CP_WAIT0();
        __syncthreads();

        // ---- content logits: Qc @ K^T (3 split streams) ----
        float ca[8][4];
        #pragma unroll
        for (int nf = 0; nf < 8; nf++)
            #pragma unroll
            for (int e = 0; e < 4; e++) ca[nf][e] = 0.f;
        #pragma unroll
        for (int kf = 0; kf < 4; kf++) {
            #pragma unroll
            for (int nf = 0; nf < 8; nf++) {
                uint32_t ro = (uint32_t)(8*nf + grp)*144 + kf*32 + tig*4;
                uint32_t bhf[2] = {lds32(sb + AK_H + ro), lds32(sb + AK_H + ro + 16)};
                uint32_t blf[2] = {lds32(sb + AK_L + ro), lds32(sb + AK_L + ro + 16)};
                mma_bf16(ca[nf], qfh[kf], bhf);
                mma_bf16(ca[nf], qfh[kf], blf);
                mma_bf16(ca[nf], qfl[kf], bhf);
            }
        }

        // ---- G = Qc @ Rband^T (+S), two 64-col halves ----
        const int grow = w*16 + grp;
        #pragma unroll
        for (int gh = 0; gh < 2; gh++) {
            float ga[8][4];
            #pragma unroll
            for (int nf = 0; nf < 8; nf++)
                #pragma unroll
                for (int e = 0; e < 4; e++) ga[nf][e] = 0.f;
            #pragma unroll
            for (int kf = 0; kf < 4; kf++) {
                #pragma unroll
                for (int nf = 0; nf < 8; nf++) {
                    uint32_t ro = (uint32_t)(gh*64 + 8*nf + grp)*144 + kf*32 + tig*4;
                    uint32_t bhf[2] = {lds32(sb + AR_H + ro), lds32(sb + AR_H + ro + 16)};
                    uint32_t blf[2] = {lds32(sb + AR_L + ro), lds32(sb + AR_L + ro + 16)};
                    mma_bf16(ga[nf], qfh[kf], bhf);
                    mma_bf16(ga[nf], qfh[kf], blf);
                    mma_bf16(ga[nf], qfl[kf], bhf);
                }
            }
            #pragma unroll
            for (int nf = 0; nf < 8; nf++) {
                int col = gh*64 + 8*nf + 2*tig;
                float s0 = sS[col], s1 = sS[col + 1];
                sG[grow*132 + col]           = ga[nf][0] + s0;
                sG[grow*132 + col + 1]       = ga[nf][1] + s1;
                sG[(grow + 8)*132 + col]     = ga[nf][2] + s0;
                sG[(grow + 8)*132 + col + 1] = ga[nf][3] + s1;
            }
        }
        __syncwarp();

        // ---- gather + mask + online softmax ----
        float pv0[16], pv1[16];
        #pragma unroll
        for (int h2 = 0; h2 < 2; h2++) {
            const int rl = grow + 8*h2;
            const unsigned long long mw = h2 ? mw1 : mw0;
            float* pvv = h2 ? pv1 : pv0;
            float lg[16];
            float tmax = -1e30f;
            #pragma unroll
            for (int nf = 0; nf < 8; nf++) {
                #pragma unroll
                for (int e = 0; e < 2; e++) {
                    int c = 8*nf + 2*tig + e;
                    int pp = c - (rl - w*16 - 8*h2 + w*16 + 8*h2) + 63;  // c - rl + 63
                    pp = c - rl + 63;
                    float val = ca[nf][2*h2 + e] + sG[rl*132 + pp];
                    bool act = (mw >> c) & 1ull;
                    float lv = act ? val : -1e30f;
                    lg[nf*2 + e] = lv;
                    tmax = fmaxf(tmax, lv);
                }
            }
            tmax = fmaxf(tmax, __shfl_xor_sync(0xffffffffu, tmax, 1));
            tmax = fmaxf(tmax, __shfl_xor_sync(0xffffffffu, tmax, 2));
            float nm = fmaxf(mrow[h2], tmax);
            float corr = __expf(mrow[h2] - nm);
            mrow[h2] = nm;
            float ps = 0.f;
            #pragma unroll
            for (int e2 = 0; e2 < 16; e2++) {
                float p = (lg[e2] <= -1e29f) ? 0.f : __expf(lg[e2] - nm);
                pvv[e2] = p;
                ps += p;
            }
            ps += __shfl_xor_sync(0xffffffffu, ps, 1);
            ps += __shfl_xor_sync(0xffffffffu, ps, 2);
            lrow[h2] = lrow[h2]*corr + ps;
            #pragma unroll
            for (int nf = 0; nf < 8; nf++) {
                o[nf][2*h2]     *= corr;
                o[nf][2*h2 + 1] *= corr;
            }
        }

        // ---- P fragments (registers only) ----
        uint32_t pfh[4][4], pfl[4][4];
        #pragma unroll
        for (int kf = 0; kf < 4; kf++) {
            split2(pv0[(2*kf)*2],   pv0[(2*kf)*2+1],   pfh[kf][0], pfl[kf][0]);
            split2(pv1[(2*kf)*2],   pv1[(2*kf)*2+1],   pfh[kf][1], pfl[kf][1]);
            split2(pv0[(2*kf+1)*2], pv0[(2*kf+1)*2+1], pfh[kf][2], pfl[kf][2]);
            split2(pv1[(2*kf+1)*2], pv1[(2*kf+1)*2+1], pfh[kf][3], pfl[kf][3]);
        }

        // ---- PV: o += P @ V (V^T as B operand) ----
        #pragma unroll
        for (int kf = 0; kf < 4; kf++) {
            #pragma unroll
            for (int nf = 0; nf < 8; nf++) {
                uint32_t ro = (uint32_t)(8*nf + grp)*144 + kf*32 + tig*4;
                uint32_t vhf[2] = {lds32(sb + AVT_H + ro), lds32(sb + AVT_H + ro + 16)};
                uint32_t vlf[2] = {lds32(sb + AVT_L + ro), lds32(sb + AVT_L + ro + 16)};
                mma_bf16(o[nf], pfh[kf], vhf);
                mma_bf16(o[nf], pfh[kf], vlf);
                mma_bf16(o[nf], pfl[kf], vhf);
            }
        }
    }

    // ---- epilogue: normalize + split-store to g_ah/g_al ----
    #pragma unroll
    for (int h2 = 0; h2 < 2; h2++) {
        float inv = 1.0f / lrow[h2];
        int rl = w*16 + grp + 8*h2;
        long rowbase = ((long)(b*N_ + i0 + rl))*(H_*D_) + h*D_;
        #pragma unroll
        for (int nf = 0; nf < 8; nf++) {
            float f0 = o[nf][2*h2]     * inv;
            float f1 = o[nf][2*h2 + 1] * inv;
            uint32_t hi, lo; split2(f0, f1, hi, lo);
            long idx = rowbase + 8*nf + 2*tig;
            *(uint32_t*)&g_ah[idx] = hi;
            *(uint32_t*)&g_al[idx] = lo;
        }
    }
}

// ---------------- launcher ----------------
extern "C" void kernel_launch(void* const* d_in, const int* in_sizes, int n_in,
                              void* d_out, int out_size)
{
    const float* x    = (const float*)d_in[0];
    const float* Wq   = (const float*)d_in[1];
    const float* Wk   = (const float*)d_in[2];
    const float* Wv   = (const float*)d_in[3];
    const float* Wrel = (const float*)d_in[4];
    const float* cb   = (const float*)d_in[5];
    const float* pb   = (const float*)d_in[6];
    const float* Wo   = (const float*)d_in[7];
    const float* bo   = (const float*)d_in[8];
    const float* pos  = (const float*)d_in[9];
    const unsigned char* lmu = (const unsigned char*)d_in[10];
    const unsigned char* isg = (const unsigned char*)d_in[11];
    float* out = (float*)d_out;

    cudaFuncSetAttribute(wmma_gemm, cudaFuncAttributeMaxDynamicSharedMemorySize, WG_SMEM);
    cudaFuncSetAttribute(attn_mma, cudaFuncAttributeMaxDynamicSharedMemorySize, ATTN2_SMEM);

    __nv_bfloat16 *xh_p, *xl_p, *wh_p, *wl_p, *woh_p, *wol_p, *ah_p, *al_p;
    cudaGetSymbolAddress((void**)&xh_p,  g_xh);
    cudaGetSymbolAddress((void**)&xl_p,  g_xl);
    cudaGetSymbolAddress((void**)&wh_p,  g_wh);
    cudaGetSymbolAddress((void**)&wl_p,  g_wl);
    cudaGetSymbolAddress((void**)&woh_p, g_woh);
    cudaGetSymbolAddress((void**)&wol_p, g_wol);
    cudaGetSymbolAddress((void**)&ah_p,  g_ah);
    cudaGetSymbolAddress((void**)&al_p,  g_al);

    probe_kernel<<<1, 1>>>(lmu);

    convA_kernel<<<(B_*N_*DIM_/4 + 255)/256, 256>>>(x, xh_p, xl_p, B_*N_*DIM_/4);
    convT_kernel<<<dim3(512/32, DIM_/32), 256>>>(Wq, wh_p,              wl_p,              DIM_, 512);
    convT_kernel<<<dim3(512/32, DIM_/32), 256>>>(Wk, wh_p + 512L*DIM_,  wl_p + 512L*DIM_,  DIM_, 512);
    convT_kernel<<<dim3(512/32, DIM_/32), 256>>>(Wv, wh_p + 1024L*DIM_, wl_p + 1024L*DIM_, DIM_, 512);
    convT_kernel<<<dim3(1536/32, 512/32), 256>>>(Wo, woh_p, wol_p, 512, 1536);

    // QKV projection (epilogue emits bf16 hi/lo q/k/v^T; q has scale+cb folded)
    wmma_gemm<<<dim3(24, 12), 256, WG_SMEM>>>(xh_p, xl_p, wh_p, wl_p,
                                              cb, nullptr, DIM_, 0);

    // rel_k projection (fp32 + bf16 hi/lo epilogue)
    gemm128<<<dim3(24, 4), 256>>>(pos, Wrel, P_, 192);
    srel_kernel<<<dim3((P_ + 255)/256, H_), 256>>>(cb, pb);

    tact_kernel<<<B_*QT_*QT_, 64>>>(lmu, isg);

    attn_mma<<<dim3(QT_, B_*H_), 128, ATTN2_SMEM>>>();

    // output projection
    wmma_gemm<<<dim3(24, 12), 256, WG_SMEM>>>(ah_p, al_p, woh_p, wol_p,
                                              bo, out, 512, 1);
}

// round 6
// speedup vs baseline: 3.6822x; 1.0361x over previous
#include <cuda_runtime.h>
#include <cuda_bf16.h>
#include <math.h>
#include <stdint.h>

#define B_   2
#define N_   1536
#define DIM_ 1536
#define H_   8
#define D_   64
#define P_   3071      // 2N-1
#define QT_  24        // N/64 tiles

// ---------------- device scratch ----------------
__device__ float g_relk[H_*P_*D_];
__device__ float g_srel[H_*P_];
__device__ unsigned char g_tact[B_*QT_*QT_];
__device__ unsigned long long g_mbits[B_*QT_*QT_*64];
__device__ int g_mtype;

__device__ __nv_bfloat16 g_xh[B_*N_*DIM_];
__device__ __nv_bfloat16 g_xl[B_*N_*DIM_];
__device__ __nv_bfloat16 g_wh[1536*DIM_];
__device__ __nv_bfloat16 g_wl[1536*DIM_];
__device__ __nv_bfloat16 g_woh[1536*512];
__device__ __nv_bfloat16 g_wol[1536*512];
__device__ __nv_bfloat16 g_ah[B_*N_*H_*D_];
__device__ __nv_bfloat16 g_al[B_*N_*H_*D_];
__device__ __nv_bfloat16 g_qh[B_*H_*N_*D_];
__device__ __nv_bfloat16 g_ql[B_*H_*N_*D_];
__device__ __nv_bfloat16 g_kh[B_*H_*N_*D_];
__device__ __nv_bfloat16 g_kl[B_*H_*N_*D_];
__device__ __nv_bfloat16 g_vth[B_*H_*D_*N_];
__device__ __nv_bfloat16 g_vtl[B_*H_*D_*N_];
__device__ __nv_bfloat16 g_rh[H_*P_*D_];
__device__ __nv_bfloat16 g_rl[H_*P_*D_];

// ---------------- helpers ----------------
__device__ __forceinline__ uint32_t smem_to_u32(const void* p) {
    uint32_t a;
    asm("{ .reg .u64 t; cvta.to.shared.u64 t, %1; cvt.u32.u64 %0, t; }" : "=r"(a) : "l"(p));
    return a;
}
__device__ __forceinline__ void cp_async16(uint32_t saddr, const void* g) {
    asm volatile("cp.async.cg.shared.global [%0], [%1], 16;" :: "r"(saddr), "l"(g));
}
#define CP_COMMIT() asm volatile("cp.async.commit_group;" ::: "memory")
#define CP_WAIT0()  asm volatile("cp.async.wait_group 0;" ::: "memory")

__device__ __forceinline__ void mma_bf16(float* c, const uint32_t* a, const uint32_t* b) {
    asm volatile("mma.sync.aligned.m16n8k16.row.col.f32.bf16.bf16.f32 "
        "{%0,%1,%2,%3}, {%4,%5,%6,%7}, {%8,%9}, {%0,%1,%2,%3};"
        : "+f"(c[0]), "+f"(c[1]), "+f"(c[2]), "+f"(c[3])
        : "r"(a[0]), "r"(a[1]), "r"(a[2]), "r"(a[3]), "r"(b[0]), "r"(b[1]));
}
__device__ __forceinline__ void ldsm_x4(uint32_t* r, uint32_t addr) {
    asm volatile("ldmatrix.sync.aligned.m8n8.x4.shared.b16 {%0,%1,%2,%3}, [%4];"
        : "=r"(r[0]), "=r"(r[1]), "=r"(r[2]), "=r"(r[3]) : "r"(addr));
}
__device__ __forceinline__ void split2(float f0, float f1, uint32_t& hi, uint32_t& lo) {
    __nv_bfloat16 h0 = __float2bfloat16(f0), h1 = __float2bfloat16(f1);
    __nv_bfloat162 hh(h0, h1);
    hi = *(uint32_t*)&hh;
    __nv_bfloat16 l0 = __float2bfloat16(f0 - __bfloat162float(h0));
    __nv_bfloat16 l1 = __float2bfloat16(f1 - __bfloat162float(h1));
    __nv_bfloat162 ll(l0, l1);
    lo = *(uint32_t*)&ll;
}

// ---------------- mask dtype probe ----------------
__global__ void probe_kernel(const unsigned char* lm) {
    unsigned int w = *(const unsigned int*)lm;
    int t;
    if ((w & 0xFFu) == 1u && ((w >> 8) & 0xFFu) == 1u) t = 0;
    else if (w == 1u) t = 1;
    else t = 2;
    g_mtype = t;
}
__device__ __forceinline__ bool rd_mask(const unsigned char* p, long idx, int mt) {
    if (mt == 0) return p[idx] != 0;
    if (mt == 1) return ((const int*)p)[idx] != 0;
    return ((const float*)p)[idx] != 0.0f;
}

// ---------------- conversions ----------------
__global__ void convA_kernel(const float* __restrict__ s, __nv_bfloat16* __restrict__ h,
                             __nv_bfloat16* __restrict__ l, int n4)
{
    int i = blockIdx.x*blockDim.x + threadIdx.x;
    if (i >= n4) return;
    float4 v = ((const float4*)s)[i];
    float a[4] = {v.x, v.y, v.z, v.w};
    __nv_bfloat16 hh[4], ll[4];
    #pragma unroll
    for (int j = 0; j < 4; j++) {
        hh[j] = __float2bfloat16(a[j]);
        ll[j] = __float2bfloat16(a[j] - __bfloat162float(hh[j]));
    }
    ((__nv_bfloat162*)h)[i*2+0] = __nv_bfloat162(hh[0], hh[1]);
    ((__nv_bfloat162*)h)[i*2+1] = __nv_bfloat162(hh[2], hh[3]);
    ((__nv_bfloat162*)l)[i*2+0] = __nv_bfloat162(ll[0], ll[1]);
    ((__nv_bfloat162*)l)[i*2+1] = __nv_bfloat162(ll[2], ll[3]);
}

// merged transpose+convert for Wq/Wk/Wv/Wo. grid (768, 4).
__global__ void convT_all(const float* __restrict__ Wq, const float* __restrict__ Wk,
                          const float* __restrict__ Wv, const float* __restrict__ Wo)
{
    __shared__ float t[32][33];
    const int job = blockIdx.y;
    const int idx = blockIdx.x;
    const float* src; __nv_bfloat16 *dh, *dl;
    int R, C, c0, r0;
    if (job < 3) {
        src = (job == 0) ? Wq : (job == 1) ? Wk : Wv;
        dh = g_wh + (long)job*512*1536; dl = g_wl + (long)job*512*1536;
        R = 1536; C = 512;
        c0 = (idx & 15)*32; r0 = (idx >> 4)*32;
    } else {
        src = Wo; dh = g_woh; dl = g_wol;
        R = 512; C = 1536;
        c0 = (idx % 48)*32; r0 = (idx / 48)*32;
    }
    int tx = threadIdx.x & 31, ty = threadIdx.x >> 5;
    #pragma unroll
    for (int i = 0; i < 4; i++)
        t[ty + i*8][tx] = src[(long)(r0 + ty + i*8)*C + c0 + tx];
    __syncthreads();
    #pragma unroll
    for (int i = 0; i < 4; i++) {
        int c = c0 + ty + i*8, r = r0 + tx;
        float v = t[tx][ty + i*8];
        __nv_bfloat16 hv = __float2bfloat16(v);
        dh[(long)c*R + r] = hv;
        dl[(long)c*R + r] = __float2bfloat16(v - __bfloat162float(hv));
    }
}

// ---------------- mask pack + tile-activity ----------------
__global__ void tact_kernel(const unsigned char* __restrict__ lm,
                            const unsigned char* __restrict__ isg)
{
    int t  = blockIdx.x;
    int jt = t % QT_;
    int qt = (t / QT_) % QT_;
    int b  = t / (QT_*QT_);
    int i0 = qt*64, j0 = jt*64;
    int mt = g_mtype;
    int r = threadIdx.x;
    bool rg = rd_mask(isg, (long)b*N_ + i0 + r, mt);
    unsigned long long bits = 0ull;
    for (int c = 0; c < 64; c++) {
        bool a = rg || rd_mask(isg, (long)b*N_ + j0 + c, mt)
                    || rd_mask(lm, (long)(i0+r)*N_ + j0 + c, mt);
        bits |= (unsigned long long)(a ? 1 : 0) << c;
    }
    g_mbits[(long)t*64 + r] = bits;
    int any = __syncthreads_or(bits != 0ull);
    if (r == 0) g_tact[t] = (unsigned char)(any ? 1 : 0);
}

// ---------------- S[h][p] = (pb-cb)·relk[p] ----------------
__global__ void srel_kernel(const float* __restrict__ cb, const float* __restrict__ pb)
{
    int p = blockIdx.x*256 + threadIdx.x;
    int h = blockIdx.y;
    if (p >= P_) return;
    const float* r = g_relk + ((long)h*P_ + p)*D_;
    float s = 0.f;
    #pragma unroll 8
    for (int d = 0; d < D_; d++) s += (pb[h*D_ + d] - cb[h*D_ + d]) * r[d];
    g_srel[(long)h*P_ + p] = s;
}

// ---------------- warp-MMA bf16 split-precision GEMM (ldmatrix) ----------------
#define TPAD   40
#define TBYTES (128*TPAD*2)
#define STAGE  (4*TBYTES)
#define WG_SMEM (2*STAGE)

__global__ __launch_bounds__(256)
void wmma_gemm(const __nv_bfloat16* __restrict__ Ah, const __nv_bfloat16* __restrict__ Al,
               const __nv_bfloat16* __restrict__ Bh, const __nv_bfloat16* __restrict__ Bl,
               const float* __restrict__ bias, float* __restrict__ Cout, int K, int mode)
{
    extern __shared__ char smem[];
    const uint32_t sb = smem_to_u32(smem);
    const int tid = threadIdx.x;
    const int lane = tid & 31;
    const int wid = tid >> 5;
    const int warp_m = wid >> 2;
    const int warp_n = wid & 3;
    const int grp = lane >> 2;
    const int tig = lane & 3;
    const int m0 = blockIdx.x * 128, n0 = blockIdx.y * 128;

    // ldmatrix per-lane address components
    const int arow_l = lane & 15;
    const int acol_l = (lane >> 4) * 16;
    const int brow_l = ((lane >> 4) << 3) + (lane & 7);
    const int bcol_l = ((lane >> 3) & 1) * 16;

    const char* srcs[4] = {(const char*)Ah, (const char*)Al, (const char*)Bh, (const char*)Bl};
    const int rb[4] = {m0, m0, n0, n0};
    const long rowB = (long)K * 2;

    auto issue_stage = [&](int kt, int st) {
        const uint32_t sbase = sb + st*STAGE;
        #pragma unroll
        for (int l = 0; l < 8; l++) {
            int i = tid + l*256;
            int t = i >> 9, r = (i >> 2) & 127, c = i & 3;
            const char* g = srcs[t] + (long)(rb[t] + r)*rowB + kt*64 + c*16;
            cp_async16(sbase + t*TBYTES + r*80 + c*16, g);
        }
        CP_COMMIT();
    };

    float acc[4][4][4];
    #pragma unroll
    for (int i = 0; i < 4; i++)
        #pragma unroll
        for (int j = 0; j < 4; j++)
            #pragma unroll
            for (int e = 0; e < 4; e++) acc[i][j][e] = 0.f;

    const int nk = K / 32;
    issue_stage(0, 0);

    for (int kt = 0; kt < nk; kt++) {
        CP_WAIT0();
        __syncthreads();
        if (kt + 1 < nk) issue_stage(kt + 1, (kt + 1) & 1);

        const uint32_t stg = sb + (kt & 1)*STAGE;
        const uint32_t aoffh = stg + 0*TBYTES;
        const uint32_t aoffl = stg + 1*TBYTES;
        const uint32_t boffh = stg + 2*TBYTES;
        const uint32_t boffl = stg + 3*TBYTES;

        #pragma unroll
        for (int ks = 0; ks < 2; ks++) {
            const uint32_t kb = ks*32;
            uint32_t bh[4][2], bl[4][2];
            #pragma unroll
            for (int jp = 0; jp < 2; jp++) {
                uint32_t ro = (uint32_t)(warp_n*32 + jp*16 + brow_l)*80 + kb + bcol_l;
                uint32_t r4[4];
                ldsm_x4(r4, boffh + ro);
                bh[2*jp][0] = r4[0]; bh[2*jp][1] = r4[1];
                bh[2*jp+1][0] = r4[2]; bh[2*jp+1][1] = r4[3];
                ldsm_x4(r4, boffl + ro);
                bl[2*jp][0] = r4[0]; bl[2*jp][1] = r4[1];
                bl[2*jp+1][0] = r4[2]; bl[2*jp+1][1] = r4[3];
            }
            #pragma unroll
            for (int i = 0; i < 4; i++) {
                uint32_t ro = (uint32_t)(warp_m*64 + i*16 + arow_l)*80 + kb + acol_l;
                uint32_t ah[4], al[4];
                ldsm_x4(ah, aoffh + ro);
                ldsm_x4(al, aoffl + ro);
                #pragma unroll
                for (int j = 0; j < 4; j++) {
                    mma_bf16(acc[i][j], ah, bh[j]);
                    mma_bf16(acc[i][j], ah, bl[j]);
                    mma_bf16(acc[i][j], al, bh[j]);
                }
            }
        }
        __syncthreads();
    }

    // epilogue
    #pragma unroll
    for (int i = 0; i < 4; i++) {
        #pragma unroll
        for (int j = 0; j < 4; j++) {
            const int r0 = m0 + warp_m*64 + i*16 + grp;
            const int c0 = n0 + warp_n*32 + j*8 + 2*tig;
            #pragma unroll
            for (int half = 0; half < 2; half++) {
                const int row = r0 + half*8;
                float v0 = acc[i][j][half*2 + 0];
                float v1 = acc[i][j][half*2 + 1];
                if (mode == 1) {
                    Cout[(long)row*1536 + c0]     = v0 + bias[c0];
                    Cout[(long)row*1536 + c0 + 1] = v1 + bias[c0 + 1];
                } else {
                    const int sel = c0 >> 9, pc = c0 & 511;
                    const int h = pc >> 6, d = pc & 63;
                    const int bb = (row >= N_) ? 1 : 0;
                    const int ii = row - bb*N_;
                    const int bhd = bb*H_ + h;
                    if (sel == 0) {
                        float f0 = v0*0.125f + bias[pc];
                        float f1 = v1*0.125f + bias[pc + 1];
                        uint32_t hi, lo; split2(f0, f1, hi, lo);
                        long idx = ((long)bhd*N_ + ii)*D_ + d;
                        *(uint32_t*)&g_qh[idx] = hi;
                        *(uint32_t*)&g_ql[idx] = lo;
                    } else if (sel == 1) {
                        uint32_t hi, lo; split2(v0, v1, hi, lo);
                        long idx = ((long)bhd*N_ + ii)*D_ + d;
                        *(uint32_t*)&g_kh[idx] = hi;
                        *(uint32_t*)&g_kl[idx] = lo;
                    } else {
                        __nv_bfloat16 h0 = __float2bfloat16(v0);
                        __nv_bfloat16 h1 = __float2bfloat16(v1);
                        long i0x = ((long)bhd*D_ + d)*N_ + ii;
                        long i1x = ((long)bhd*D_ + d + 1)*N_ + ii;
                        g_vth[i0x] = h0;
                        g_vth[i1x] = h1;
                        g_vtl[i0x] = __float2bfloat16(v0 - __bfloat162float(h0));
                        g_vtl[i1x] = __float2bfloat16(v1 - __bfloat162float(h1));
                    }
                }
            }
        }
    }
}

// ---------------- fp32 SIMT GEMM (rel_k projection, K=192) ----------------
#define BM 128
#define BN 128
#define BK 16
__global__ __launch_bounds__(256)
void gemm128(const float* __restrict__ A, const float* __restrict__ B0,
             int M, int K)
{
    __shared__ float sA[2][BK][BM];
    __shared__ float sB[2][BK][BN];
    const int tid = threadIdx.x;
    const int m0 = blockIdx.x * BM;
    const int n0 = blockIdx.y * BN;
    const float* Bm = B0;
    const int Bs = 512, nb = n0;

    const int ar  = tid & 63;
    const int ac4 = tid >> 6;
    const int br  = tid >> 5;
    const int bc4 = tid & 31;
    const int tx = tid & 15, ty = tid >> 4;

    float acc[8][8];
    #pragma unroll
    for (int r = 0; r < 8; r++)
        #pragma unroll
        for (int c = 0; c < 8; c++) acc[r][c] = 0.f;

    const int nk = K / BK;
    const long arow0 = (long)(m0 + ar);
    const long arow1 = (long)(m0 + ar + 64);
    const bool g0 = (m0 + ar)      < M;
    const bool g1 = (m0 + ar + 64) < M;

    {
        float4 pa0 = g0 ? *(const float4*)&A[arow0*K + 4*ac4] : make_float4(0,0,0,0);
        float4 pa1 = g1 ? *(const float4*)&A[arow1*K + 4*ac4] : make_float4(0,0,0,0);
        float4 pb0 = *(const float4*)&Bm[(long)br*Bs      + nb + 4*bc4];
        float4 pb1 = *(const float4*)&Bm[(long)(br+8)*Bs  + nb + 4*bc4];
        sA[0][4*ac4+0][ar]    = pa0.x; sA[0][4*ac4+1][ar]    = pa0.y;
        sA[0][4*ac4+2][ar]    = pa0.z; sA[0][4*ac4+3][ar]    = pa0.w;
        sA[0][4*ac4+0][ar+64] = pa1.x; sA[0][4*ac4+1][ar+64] = pa1.y;
        sA[0][4*ac4+2][ar+64] = pa1.z; sA[0][4*ac4+3][ar+64] = pa1.w;
        *(float4*)&sB[0][br  ][4*bc4] = pb0;
        *(float4*)&sB[0][br+8][4*bc4] = pb1;
    }
    __syncthreads();

    for (int kt = 0; kt < nk; kt++) {
        const int cur = kt & 1;
        float4 pa0, pa1, pb0, pb1;
        const bool more = (kt + 1 < nk);
        if (more) {
            const int k0 = (kt + 1) * BK;
            pa0 = g0 ? *(const float4*)&A[arow0*K + k0 + 4*ac4] : make_float4(0,0,0,0);
            pa1 = g1 ? *(const float4*)&A[arow1*K + k0 + 4*ac4] : make_float4(0,0,0,0);
            pb0 = *(const float4*)&Bm[(long)(k0+br)*Bs     + nb + 4*bc4];
            pb1 = *(const float4*)&Bm[(long)(k0+br+8)*Bs   + nb + 4*bc4];
        }
        #pragma unroll
        for (int kk = 0; kk < BK; kk++) {
            float a[8], b[8];
            *(float4*)&a[0] = *(float4*)&sA[cur][kk][ty*4];
            *(float4*)&a[4] = *(float4*)&sA[cur][kk][64 + ty*4];
            *(float4*)&b[0] = *(float4*)&sB[cur][kk][tx*4];
            *(float4*)&b[4] = *(float4*)&sB[cur][kk][64 + tx*4];
            #pragma unroll
            for (int r = 0; r < 8; r++)
                #pragma unroll
                for (int c = 0; c < 8; c++) acc[r][c] += a[r]*b[c];
        }
        if (more) {
            const int nxt = cur ^ 1;
            sA[nxt][4*ac4+0][ar]    = pa0.x; sA[nxt][4*ac4+1][ar]    = pa0.y;
            sA[nxt][4*ac4+2][ar]    = pa0.z; sA[nxt][4*ac4+3][ar]    = pa0.w;
            sA[nxt][4*ac4+0][ar+64] = pa1.x; sA[nxt][4*ac4+1][ar+64] = pa1.y;
            sA[nxt][4*ac4+2][ar+64] = pa1.z; sA[nxt][4*ac4+3][ar+64] = pa1.w;
            *(float4*)&sB[nxt][br  ][4*bc4] = pb0;
            *(float4*)&sB[nxt][br+8][4*bc4] = pb1;
            __syncthreads();
        }
    }

    #pragma unroll
    for (int rr = 0; rr < 8; rr++) {
        const int lrow = (rr < 4) ? (ty*4 + rr) : (64 + ty*4 + rr - 4);
        const int row = m0 + lrow;
        if (row >= M) continue;
        #pragma unroll
        for (int cg = 0; cg < 2; cg++) {
            const int lc = cg ? (64 + tx*4) : (tx*4);
            float4 v = make_float4(acc[rr][cg*4+0], acc[rr][cg*4+1],
                                   acc[rr][cg*4+2], acc[rr][cg*4+3]);
            const int pc = n0 + lc;
            const int h = pc >> 6, d = pc & 63;
            long base = ((long)h*P_ + row)*D_ + d;
            *(float4*)&g_relk[base] = v;
            uint32_t hi0, lo0, hi1, lo1;
            split2(v.x, v.y, hi0, lo0);
            split2(v.z, v.w, hi1, lo1);
            *(uint32_t*)&g_rh[base]     = hi0;
            *(uint32_t*)&g_rh[base + 2] = hi1;
            *(uint32_t*)&g_rl[base]     = lo0;
            *(uint32_t*)&g_rl[base + 2] = lo1;
        }
    }
}

// ---------------- mma.sync flash attention (ldmatrix) ----------------
#define AK_H   0u
#define AK_L   9216u
#define AVT_H  18432u
#define AVT_L  27648u
#define AR_H   36864u
#define AR_L   55296u
#define AG     73728u
#define AS     107520u
#define ATTN2_SMEM 108032

__global__ __launch_bounds__(128)
void attn_mma()
{
    extern __shared__ char sm2[];
    const uint32_t sb = smem_to_u32(sm2);
    float* sG = (float*)(sm2 + AG);
    float* sS = (float*)(sm2 + AS);

    const int tid = threadIdx.x;
    const int lane = tid & 31;
    const int w = tid >> 5;
    const int grp = lane >> 2;
    const int tig = lane & 3;
    const int qt = blockIdx.x;
    const int bh = blockIdx.y;
    const int b = bh >> 3, h = bh & 7;
    const int i0 = qt * 64;

    const int brow_l = ((lane >> 4) << 3) + (lane & 7);
    const int bcol_l = ((lane >> 3) & 1) * 16;

    // ---- Q fragments (persistent) ----
    const __nv_bfloat16* qbh = g_qh + (long)bh*N_*D_;
    const __nv_bfloat16* qbl = g_ql + (long)bh*N_*D_;
    const int rq0 = i0 + w*16 + grp, rq1 = rq0 + 8;
    uint32_t qfh[4][4], qfl[4][4];
    #pragma unroll
    for (int kf = 0; kf < 4; kf++) {
        qfh[kf][0] = *(const uint32_t*)(qbh + (long)rq0*D_ + kf*16 + 2*tig);
        qfh[kf][1] = *(const uint32_t*)(qbh + (long)rq1*D_ + kf*16 + 2*tig);
        qfh[kf][2] = *(const uint32_t*)(qbh + (long)rq0*D_ + kf*16 + 8 + 2*tig);
        qfh[kf][3] = *(const uint32_t*)(qbh + (long)rq1*D_ + kf*16 + 8 + 2*tig);
        qfl[kf][0] = *(const uint32_t*)(qbl + (long)rq0*D_ + kf*16 + 2*tig);
        qfl[kf][1] = *(const uint32_t*)(qbl + (long)rq1*D_ + kf*16 + 2*tig);
        qfl[kf][2] = *(const uint32_t*)(qbl + (long)rq0*D_ + kf*16 + 8 + 2*tig);
        qfl[kf][3] = *(const uint32_t*)(qbl + (long)rq1*D_ + kf*16 + 8 + 2*tig);
    }

    float o[8][4];
    #pragma unroll
    for (int nf = 0; nf < 8; nf++)
        #pragma unroll
        for (int e = 0; e < 4; e++) o[nf][e] = 0.f;
    float mrow[2] = {-1e30f, -1e30f};
    float lrow[2] = {0.f, 0.f};

    const unsigned char* tact = &g_tact[(b*QT_ + qt)*QT_];
    const long kbase  = (long)bh*N_*D_;
    const long vbase  = (long)bh*D_*N_;
    const long rbase  = (long)h*P_*D_;

    for (int jt = 0; jt < QT_; jt++) {
        if (!tact[jt]) continue;
        const int j0 = jt*64;
        const int p0 = j0 - i0 + (N_ - 1) - 63;

        __syncthreads();
        #pragma unroll
        for (int l = 0; l < 4; l++) {
            int i = tid + l*128;
            int r = i >> 3, c = i & 7;
            long krow = (kbase + (long)(j0 + r)*D_)*2;
            long vrow = (vbase + (long)r*N_ + j0)*2;
            cp_async16(sb + AK_H  + r*144 + c*16, (const char*)g_kh  + krow + c*16);
            cp_async16(sb + AK_L  + r*144 + c*16, (const char*)g_kl  + krow + c*16);
            cp_async16(sb + AVT_H + r*144 + c*16, (const char*)g_vth + vrow + c*16);
            cp_async16(sb + AVT_L + r*144 + c*16, (const char*)g_vtl + vrow + c*16);
        }
        #pragma unroll
        for (int l = 0; l < 8; l++) {
            int i = tid + l*128;
            int r = i >> 3, c = i & 7;
            int pr = p0 + r; if (pr > P_ - 1) pr = P_ - 1;
            long rrow = (rbase + (long)pr*D_)*2;
            cp_async16(sb + AR_H + r*144 + c*16, (const char*)g_rh + rrow + c*16);
            cp_async16(sb + AR_L + r*144 + c*16, (const char*)g_rl + rrow + c*16);
        }
        CP_COMMIT();

        sS[tid] = (tid < 127) ? g_srel[(long)h*P_ + p0 + tid] : 0.f;
        const unsigned long long* mb = g_mbits + ((long)(b*QT_ + qt)*QT_ + jt)*64;
        unsigned long long mw0 = mb[w*16 + grp];
        unsigned long long mw1 = mb[w*16 + grp + 8];

        CP_WAIT0();
        __syncthreads();

        // ---- content logits: Qc @ K^T ----
        float ca[8][4];
        #pragma unroll
        for (int nf = 0; nf < 8; nf++)
            #pragma unroll
            for (int e = 0; e < 4; e++) ca[nf][e] = 0.f;
        #pragma unroll
        for (int kf = 0; kf < 4; kf++) {
            #pragma unroll
            for (int np = 0; np < 4; np++) {
                uint32_t ro = (uint32_t)(np*16 + brow_l)*144 + kf*32 + bcol_l;
                uint32_t kh4[4], kl4[4];
                ldsm_x4(kh4, sb + AK_H + ro);
                ldsm_x4(kl4, sb + AK_L + ro);
                mma_bf16(ca[2*np],   qfh[kf], &kh4[0]);
                mma_bf16(ca[2*np],   qfh[kf], &kl4[0]);
                mma_bf16(ca[2*np],   qfl[kf], &kh4[0]);
                mma_bf16(ca[2*np+1], qfh[kf], &kh4[2]);
                mma_bf16(ca[2*np+1], qfh[kf], &kl4[2]);
                mma_bf16(ca[2*np+1], qfl[kf], &kh4[2]);
            }
        }

        // ---- G = Qc @ Rband^T (+S) ----
        const int grow = w*16 + grp;
        #pragma unroll
        for (int gh = 0; gh < 2; gh++) {
            float ga[8][4];
            #pragma unroll
            for (int nf = 0; nf < 8; nf++)
                #pragma unroll
                for (int e = 0; e < 4; e++) ga[nf][e] = 0.f;
            #pragma unroll
            for (int kf = 0; kf < 4; kf++) {
                #pragma unroll
                for (int np = 0; np < 4; np++) {
                    uint32_t ro = (uint32_t)(gh*64 + np*16 + brow_l)*144 + kf*32 + bcol_l;
                    uint32_t rh4[4], rl4[4];
                    ldsm_x4(rh4, sb + AR_H + ro);
                    ldsm_x4(rl4, sb + AR_L + ro);
                    mma_bf16(ga[2*np],   qfh[kf], &rh4[0]);
                    mma_bf16(ga[2*np],   qfh[kf], &rl4[0]);
                    mma_bf16(ga[2*np],   qfl[kf], &rh4[0]);
                    mma_bf16(ga[2*np+1], qfh[kf], &rh4[2]);
                    mma_bf16(ga[2*np+1], qfh[kf], &rl4[2]);
                    mma_bf16(ga[2*np+1], qfl[kf], &rh4[2]);
                }
            }
            #pragma unroll
            for (int nf = 0; nf < 8; nf++) {
                int col = gh*64 + 8*nf + 2*tig;
                float s0 = sS[col], s1 = sS[col + 1];
                sG[grow*132 + col]           = ga[nf][0] + s0;
                sG[grow*132 + col + 1]       = ga[nf][1] + s1;
                sG[(grow + 8)*132 + col]     = ga[nf][2] + s0;
                sG[(grow + 8)*132 + col + 1] = ga[nf][3] + s1;
            }
        }
        __syncwarp();

        // ---- gather + mask + online softmax ----
        float pv0[16], pv1[16];
        #pragma unroll
        for (int h2 = 0; h2 < 2; h2++) {
            const int rl = grow + 8*h2;
            const unsigned long long mw = h2 ? mw1 : mw0;
            float* pvv = h2 ? pv1 : pv0;
            float lg[16];
            float tmax = -1e30f;
            #pragma unroll
            for (int nf = 0; nf < 8; nf++) {
                #pragma unroll
                for (int e = 0; e < 2; e++) {
                    int c = 8*nf + 2*tig + e;
                    int pp = c - rl + 63;
                    float val = ca[nf][2*h2 + e] + sG[rl*132 + pp];
                    bool act = (mw >> c) & 1ull;
                    float lv = act ? val : -1e30f;
                    lg[nf*2 + e] = lv;
                    tmax = fmaxf(tmax, lv);
                }
            }
            tmax = fmaxf(tmax, __shfl_xor_sync(0xffffffffu, tmax, 1));
            tmax = fmaxf(tmax, __shfl_xor_sync(0xffffffffu, tmax, 2));
            float nm = fmaxf(mrow[h2], tmax);
            float corr = __expf(mrow[h2] - nm);
            mrow[h2] = nm;
            float ps = 0.f;
            #pragma unroll
            for (int e2 = 0; e2 < 16; e2++) {
                float p = (lg[e2] <= -1e29f) ? 0.f : __expf(lg[e2] - nm);
                pvv[e2] = p;
                ps += p;
            }
            ps += __shfl_xor_sync(0xffffffffu, ps, 1);
            ps += __shfl_xor_sync(0xffffffffu, ps, 2);
            lrow[h2] = lrow[h2]*corr + ps;
            #pragma unroll
            for (int nf = 0; nf < 8; nf++) {
                o[nf][2*h2]     *= corr;
                o[nf][2*h2 + 1] *= corr;
            }
        }

        // ---- P fragments ----
        uint32_t pfh[4][4], pfl[4][4];
        #pragma unroll
        for (int kf = 0; kf < 4; kf++) {
            split2(pv0[(2*kf)*2],   pv0[(2*kf)*2+1],   pfh[kf][0], pfl[kf][0]);
            split2(pv1[(2*kf)*2],   pv1[(2*kf)*2+1],   pfh[kf][1], pfl[kf][1]);
            split2(pv0[(2*kf+1)*2], pv0[(2*kf+1)*2+1], pfh[kf][2], pfl[kf][2]);
            split2(pv1[(2*kf+1)*2], pv1[(2*kf+1)*2+1], pfh[kf][3], pfl[kf][3]);
        }

        // ---- PV ----
        #pragma unroll
        for (int kf = 0; kf < 4; kf++) {
            #pragma unroll
            for (int np = 0; np < 4; np++) {
                uint32_t ro = (uint32_t)(np*16 + brow_l)*144 + kf*32 + bcol_l;
                uint32_t vh4[4], vl4[4];
                ldsm_x4(vh4, sb + AVT_H + ro);
                ldsm_x4(vl4, sb + AVT_L + ro);
                mma_bf16(o[2*np],   pfh[kf], &vh4[0]);
                mma_bf16(o[2*np],   pfh[kf], &vl4[0]);
                mma_bf16(o[2*np],   pfl[kf], &vh4[0]);
                mma_bf16(o[2*np+1], pfh[kf], &vh4[2]);
                mma_bf16(o[2*np+1], pfh[kf], &vl4[2]);
                mma_bf16(o[2*np+1], pfl[kf], &vh4[2]);
            }
        }
    }

    // ---- epilogue ----
    #pragma unroll
    for (int h2 = 0; h2 < 2; h2++) {
        float inv = 1.0f / lrow[h2];
        int rl = w*16 + grp + 8*h2;
        long rowbase = ((long)(b*N_ + i0 + rl))*(H_*D_) + h*D_;
        #pragma unroll
        for (int nf = 0; nf < 8; nf++) {
            float f0 = o[nf][2*h2]     * inv;
            float f1 = o[nf][2*h2 + 1] * inv;
            uint32_t hi, lo; split2(f0, f1, hi, lo);
            long idx = rowbase + 8*nf + 2*tig;
            *(uint32_t*)&g_ah[idx] = hi;
            *(uint32_t*)&g_al[idx] = lo;
        }
    }
}

// ---------------- launcher ----------------
extern "C" void kernel_launch(void* const* d_in, const int* in_sizes, int n_in,
                              void* d_out, int out_size)
{
    const float* x    = (const float*)d_in[0];
    const float* Wq   = (const float*)d_in[1];
    const float* Wk   = (const float*)d_in[2];
    const float* Wv   = (const float*)d_in[3];
    const float* Wrel = (const float*)d_in[4];
    const float* cb   = (const float*)d_in[5];
    const float* pb   = (const float*)d_in[6];
    const float* Wo   = (const float*)d_in[7];
    const float* bo   = (const float*)d_in[8];
    const float* pos  = (const float*)d_in[9];
    const unsigned char* lmu = (const unsigned char*)d_in[10];
    const unsigned char* isg = (const unsigned char*)d_in[11];
    float* out = (float*)d_out;

    cudaFuncSetAttribute(wmma_gemm, cudaFuncAttributeMaxDynamicSharedMemorySize, WG_SMEM);
    cudaFuncSetAttribute(attn_mma, cudaFuncAttributeMaxDynamicSharedMemorySize, ATTN2_SMEM);

    __nv_bfloat16 *xh_p, *xl_p, *wh_p, *wl_p, *woh_p, *wol_p, *ah_p, *al_p;
    cudaGetSymbolAddress((void**)&xh_p,  g_xh);
    cudaGetSymbolAddress((void**)&xl_p,  g_xl);
    cudaGetSymbolAddress((void**)&wh_p,  g_wh);
    cudaGetSymbolAddress((void**)&wl_p,  g_wl);
    cudaGetSymbolAddress((void**)&woh_p, g_woh);
    cudaGetSymbolAddress((void**)&wol_p, g_wol);
    cudaGetSymbolAddress((void**)&ah_p,  g_ah);
    cudaGetSymbolAddress((void**)&al_p,  g_al);

    // launch order chosen so ncu (-s 5 -c 1) profiles the QKV wmma_gemm (6th)
    probe_kernel<<<1, 1>>>(lmu);                                           // 1
    convA_kernel<<<(B_*N_*DIM_/4 + 255)/256, 256>>>(x, xh_p, xl_p,
                                                    B_*N_*DIM_/4);         // 2
    convT_all<<<dim3(768, 4), 256>>>(Wq, Wk, Wv, Wo);                      // 3
    gemm128<<<dim3(24, 4), 256>>>(pos, Wrel, P_, 192);                     // 4
    srel_kernel<<<dim3((P_ + 255)/256, H_), 256>>>(cb, pb);                // 5
    wmma_gemm<<<dim3(24, 12), 256, WG_SMEM>>>(xh_p, xl_p, wh_p, wl_p,
                                              cb, nullptr, DIM_, 0);       // 6  <- profiled
    tact_kernel<<<B_*QT_*QT_, 64>>>(lmu, isg);                             // 7
    attn_mma<<<dim3(QT_, B_*H_), 128, ATTN2_SMEM>>>();                     // 8
    wmma_gemm<<<dim3(24, 12), 256, WG_SMEM>>>(ah_p, al_p, woh_p, wol_p,
                                              bo, out, 512, 1);            // 9
}

// round 7
// speedup vs baseline: 3.9228x; 1.0653x over previous
#include <cuda_runtime.h>
#include <cuda_bf16.h>
#include <math.h>
#include <stdint.h>

#define B_   2
#define N_   1536
#define DIM_ 1536
#define H_   8
#define D_   64
#define P_   3071      // 2N-1
#define RP_  3072      // padded row stride for rel tables
#define QT_  24        // N/64 tiles

// ---------------- device scratch (zero-initialized statics) ----------------
__device__ unsigned char g_tact[B_*QT_*QT_];
__device__ unsigned long long g_mbits[B_*QT_*QT_*64];

__device__ __nv_bfloat16 g_xh[B_*N_*DIM_];
__device__ __nv_bfloat16 g_xl[B_*N_*DIM_];
__device__ __nv_bfloat16 g_ph[RP_*192];           // pos_embed hi (row 3071 zero)
__device__ __nv_bfloat16 g_pl[RP_*192];
__device__ __nv_bfloat16 g_wh[1536*DIM_];
__device__ __nv_bfloat16 g_wl[1536*DIM_];
__device__ __nv_bfloat16 g_wrh[512*192];          // Wrel^T hi [512][192]
__device__ __nv_bfloat16 g_wrl[512*192];
__device__ __nv_bfloat16 g_woh[1536*512];
__device__ __nv_bfloat16 g_wol[1536*512];
__device__ __nv_bfloat16 g_ah[B_*N_*H_*D_];
__device__ __nv_bfloat16 g_al[B_*N_*H_*D_];
__device__ __nv_bfloat16 g_qh[B_*H_*N_*D_];       // q*scale + cb
__device__ __nv_bfloat16 g_ql[B_*H_*N_*D_];
__device__ __nv_bfloat16 g_qph[B_*H_*N_*D_];      // q*scale + pb
__device__ __nv_bfloat16 g_qpl[B_*H_*N_*D_];
__device__ __nv_bfloat16 g_kh[B_*H_*N_*D_];
__device__ __nv_bfloat16 g_kl[B_*H_*N_*D_];
__device__ __nv_bfloat16 g_vth[B_*H_*D_*N_];
__device__ __nv_bfloat16 g_vtl[B_*H_*D_*N_];
__device__ __nv_bfloat16 g_rh[H_*RP_*D_];         // rel_k hi [h][p(3072)][d]
__device__ __nv_bfloat16 g_rl[H_*RP_*D_];

// ---------------- helpers ----------------
__device__ __forceinline__ uint32_t smem_to_u32(const void* p) {
    uint32_t a;
    asm("{ .reg .u64 t; cvta.to.shared.u64 t, %1; cvt.u32.u64 %0, t; }" : "=r"(a) : "l"(p));
    return a;
}
__device__ __forceinline__ void cp_async16(uint32_t saddr, const void* g) {
    asm volatile("cp.async.cg.shared.global [%0], [%1], 16;" :: "r"(saddr), "l"(g));
}
#define CP_COMMIT() asm volatile("cp.async.commit_group;" ::: "memory")
#define CP_WAIT0()  asm volatile("cp.async.wait_group 0;" ::: "memory")

__device__ __forceinline__ void mma_bf16(float* c, const uint32_t* a, const uint32_t* b) {
    asm volatile("mma.sync.aligned.m16n8k16.row.col.f32.bf16.bf16.f32 "
        "{%0,%1,%2,%3}, {%4,%5,%6,%7}, {%8,%9}, {%0,%1,%2,%3};"
        : "+f"(c[0]), "+f"(c[1]), "+f"(c[2]), "+f"(c[3])
        : "r"(a[0]), "r"(a[1]), "r"(a[2]), "r"(a[3]), "r"(b[0]), "r"(b[1]));
}
__device__ __forceinline__ void ldsm_x4(uint32_t* r, uint32_t addr) {
    asm volatile("ldmatrix.sync.aligned.m8n8.x4.shared.b16 {%0,%1,%2,%3}, [%4];"
        : "=r"(r[0]), "=r"(r[1]), "=r"(r[2]), "=r"(r[3]) : "r"(addr));
}
__device__ __forceinline__ void split2(float f0, float f1, uint32_t& hi, uint32_t& lo) {
    __nv_bfloat16 h0 = __float2bfloat16(f0), h1 = __float2bfloat16(f1);
    __nv_bfloat162 hh(h0, h1);
    hi = *(uint32_t*)&hh;
    __nv_bfloat16 l0 = __float2bfloat16(f0 - __bfloat162float(h0));
    __nv_bfloat16 l1 = __float2bfloat16(f1 - __bfloat162float(h1));
    __nv_bfloat162 ll(l0, l1);
    lo = *(uint32_t*)&ll;
}
__device__ __forceinline__ bool rd_mask(const unsigned char* p, long idx, int mt) {
    if (mt == 0) return p[idx] != 0;
    if (mt == 1) return ((const int*)p)[idx] != 0;
    return ((const float*)p)[idx] != 0.0f;
}

// ---------------- conversions ----------------
__global__ void convA_kernel(const float* __restrict__ s, __nv_bfloat16* __restrict__ h,
                             __nv_bfloat16* __restrict__ l, int n4)
{
    int i = blockIdx.x*blockDim.x + threadIdx.x;
    if (i >= n4) return;
    float4 v = ((const float4*)s)[i];
    float a[4] = {v.x, v.y, v.z, v.w};
    __nv_bfloat16 hh[4], ll[4];
    #pragma unroll
    for (int j = 0; j < 4; j++) {
        hh[j] = __float2bfloat16(a[j]);
        ll[j] = __float2bfloat16(a[j] - __bfloat162float(hh[j]));
    }
    ((__nv_bfloat162*)h)[i*2+0] = __nv_bfloat162(hh[0], hh[1]);
    ((__nv_bfloat162*)h)[i*2+1] = __nv_bfloat162(hh[2], hh[3]);
    ((__nv_bfloat162*)l)[i*2+0] = __nv_bfloat162(ll[0], ll[1]);
    ((__nv_bfloat162*)l)[i*2+1] = __nv_bfloat162(ll[2], ll[3]);
}

// merged transpose+convert for Wq/Wk/Wv/Wo/Wrel. grid (768, 5).
__global__ void convT_all(const float* __restrict__ Wq, const float* __restrict__ Wk,
                          const float* __restrict__ Wv, const float* __restrict__ Wo,
                          const float* __restrict__ Wrel)
{
    __shared__ float t[32][33];
    const int job = blockIdx.y;
    const int idx = blockIdx.x;
    const float* src; __nv_bfloat16 *dh, *dl;
    int R, C, c0, r0;
    if (job < 3) {
        src = (job == 0) ? Wq : (job == 1) ? Wk : Wv;
        dh = g_wh + (long)job*512*1536; dl = g_wl + (long)job*512*1536;
        R = 1536; C = 512;
        c0 = (idx & 15)*32; r0 = (idx >> 4)*32;
    } else if (job == 3) {
        src = Wo; dh = g_woh; dl = g_wol;
        R = 512; C = 1536;
        c0 = (idx % 48)*32; r0 = (idx / 48)*32;
    } else {
        if (idx >= 96) return;
        src = Wrel; dh = g_wrh; dl = g_wrl;
        R = 192; C = 512;
        c0 = (idx & 15)*32; r0 = (idx >> 4)*32;
    }
    int tx = threadIdx.x & 31, ty = threadIdx.x >> 5;
    #pragma unroll
    for (int i = 0; i < 4; i++)
        t[ty + i*8][tx] = src[(long)(r0 + ty + i*8)*C + c0 + tx];
    __syncthreads();
    #pragma unroll
    for (int i = 0; i < 4; i++) {
        int c = c0 + ty + i*8, r = r0 + tx;
        float v = t[tx][ty + i*8];
        __nv_bfloat16 hv = __float2bfloat16(v);
        dh[(long)c*R + r] = hv;
        dl[(long)c*R + r] = __float2bfloat16(v - __bfloat162float(hv));
    }
}

// ---------------- mask pack + tile-activity (mtype computed inline) ----------------
__global__ void tact_kernel(const unsigned char* __restrict__ lm,
                            const unsigned char* __restrict__ isg)
{
    int t  = blockIdx.x;
    int jt = t % QT_;
    int qt = (t / QT_) % QT_;
    int b  = t / (QT_*QT_);
    int i0 = qt*64, j0 = jt*64;
    unsigned int w0 = *(const unsigned int*)lm;
    int mt;
    if ((w0 & 0xFFu) == 1u && ((w0 >> 8) & 0xFFu) == 1u) mt = 0;
    else if (w0 == 1u) mt = 1;
    else mt = 2;
    int r = threadIdx.x;
    bool rg = rd_mask(isg, (long)b*N_ + i0 + r, mt);
    unsigned long long bits = 0ull;
    for (int c = 0; c < 64; c++) {
        bool a = rg || rd_mask(isg, (long)b*N_ + j0 + c, mt)
                    || rd_mask(lm, (long)(i0+r)*N_ + j0 + c, mt);
        bits |= (unsigned long long)(a ? 1 : 0) << c;
    }
    g_mbits[(long)t*64 + r] = bits;
    int any = __syncthreads_or(bits != 0ull);
    if (r == 0) g_tact[t] = (unsigned char)(any ? 1 : 0);
}

// ---------------- warp-MMA bf16 split-precision GEMM (ldmatrix) ----------------
// mode 0: QKV -> q(+cb)/qp(+pb)/k/v^T bf16 hi/lo   (bias=cb, bias2=pb)
// mode 1: out = A@Wo^T + bias -> fp32 Cout
// mode 2: rel -> g_rh/g_rl [h][p][d]
#define TPAD   40
#define TBYTES (128*TPAD*2)
#define STAGE  (4*TBYTES)
#define WG_SMEM (2*STAGE)

__global__ __launch_bounds__(256)
void wmma_gemm(const __nv_bfloat16* __restrict__ Ah, const __nv_bfloat16* __restrict__ Al,
               const __nv_bfloat16* __restrict__ Bh, const __nv_bfloat16* __restrict__ Bl,
               const float* __restrict__ bias, const float* __restrict__ bias2,
               float* __restrict__ Cout, int K, int mode)
{
    extern __shared__ char smem[];
    const uint32_t sb = smem_to_u32(smem);
    const int tid = threadIdx.x;
    const int lane = tid & 31;
    const int wid = tid >> 5;
    const int warp_m = wid >> 2;
    const int warp_n = wid & 3;
    const int grp = lane >> 2;
    const int tig = lane & 3;
    const int m0 = blockIdx.x * 128, n0 = blockIdx.y * 128;

    const int arow_l = lane & 15;
    const int acol_l = (lane >> 4) * 16;
    const int brow_l = ((lane >> 4) << 3) + (lane & 7);
    const int bcol_l = ((lane >> 3) & 1) * 16;

    const char* srcs[4] = {(const char*)Ah, (const char*)Al, (const char*)Bh, (const char*)Bl};
    const int rb[4] = {m0, m0, n0, n0};
    const long rowB = (long)K * 2;

    auto issue_stage = [&](int kt, int st) {
        const uint32_t sbase = sb + st*STAGE;
        #pragma unroll
        for (int l = 0; l < 8; l++) {
            int i = tid + l*256;
            int t = i >> 9, r = (i >> 2) & 127, c = i & 3;
            const char* g = srcs[t] + (long)(rb[t] + r)*rowB + kt*64 + c*16;
            cp_async16(sbase + t*TBYTES + r*80 + c*16, g);
        }
        CP_COMMIT();
    };

    float acc[4][4][4];
    #pragma unroll
    for (int i = 0; i < 4; i++)
        #pragma unroll
        for (int j = 0; j < 4; j++)
            #pragma unroll
            for (int e = 0; e < 4; e++) acc[i][j][e] = 0.f;

    const int nk = K / 32;
    issue_stage(0, 0);

    for (int kt = 0; kt < nk; kt++) {
        CP_WAIT0();
        __syncthreads();
        if (kt + 1 < nk) issue_stage(kt + 1, (kt + 1) & 1);

        const uint32_t stg = sb + (kt & 1)*STAGE;
        const uint32_t aoffh = stg + 0*TBYTES;
        const uint32_t aoffl = stg + 1*TBYTES;
        const uint32_t boffh = stg + 2*TBYTES;
        const uint32_t boffl = stg + 3*TBYTES;

        #pragma unroll
        for (int ks = 0; ks < 2; ks++) {
            const uint32_t kb = ks*32;
            uint32_t bh[4][2], bl[4][2];
            #pragma unroll
            for (int jp = 0; jp < 2; jp++) {
                uint32_t ro = (uint32_t)(warp_n*32 + jp*16 + brow_l)*80 + kb + bcol_l;
                uint32_t r4[4];
                ldsm_x4(r4, boffh + ro);
                bh[2*jp][0] = r4[0]; bh[2*jp][1] = r4[1];
                bh[2*jp+1][0] = r4[2]; bh[2*jp+1][1] = r4[3];
                ldsm_x4(r4, boffl + ro);
                bl[2*jp][0] = r4[0]; bl[2*jp][1] = r4[1];
                bl[2*jp+1][0] = r4[2]; bl[2*jp+1][1] = r4[3];
            }
            #pragma unroll
            for (int i = 0; i < 4; i++) {
                uint32_t ro = (uint32_t)(warp_m*64 + i*16 + arow_l)*80 + kb + acol_l;
                uint32_t ah[4], al[4];
                ldsm_x4(ah, aoffh + ro);
                ldsm_x4(al, aoffl + ro);
                #pragma unroll
                for (int j = 0; j < 4; j++) {
                    mma_bf16(acc[i][j], ah, bh[j]);
                    mma_bf16(acc[i][j], ah, bl[j]);
                    mma_bf16(acc[i][j], al, bh[j]);
                }
            }
        }
        __syncthreads();
    }

    // epilogue
    #pragma unroll
    for (int i = 0; i < 4; i++) {
        #pragma unroll
        for (int j = 0; j < 4; j++) {
            const int r0 = m0 + warp_m*64 + i*16 + grp;
            const int c0 = n0 + warp_n*32 + j*8 + 2*tig;
            #pragma unroll
            for (int half = 0; half < 2; half++) {
                const int row = r0 + half*8;
                float v0 = acc[i][j][half*2 + 0];
                float v1 = acc[i][j][half*2 + 1];
                if (mode == 1) {
                    Cout[(long)row*1536 + c0]     = v0 + bias[c0];
                    Cout[(long)row*1536 + c0 + 1] = v1 + bias[c0 + 1];
                } else if (mode == 2) {
                    const int h = c0 >> 6, d = c0 & 63;
                    uint32_t hi, lo; split2(v0, v1, hi, lo);
                    long idx = ((long)h*RP_ + row)*D_ + d;
                    *(uint32_t*)&g_rh[idx] = hi;
                    *(uint32_t*)&g_rl[idx] = lo;
                } else {
                    const int sel = c0 >> 9, pc = c0 & 511;
                    const int h = pc >> 6, d = pc & 63;
                    const int bb = (row >= N_) ? 1 : 0;
                    const int ii = row - bb*N_;
                    const int bhd = bb*H_ + h;
                    if (sel == 0) {
                        float s0 = v0*0.125f, s1 = v1*0.125f;
                        long idx = ((long)bhd*N_ + ii)*D_ + d;
                        uint32_t hi, lo;
                        split2(s0 + bias[pc], s1 + bias[pc + 1], hi, lo);
                        *(uint32_t*)&g_qh[idx] = hi;
                        *(uint32_t*)&g_ql[idx] = lo;
                        split2(s0 + bias2[pc], s1 + bias2[pc + 1], hi, lo);
                        *(uint32_t*)&g_qph[idx] = hi;
                        *(uint32_t*)&g_qpl[idx] = lo;
                    } else if (sel == 1) {
                        uint32_t hi, lo; split2(v0, v1, hi, lo);
                        long idx = ((long)bhd*N_ + ii)*D_ + d;
                        *(uint32_t*)&g_kh[idx] = hi;
                        *(uint32_t*)&g_kl[idx] = lo;
                    } else {
                        __nv_bfloat16 h0 = __float2bfloat16(v0);
                        __nv_bfloat16 h1 = __float2bfloat16(v1);
                        long i0x = ((long)bhd*D_ + d)*N_ + ii;
                        long i1x = ((long)bhd*D_ + d + 1)*N_ + ii;
                        g_vth[i0x] = h0;
                        g_vth[i1x] = h1;
                        g_vtl[i0x] = __float2bfloat16(v0 - __bfloat162float(h0));
                        g_vtl[i1x] = __float2bfloat16(v1 - __bfloat162float(h1));
                    }
                }
            }
        }
    }
}

// ---------------- mma.sync flash attention (ldmatrix) ----------------
#define AK_H   0u
#define AK_L   9216u
#define AVT_H  18432u
#define AVT_L  27648u
#define AR_H   36864u
#define AR_L   55296u
#define AG     73728u
#define ATTN2_SMEM (73728 + 64*132*4)

__global__ __launch_bounds__(128)
void attn_mma()
{
    extern __shared__ char sm2[];
    const uint32_t sb = smem_to_u32(sm2);
    float* sG = (float*)(sm2 + AG);

    const int tid = threadIdx.x;
    const int lane = tid & 31;
    const int w = tid >> 5;
    const int grp = lane >> 2;
    const int tig = lane & 3;
    const int qt = blockIdx.x;
    const int bh = blockIdx.y;
    const int b = bh >> 3, h = bh & 7;
    const int i0 = qt * 64;

    const int brow_l = ((lane >> 4) << 3) + (lane & 7);
    const int bcol_l = ((lane >> 3) & 1) * 16;

    // ---- Q fragments (persistent): content (cb) + positional (pb) ----
    const __nv_bfloat16* qbh = g_qh  + (long)bh*N_*D_;
    const __nv_bfloat16* qbl = g_ql  + (long)bh*N_*D_;
    const __nv_bfloat16* pqh = g_qph + (long)bh*N_*D_;
    const __nv_bfloat16* pql = g_qpl + (long)bh*N_*D_;
    const int rq0 = i0 + w*16 + grp, rq1 = rq0 + 8;
    uint32_t qfh[4][4], qfl[4][4], qgh[4][4], qgl[4][4];
    #pragma unroll
    for (int kf = 0; kf < 4; kf++) {
        qfh[kf][0] = *(const uint32_t*)(qbh + (long)rq0*D_ + kf*16 + 2*tig);
        qfh[kf][1] = *(const uint32_t*)(qbh + (long)rq1*D_ + kf*16 + 2*tig);
        qfh[kf][2] = *(const uint32_t*)(qbh + (long)rq0*D_ + kf*16 + 8 + 2*tig);
        qfh[kf][3] = *(const uint32_t*)(qbh + (long)rq1*D_ + kf*16 + 8 + 2*tig);
        qfl[kf][0] = *(const uint32_t*)(qbl + (long)rq0*D_ + kf*16 + 2*tig);
        qfl[kf][1] = *(const uint32_t*)(qbl + (long)rq1*D_ + kf*16 + 2*tig);
        qfl[kf][2] = *(const uint32_t*)(qbl + (long)rq0*D_ + kf*16 + 8 + 2*tig);
        qfl[kf][3] = *(const uint32_t*)(qbl + (long)rq1*D_ + kf*16 + 8 + 2*tig);
        qgh[kf][0] = *(const uint32_t*)(pqh + (long)rq0*D_ + kf*16 + 2*tig);
        qgh[kf][1] = *(const uint32_t*)(pqh + (long)rq1*D_ + kf*16 + 2*tig);
        qgh[kf][2] = *(const uint32_t*)(pqh + (long)rq0*D_ + kf*16 + 8 + 2*tig);
        qgh[kf][3] = *(const uint32_t*)(pqh + (long)rq1*D_ + kf*16 + 8 + 2*tig);
        qgl[kf][0] = *(const uint32_t*)(pql + (long)rq0*D_ + kf*16 + 2*tig);
        qgl[kf][1] = *(const uint32_t*)(pql + (long)rq1*D_ + kf*16 + 2*tig);
        qgl[kf][2] = *(const uint32_t*)(pql + (long)rq0*D_ + kf*16 + 8 + 2*tig);
        qgl[kf][3] = *(const uint32_t*)(pql + (long)rq1*D_ + kf*16 + 8 + 2*tig);
    }

    float o[8][4];
    #pragma unroll
    for (int nf = 0; nf < 8; nf++)
        #pragma unroll
        for (int e = 0; e < 4; e++) o[nf][e] = 0.f;
    float mrow[2] = {-1e30f, -1e30f};
    float lrow[2] = {0.f, 0.f};

    const unsigned char* tact = &g_tact[(b*QT_ + qt)*QT_];
    const long kbase  = (long)bh*N_*D_;
    const long vbase  = (long)bh*D_*N_;
    const long rbase  = (long)h*RP_*D_;

    for (int jt = 0; jt < QT_; jt++) {
        if (!tact[jt]) continue;
        const int j0 = jt*64;
        const int p0 = j0 - i0 + (N_ - 1) - 63;

        __syncthreads();
        #pragma unroll
        for (int l = 0; l < 4; l++) {
            int i = tid + l*128;
            int r = i >> 3, c = i & 7;
            long krow = (kbase + (long)(j0 + r)*D_)*2;
            long vrow = (vbase + (long)r*N_ + j0)*2;
            cp_async16(sb + AK_H  + r*144 + c*16, (const char*)g_kh  + krow + c*16);
            cp_async16(sb + AK_L  + r*144 + c*16, (const char*)g_kl  + krow + c*16);
            cp_async16(sb + AVT_H + r*144 + c*16, (const char*)g_vth + vrow + c*16);
            cp_async16(sb + AVT_L + r*144 + c*16, (const char*)g_vtl + vrow + c*16);
        }
        #pragma unroll
        for (int l = 0; l < 8; l++) {
            int i = tid + l*128;
            int r = i >> 3, c = i & 7;
            long rrow = (rbase + (long)(p0 + r)*D_)*2;
            cp_async16(sb + AR_H + r*144 + c*16, (const char*)g_rh + rrow + c*16);
            cp_async16(sb + AR_L + r*144 + c*16, (const char*)g_rl + rrow + c*16);
        }
        CP_COMMIT();

        const unsigned long long* mb = g_mbits + ((long)(b*QT_ + qt)*QT_ + jt)*64;
        unsigned long long mw0 = mb[w*16 + grp];
        unsigned long long mw1 = mb[w*16 + grp + 8];

        CP_WAIT0();
        __syncthreads();

        // ---- content logits: Qc @ K^T ----
        float ca[8][4];
        #pragma unroll
        for (int nf = 0; nf < 8; nf++)
            #pragma unroll
            for (int e = 0; e < 4; e++) ca[nf][e] = 0.f;
        #pragma unroll
        for (int kf = 0; kf < 4; kf++) {
            #pragma unroll
            for (int np = 0; np < 4; np++) {
                uint32_t ro = (uint32_t)(np*16 + brow_l)*144 + kf*32 + bcol_l;
                uint32_t kh4[4], kl4[4];
                ldsm_x4(kh4, sb + AK_H + ro);
                ldsm_x4(kl4, sb + AK_L + ro);
                mma_bf16(ca[2*np],   qfh[kf], &kh4[0]);
                mma_bf16(ca[2*np],   qfh[kf], &kl4[0]);
                mma_bf16(ca[2*np],   qfl[kf], &kh4[0]);
                mma_bf16(ca[2*np+1], qfh[kf], &kh4[2]);
                mma_bf16(ca[2*np+1], qfh[kf], &kl4[2]);
                mma_bf16(ca[2*np+1], qfl[kf], &kh4[2]);
            }
        }

        // ---- G = Qp @ Rband^T ----
        const int grow = w*16 + grp;
        #pragma unroll
        for (int gh = 0; gh < 2; gh++) {
            float ga[8][4];
            #pragma unroll
            for (int nf = 0; nf < 8; nf++)
                #pragma unroll
                for (int e = 0; e < 4; e++) ga[nf][e] = 0.f;
            #pragma unroll
            for (int kf = 0; kf < 4; kf++) {
                #pragma unroll
                for (int np = 0; np < 4; np++) {
                    uint32_t ro = (uint32_t)(gh*64 + np*16 + brow_l)*144 + kf*32 + bcol_l;
                    uint32_t rh4[4], rl4[4];
                    ldsm_x4(rh4, sb + AR_H + ro);
                    ldsm_x4(rl4, sb + AR_L + ro);
                    mma_bf16(ga[2*np],   qgh[kf], &rh4[0]);
                    mma_bf16(ga[2*np],   qgh[kf], &rl4[0]);
                    mma_bf16(ga[2*np],   qgl[kf], &rh4[0]);
                    mma_bf16(ga[2*np+1], qgh[kf], &rh4[2]);
                    mma_bf16(ga[2*np+1], qgh[kf], &rl4[2]);
                    mma_bf16(ga[2*np+1], qgl[kf], &rh4[2]);
                }
            }
            #pragma unroll
            for (int nf = 0; nf < 8; nf++) {
                int col = gh*64 + 8*nf + 2*tig;
                sG[grow*132 + col]           = ga[nf][0];
                sG[grow*132 + col + 1]       = ga[nf][1];
                sG[(grow + 8)*132 + col]     = ga[nf][2];
                sG[(grow + 8)*132 + col + 1] = ga[nf][3];
            }
        }
        __syncwarp();

        // ---- gather + mask + online softmax ----
        float pv0[16], pv1[16];
        #pragma unroll
        for (int h2 = 0; h2 < 2; h2++) {
            const int rl = grow + 8*h2;
            const unsigned long long mw = h2 ? mw1 : mw0;
            float* pvv = h2 ? pv1 : pv0;
            float lg[16];
            float tmax = -1e30f;
            #pragma unroll
            for (int nf = 0; nf < 8; nf++) {
                #pragma unroll
                for (int e = 0; e < 2; e++) {
                    int c = 8*nf + 2*tig + e;
                    int pp = c - rl + 63;
                    float val = ca[nf][2*h2 + e] + sG[rl*132 + pp];
                    bool act = (mw >> c) & 1ull;
                    float lv = act ? val : -1e30f;
                    lg[nf*2 + e] = lv;
                    tmax = fmaxf(tmax, lv);
                }
            }
            tmax = fmaxf(tmax, __shfl_xor_sync(0xffffffffu, tmax, 1));
            tmax = fmaxf(tmax, __shfl_xor_sync(0xffffffffu, tmax, 2));
            float nm = fmaxf(mrow[h2], tmax);
            float corr = __expf(mrow[h2] - nm);
            mrow[h2] = nm;
            float ps = 0.f;
            #pragma unroll
            for (int e2 = 0; e2 < 16; e2++) {
                float p = (lg[e2] <= -1e29f) ? 0.f : __expf(lg[e2] - nm);
                pvv[e2] = p;
                ps += p;
            }
            ps += __shfl_xor_sync(0xffffffffu, ps, 1);
            ps += __shfl_xor_sync(0xffffffffu, ps, 2);
            lrow[h2] = lrow[h2]*corr + ps;
            #pragma unroll
            for (int nf = 0; nf < 8; nf++) {
                o[nf][2*h2]     *= corr;
                o[nf][2*h2 + 1] *= corr;
            }
        }

        // ---- P fragments ----
        uint32_t pfh[4][4], pfl[4][4];
        #pragma unroll
        for (int kf = 0; kf < 4; kf++) {
            split2(pv0[(2*kf)*2],   pv0[(2*kf)*2+1],   pfh[kf][0], pfl[kf][0]);
            split2(pv1[(2*kf)*2],   pv1[(2*kf)*2+1],   pfh[kf][1], pfl[kf][1]);
            split2(pv0[(2*kf+1)*2], pv0[(2*kf+1)*2+1], pfh[kf][2], pfl[kf][2]);
            split2(pv1[(2*kf+1)*2], pv1[(2*kf+1)*2+1], pfh[kf][3], pfl[kf][3]);
        }

        // ---- PV ----
        #pragma unroll
        for (int kf = 0; kf < 4; kf++) {
            #pragma unroll
            for (int np = 0; np < 4; np++) {
                uint32_t ro = (uint32_t)(np*16 + brow_l)*144 + kf*32 + bcol_l;
                uint32_t vh4[4], vl4[4];
                ldsm_x4(vh4, sb + AVT_H + ro);
                ldsm_x4(vl4, sb + AVT_L + ro);
                mma_bf16(o[2*np],   pfh[kf], &vh4[0]);
                mma_bf16(o[2*np],   pfh[kf], &vl4[0]);
                mma_bf16(o[2*np],   pfl[kf], &vh4[0]);
                mma_bf16(o[2*np+1], pfh[kf], &vh4[2]);
                mma_bf16(o[2*np+1], pfh[kf], &vl4[2]);
                mma_bf16(o[2*np+1], pfl[kf], &vh4[2]);
            }
        }
    }

    // ---- epilogue ----
    #pragma unroll
    for (int h2 = 0; h2 < 2; h2++) {
        float inv = 1.0f / lrow[h2];
        int rl = w*16 + grp + 8*h2;
        long rowbase = ((long)(b*N_ + i0 + rl))*(H_*D_) + h*D_;
        #pragma unroll
        for (int nf = 0; nf < 8; nf++) {
            float f0 = o[nf][2*h2]     * inv;
            float f1 = o[nf][2*h2 + 1] * inv;
            uint32_t hi, lo; split2(f0, f1, hi, lo);
            long idx = rowbase + 8*nf + 2*tig;
            *(uint32_t*)&g_ah[idx] = hi;
            *(uint32_t*)&g_al[idx] = lo;
        }
    }
}

// ---------------- launcher ----------------
extern "C" void kernel_launch(void* const* d_in, const int* in_sizes, int n_in,
                              void* d_out, int out_size)
{
    const float* x    = (const float*)d_in[0];
    const float* Wq   = (const float*)d_in[1];
    const float* Wk   = (const float*)d_in[2];
    const float* Wv   = (const float*)d_in[3];
    const float* Wrel = (const float*)d_in[4];
    const float* cb   = (const float*)d_in[5];
    const float* pb   = (const float*)d_in[6];
    const float* Wo   = (const float*)d_in[7];
    const float* bo   = (const float*)d_in[8];
    const float* pos  = (const float*)d_in[9];
    const unsigned char* lmu = (const unsigned char*)d_in[10];
    const unsigned char* isg = (const unsigned char*)d_in[11];
    float* out = (float*)d_out;

    cudaFuncSetAttribute(wmma_gemm, cudaFuncAttributeMaxDynamicSharedMemorySize, WG_SMEM);
    cudaFuncSetAttribute(attn_mma, cudaFuncAttributeMaxDynamicSharedMemorySize, ATTN2_SMEM);

    __nv_bfloat16 *xh_p, *xl_p, *ph_p, *pl_p, *wh_p, *wl_p, *wrh_p, *wrl_p,
                  *woh_p, *wol_p, *ah_p, *al_p;
    cudaGetSymbolAddress((void**)&xh_p,  g_xh);
    cudaGetSymbolAddress((void**)&xl_p,  g_xl);
    cudaGetSymbolAddress((void**)&ph_p,  g_ph);
    cudaGetSymbolAddress((void**)&pl_p,  g_pl);
    cudaGetSymbolAddress((void**)&wh_p,  g_wh);
    cudaGetSymbolAddress((void**)&wl_p,  g_wl);
    cudaGetSymbolAddress((void**)&wrh_p, g_wrh);
    cudaGetSymbolAddress((void**)&wrl_p, g_wrl);
    cudaGetSymbolAddress((void**)&woh_p, g_woh);
    cudaGetSymbolAddress((void**)&wol_p, g_wol);
    cudaGetSymbolAddress((void**)&ah_p,  g_ah);
    cudaGetSymbolAddress((void**)&al_p,  g_al);

    convA_kernel<<<(B_*N_*DIM_/4 + 255)/256, 256>>>(x, xh_p, xl_p,
                                                    B_*N_*DIM_/4);          // 1
    convT_all<<<dim3(768, 5), 256>>>(Wq, Wk, Wv, Wo, Wrel);                 // 2
    convA_kernel<<<(P_*192/4 + 255)/256, 256>>>(pos, ph_p, pl_p, P_*192/4); // 3
    wmma_gemm<<<dim3(24, 4), 256, WG_SMEM>>>(ph_p, pl_p, wrh_p, wrl_p,
                                             nullptr, nullptr, nullptr,
                                             192, 2);                       // 4  rel
    tact_kernel<<<B_*QT_*QT_, 64>>>(lmu, isg);                              // 5
    wmma_gemm<<<dim3(24, 12), 256, WG_SMEM>>>(xh_p, xl_p, wh_p, wl_p,
                                              cb, pb, nullptr, DIM_, 0);    // 6  QKV
    attn_mma<<<dim3(QT_, B_*H_), 128, ATTN2_SMEM>>>();                      // 7
    wmma_gemm<<<dim3(24, 12), 256, WG_SMEM>>>(ah_p, al_p, woh_p, wol_p,
                                              bo, nullptr, out, 512, 1);    // 8  out
}

// round 8
// speedup vs baseline: 4.0532x; 1.0332x over previous
#include <cuda_runtime.h>
#include <cuda_bf16.h>
#include <math.h>
#include <stdint.h>

#define B_   2
#define N_   1536
#define DIM_ 1536
#define H_   8
#define D_   64
#define P_   3071      // 2N-1
#define RP_  3072      // padded row stride for rel tables
#define QT_  24        // N/64 tiles

// ---------------- device scratch (zero-initialized statics) ----------------
__device__ unsigned char g_tact[B_*QT_*QT_];
__device__ unsigned long long g_mbits[B_*QT_*QT_*64];

__device__ __nv_bfloat16 g_xh[B_*N_*DIM_];
__device__ __nv_bfloat16 g_xl[B_*N_*DIM_];
__device__ __nv_bfloat16 g_ph[RP_*192];           // pos_embed hi (row 3071 zero)
__device__ __nv_bfloat16 g_pl[RP_*192];
__device__ __nv_bfloat16 g_wh[1536*DIM_];
__device__ __nv_bfloat16 g_wl[1536*DIM_];
__device__ __nv_bfloat16 g_wrh[512*192];          // Wrel^T hi [512][192]
__device__ __nv_bfloat16 g_wrl[512*192];
__device__ __nv_bfloat16 g_woh[1536*512];
__device__ __nv_bfloat16 g_wol[1536*512];
__device__ __nv_bfloat16 g_ah[B_*N_*H_*D_];
__device__ __nv_bfloat16 g_al[B_*N_*H_*D_];
__device__ __nv_bfloat16 g_qh[B_*H_*N_*D_];       // q*scale + cb
__device__ __nv_bfloat16 g_ql[B_*H_*N_*D_];
__device__ __nv_bfloat16 g_qph[B_*H_*N_*D_];      // q*scale + pb
__device__ __nv_bfloat16 g_qpl[B_*H_*N_*D_];
__device__ __nv_bfloat16 g_kh[B_*H_*N_*D_];
__device__ __nv_bfloat16 g_kl[B_*H_*N_*D_];
__device__ __nv_bfloat16 g_vth[B_*H_*D_*N_];
__device__ __nv_bfloat16 g_vtl[B_*H_*D_*N_];
__device__ __nv_bfloat16 g_rh[H_*RP_*D_];         // rel_k hi [h][p(3072)][d]
__device__ __nv_bfloat16 g_rl[H_*RP_*D_];

// ---------------- helpers ----------------
__device__ __forceinline__ uint32_t smem_to_u32(const void* p) {
    uint32_t a;
    asm("{ .reg .u64 t; cvta.to.shared.u64 t, %1; cvt.u32.u64 %0, t; }" : "=r"(a) : "l"(p));
    return a;
}
__device__ __forceinline__ void cp_async16(uint32_t saddr, const void* g) {
    asm volatile("cp.async.cg.shared.global [%0], [%1], 16;" :: "r"(saddr), "l"(g));
}
#define CP_COMMIT() asm volatile("cp.async.commit_group;" ::: "memory")
#define CP_WAIT0()  asm volatile("cp.async.wait_group 0;" ::: "memory")

__device__ __forceinline__ void mma_bf16(float* c, const uint32_t* a, const uint32_t* b) {
    asm volatile("mma.sync.aligned.m16n8k16.row.col.f32.bf16.bf16.f32 "
        "{%0,%1,%2,%3}, {%4,%5,%6,%7}, {%8,%9}, {%0,%1,%2,%3};"
        : "+f"(c[0]), "+f"(c[1]), "+f"(c[2]), "+f"(c[3])
        : "r"(a[0]), "r"(a[1]), "r"(a[2]), "r"(a[3]), "r"(b[0]), "r"(b[1]));
}
__device__ __forceinline__ void ldsm_x4(uint32_t* r, uint32_t addr) {
    asm volatile("ldmatrix.sync.aligned.m8n8.x4.shared.b16 {%0,%1,%2,%3}, [%4];"
        : "=r"(r[0]), "=r"(r[1]), "=r"(r[2]), "=r"(r[3]) : "r"(addr));
}
__device__ __forceinline__ void split2(float f0, float f1, uint32_t& hi, uint32_t& lo) {
    __nv_bfloat16 h0 = __float2bfloat16(f0), h1 = __float2bfloat16(f1);
    __nv_bfloat162 hh(h0, h1);
    hi = *(uint32_t*)&hh;
    __nv_bfloat16 l0 = __float2bfloat16(f0 - __bfloat162float(h0));
    __nv_bfloat16 l1 = __float2bfloat16(f1 - __bfloat162float(h1));
    __nv_bfloat162 ll(l0, l1);
    lo = *(uint32_t*)&ll;
}
__device__ __forceinline__ bool rd_mask(const unsigned char* p, long idx, int mt) {
    if (mt == 0) return p[idx] != 0;
    if (mt == 1) return ((const int*)p)[idx] != 0;
    return ((const float*)p)[idx] != 0.0f;
}

// ---------------- conversions ----------------
__global__ void convA_kernel(const float* __restrict__ s, __nv_bfloat16* __restrict__ h,
                             __nv_bfloat16* __restrict__ l, int n4)
{
    int i = blockIdx.x*blockDim.x + threadIdx.x;
    if (i >= n4) return;
    float4 v = ((const float4*)s)[i];
    float a[4] = {v.x, v.y, v.z, v.w};
    __nv_bfloat16 hh[4], ll[4];
    #pragma unroll
    for (int j = 0; j < 4; j++) {
        hh[j] = __float2bfloat16(a[j]);
        ll[j] = __float2bfloat16(a[j] - __bfloat162float(hh[j]));
    }
    ((__nv_bfloat162*)h)[i*2+0] = __nv_bfloat162(hh[0], hh[1]);
    ((__nv_bfloat162*)h)[i*2+1] = __nv_bfloat162(hh[2], hh[3]);
    ((__nv_bfloat162*)l)[i*2+0] = __nv_bfloat162(ll[0], ll[1]);
    ((__nv_bfloat162*)l)[i*2+1] = __nv_bfloat162(ll[2], ll[3]);
}

// merged transpose+convert for Wq/Wk/Wv/Wo/Wrel. grid (768, 5).
__global__ void convT_all(const float* __restrict__ Wq, const float* __restrict__ Wk,
                          const float* __restrict__ Wv, const float* __restrict__ Wo,
                          const float* __restrict__ Wrel)
{
    __shared__ float t[32][33];
    const int job = blockIdx.y;
    const int idx = blockIdx.x;
    const float* src; __nv_bfloat16 *dh, *dl;
    int R, C, c0, r0;
    if (job < 3) {
        src = (job == 0) ? Wq : (job == 1) ? Wk : Wv;
        dh = g_wh + (long)job*512*1536; dl = g_wl + (long)job*512*1536;
        R = 1536; C = 512;
        c0 = (idx & 15)*32; r0 = (idx >> 4)*32;
    } else if (job == 3) {
        src = Wo; dh = g_woh; dl = g_wol;
        R = 512; C = 1536;
        c0 = (idx % 48)*32; r0 = (idx / 48)*32;
    } else {
        if (idx >= 96) return;
        src = Wrel; dh = g_wrh; dl = g_wrl;
        R = 192; C = 512;
        c0 = (idx & 15)*32; r0 = (idx >> 4)*32;
    }
    int tx = threadIdx.x & 31, ty = threadIdx.x >> 5;
    #pragma unroll
    for (int i = 0; i < 4; i++)
        t[ty + i*8][tx] = src[(long)(r0 + ty + i*8)*C + c0 + tx];
    __syncthreads();
    #pragma unroll
    for (int i = 0; i < 4; i++) {
        int c = c0 + ty + i*8, r = r0 + tx;
        float v = t[tx][ty + i*8];
        __nv_bfloat16 hv = __float2bfloat16(v);
        dh[(long)c*R + r] = hv;
        dl[(long)c*R + r] = __float2bfloat16(v - __bfloat162float(hv));
    }
}

// ---------------- mask pack + tile-activity (mtype computed inline) ----------------
__global__ void tact_kernel(const unsigned char* __restrict__ lm,
                            const unsigned char* __restrict__ isg)
{
    int t  = blockIdx.x;
    int jt = t % QT_;
    int qt = (t / QT_) % QT_;
    int b  = t / (QT_*QT_);
    int i0 = qt*64, j0 = jt*64;
    unsigned int w0 = *(const unsigned int*)lm;
    int mt;
    if ((w0 & 0xFFu) == 1u && ((w0 >> 8) & 0xFFu) == 1u) mt = 0;
    else if (w0 == 1u) mt = 1;
    else mt = 2;
    int r = threadIdx.x;
    bool rg = rd_mask(isg, (long)b*N_ + i0 + r, mt);
    unsigned long long bits = 0ull;
    for (int c = 0; c < 64; c++) {
        bool a = rg || rd_mask(isg, (long)b*N_ + j0 + c, mt)
                    || rd_mask(lm, (long)(i0+r)*N_ + j0 + c, mt);
        bits |= (unsigned long long)(a ? 1 : 0) << c;
    }
    g_mbits[(long)t*64 + r] = bits;
    int any = __syncthreads_or(bits != 0ull);
    if (r == 0) g_tact[t] = (unsigned char)(any ? 1 : 0);
}

// ---------------- warp-MMA bf16 split-precision GEMM (ldmatrix) ----------------
// mode 0 (grid 1D 384): blocks 0-287 = QKV (K=1536), 288-383 = rel (K=192, globals)
// mode 1 (grid 2D):     out = A@Wo^T + bias -> fp32 Cout, K=512
#define TPAD   40
#define TBYTES (128*TPAD*2)
#define STAGE  (4*TBYTES)
#define WG_SMEM (2*STAGE)

__global__ __launch_bounds__(256)
void wmma_gemm(const __nv_bfloat16* __restrict__ Ah, const __nv_bfloat16* __restrict__ Al,
               const __nv_bfloat16* __restrict__ Bh, const __nv_bfloat16* __restrict__ Bl,
               const float* __restrict__ bias, const float* __restrict__ bias2,
               float* __restrict__ Cout, int K, int mode)
{
    extern __shared__ char smem[];
    const uint32_t sb = smem_to_u32(smem);
    const int tid = threadIdx.x;
    const int lane = tid & 31;
    const int wid = tid >> 5;
    const int warp_m = wid >> 2;
    const int warp_n = wid & 3;
    const int grp = lane >> 2;
    const int tig = lane & 3;

    int m0, n0, Keff = K, mode_eff = mode;
    const char* srcs[4];
    if (mode == 0) {
        int id = blockIdx.x;
        if (id < 288) {
            m0 = (id % 24) * 128; n0 = (id / 24) * 128;
            srcs[0] = (const char*)Ah; srcs[1] = (const char*)Al;
            srcs[2] = (const char*)Bh; srcs[3] = (const char*)Bl;
        } else {
            id -= 288;
            m0 = (id % 24) * 128; n0 = (id / 24) * 128;
            srcs[0] = (const char*)g_ph;  srcs[1] = (const char*)g_pl;
            srcs[2] = (const char*)g_wrh; srcs[3] = (const char*)g_wrl;
            Keff = 192; mode_eff = 2;
        }
    } else {
        m0 = blockIdx.x * 128; n0 = blockIdx.y * 128;
        srcs[0] = (const char*)Ah; srcs[1] = (const char*)Al;
        srcs[2] = (const char*)Bh; srcs[3] = (const char*)Bl;
    }

    const int arow_l = lane & 15;
    const int acol_l = (lane >> 4) * 16;
    const int brow_l = ((lane >> 4) << 3) + (lane & 7);
    const int bcol_l = ((lane >> 3) & 1) * 16;

    const int rb[4] = {m0, m0, n0, n0};
    const long rowB = (long)Keff * 2;

    auto issue_stage = [&](int kt, int st) {
        const uint32_t sbase = sb + st*STAGE;
        #pragma unroll
        for (int l = 0; l < 8; l++) {
            int i = tid + l*256;
            int t = i >> 9, r = (i >> 2) & 127, c = i & 3;
            const char* g = srcs[t] + (long)(rb[t] + r)*rowB + kt*64 + c*16;
            cp_async16(sbase + t*TBYTES + r*80 + c*16, g);
        }
        CP_COMMIT();
    };

    float acc[4][4][4];
    #pragma unroll
    for (int i = 0; i < 4; i++)
        #pragma unroll
        for (int j = 0; j < 4; j++)
            #pragma unroll
            for (int e = 0; e < 4; e++) acc[i][j][e] = 0.f;

    const int nk = Keff / 32;
    issue_stage(0, 0);

    for (int kt = 0; kt < nk; kt++) {
        CP_WAIT0();
        __syncthreads();
        if (kt + 1 < nk) issue_stage(kt + 1, (kt + 1) & 1);

        const uint32_t stg = sb + (kt & 1)*STAGE;
        const uint32_t aoffh = stg + 0*TBYTES;
        const uint32_t aoffl = stg + 1*TBYTES;
        const uint32_t boffh = stg + 2*TBYTES;
        const uint32_t boffl = stg + 3*TBYTES;

        #pragma unroll
        for (int ks = 0; ks < 2; ks++) {
            const uint32_t kb = ks*32;
            uint32_t bh[4][2], bl[4][2];
            #pragma unroll
            for (int jp = 0; jp < 2; jp++) {
                uint32_t ro = (uint32_t)(warp_n*32 + jp*16 + brow_l)*80 + kb + bcol_l;
                uint32_t r4[4];
                ldsm_x4(r4, boffh + ro);
                bh[2*jp][0] = r4[0]; bh[2*jp][1] = r4[1];
                bh[2*jp+1][0] = r4[2]; bh[2*jp+1][1] = r4[3];
                ldsm_x4(r4, boffl + ro);
                bl[2*jp][0] = r4[0]; bl[2*jp][1] = r4[1];
                bl[2*jp+1][0] = r4[2]; bl[2*jp+1][1] = r4[3];
            }
            #pragma unroll
            for (int i = 0; i < 4; i++) {
                uint32_t ro = (uint32_t)(warp_m*64 + i*16 + arow_l)*80 + kb + acol_l;
                uint32_t ah[4], al[4];
                ldsm_x4(ah, aoffh + ro);
                ldsm_x4(al, aoffl + ro);
                #pragma unroll
                for (int j = 0; j < 4; j++) {
                    mma_bf16(acc[i][j], ah, bh[j]);
                    mma_bf16(acc[i][j], ah, bl[j]);
                    mma_bf16(acc[i][j], al, bh[j]);
                }
            }
        }
        __syncthreads();
    }

    // epilogue
    #pragma unroll
    for (int i = 0; i < 4; i++) {
        #pragma unroll
        for (int j = 0; j < 4; j++) {
            const int r0 = m0 + warp_m*64 + i*16 + grp;
            const int c0 = n0 + warp_n*32 + j*8 + 2*tig;
            #pragma unroll
            for (int half = 0; half < 2; half++) {
                const int row = r0 + half*8;
                float v0 = acc[i][j][half*2 + 0];
                float v1 = acc[i][j][half*2 + 1];
                if (mode_eff == 1) {
                    Cout[(long)row*1536 + c0]     = v0 + bias[c0];
                    Cout[(long)row*1536 + c0 + 1] = v1 + bias[c0 + 1];
                } else if (mode_eff == 2) {
                    const int h = c0 >> 6, d = c0 & 63;
                    uint32_t hi, lo; split2(v0, v1, hi, lo);
                    long idx = ((long)h*RP_ + row)*D_ + d;
                    *(uint32_t*)&g_rh[idx] = hi;
                    *(uint32_t*)&g_rl[idx] = lo;
                } else {
                    const int sel = c0 >> 9, pc = c0 & 511;
                    const int h = pc >> 6, d = pc & 63;
                    const int bb = (row >= N_) ? 1 : 0;
                    const int ii = row - bb*N_;
                    const int bhd = bb*H_ + h;
                    if (sel == 0) {
                        float s0 = v0*0.125f, s1 = v1*0.125f;
                        long idx = ((long)bhd*N_ + ii)*D_ + d;
                        uint32_t hi, lo;
                        split2(s0 + bias[pc], s1 + bias[pc + 1], hi, lo);
                        *(uint32_t*)&g_qh[idx] = hi;
                        *(uint32_t*)&g_ql[idx] = lo;
                        split2(s0 + bias2[pc], s1 + bias2[pc + 1], hi, lo);
                        *(uint32_t*)&g_qph[idx] = hi;
                        *(uint32_t*)&g_qpl[idx] = lo;
                    } else if (sel == 1) {
                        uint32_t hi, lo; split2(v0, v1, hi, lo);
                        long idx = ((long)bhd*N_ + ii)*D_ + d;
                        *(uint32_t*)&g_kh[idx] = hi;
                        *(uint32_t*)&g_kl[idx] = lo;
                    } else {
                        __nv_bfloat16 h0 = __float2bfloat16(v0);
                        __nv_bfloat16 h1 = __float2bfloat16(v1);
                        long i0x = ((long)bhd*D_ + d)*N_ + ii;
                        long i1x = ((long)bhd*D_ + d + 1)*N_ + ii;
                        g_vth[i0x] = h0;
                        g_vth[i1x] = h1;
                        g_vtl[i0x] = __float2bfloat16(v0 - __bfloat162float(h0));
                        g_vtl[i1x] = __float2bfloat16(v1 - __bfloat162float(h1));
                    }
                }
            }
        }
    }
}

// ---------------- mma.sync flash attention (ldmatrix) ----------------
#define AK_H   0u
#define AK_L   9216u
#define AVT_H  18432u
#define AVT_L  27648u
#define AR_H   36864u
#define AR_L   55296u
#define AG     73728u
#define ATTN2_SMEM (73728 + 64*132*4)

__global__ __launch_bounds__(128, 2)
void attn_mma()
{
    extern __shared__ char sm2[];
    const uint32_t sb = smem_to_u32(sm2);
    float* sG = (float*)(sm2 + AG);

    const int tid = threadIdx.x;
    const int lane = tid & 31;
    const int w = tid >> 5;
    const int grp = lane >> 2;
    const int tig = lane & 3;
    const int qt = blockIdx.x;
    const int bh = blockIdx.y;
    const int b = bh >> 3, h = bh & 7;
    const int i0 = qt * 64;

    const int brow_l = ((lane >> 4) << 3) + (lane & 7);
    const int bcol_l = ((lane >> 3) & 1) * 16;

    // ---- Q fragments (persistent): content (cb) + positional (pb) ----
    const __nv_bfloat16* qbh = g_qh  + (long)bh*N_*D_;
    const __nv_bfloat16* qbl = g_ql  + (long)bh*N_*D_;
    const __nv_bfloat16* pqh = g_qph + (long)bh*N_*D_;
    const __nv_bfloat16* pql = g_qpl + (long)bh*N_*D_;
    const int rq0 = i0 + w*16 + grp, rq1 = rq0 + 8;
    uint32_t qfh[4][4], qfl[4][4], qgh[4][4], qgl[4][4];
    #pragma unroll
    for (int kf = 0; kf < 4; kf++) {
        qfh[kf][0] = *(const uint32_t*)(qbh + (long)rq0*D_ + kf*16 + 2*tig);
        qfh[kf][1] = *(const uint32_t*)(qbh + (long)rq1*D_ + kf*16 + 2*tig);
        qfh[kf][2] = *(const uint32_t*)(qbh + (long)rq0*D_ + kf*16 + 8 + 2*tig);
        qfh[kf][3] = *(const uint32_t*)(qbh + (long)rq1*D_ + kf*16 + 8 + 2*tig);
        qfl[kf][0] = *(const uint32_t*)(qbl + (long)rq0*D_ + kf*16 + 2*tig);
        qfl[kf][1] = *(const uint32_t*)(qbl + (long)rq1*D_ + kf*16 + 2*tig);
        qfl[kf][2] = *(const uint32_t*)(qbl + (long)rq0*D_ + kf*16 + 8 + 2*tig);
        qfl[kf][3] = *(const uint32_t*)(qbl + (long)rq1*D_ + kf*16 + 8 + 2*tig);
        qgh[kf][0] = *(const uint32_t*)(pqh + (long)rq0*D_ + kf*16 + 2*tig);
        qgh[kf][1] = *(const uint32_t*)(pqh + (long)rq1*D_ + kf*16 + 2*tig);
        qgh[kf][2] = *(const uint32_t*)(pqh + (long)rq0*D_ + kf*16 + 8 + 2*tig);
        qgh[kf][3] = *(const uint32_t*)(pqh + (long)rq1*D_ + kf*16 + 8 + 2*tig);
        qgl[kf][0] = *(const uint32_t*)(pql + (long)rq0*D_ + kf*16 + 2*tig);
        qgl[kf][1] = *(const uint32_t*)(pql + (long)rq1*D_ + kf*16 + 2*tig);
        qgl[kf][2] = *(const uint32_t*)(pql + (long)rq0*D_ + kf*16 + 8 + 2*tig);
        qgl[kf][3] = *(const uint32_t*)(pql + (long)rq1*D_ + kf*16 + 8 + 2*tig);
    }

    float o[8][4];
    #pragma unroll
    for (int nf = 0; nf < 8; nf++)
        #pragma unroll
        for (int e = 0; e < 4; e++) o[nf][e] = 0.f;
    float mrow[2] = {-1e30f, -1e30f};
    float lrow[2] = {0.f, 0.f};

    const unsigned char* tact = &g_tact[(b*QT_ + qt)*QT_];
    const long kbase  = (long)bh*N_*D_;
    const long vbase  = (long)bh*D_*N_;
    const long rbase  = (long)h*RP_*D_;

    for (int jt = 0; jt < QT_; jt++) {
        if (!tact[jt]) continue;
        const int j0 = jt*64;
        const int p0 = j0 - i0 + (N_ - 1) - 63;

        __syncthreads();
        #pragma unroll
        for (int l = 0; l < 4; l++) {
            int i = tid + l*128;
            int r = i >> 3, c = i & 7;
            long krow = (kbase + (long)(j0 + r)*D_)*2;
            long vrow = (vbase + (long)r*N_ + j0)*2;
            cp_async16(sb + AK_H  + r*144 + c*16, (const char*)g_kh  + krow + c*16);
            cp_async16(sb + AK_L  + r*144 + c*16, (const char*)g_kl  + krow + c*16);
            cp_async16(sb + AVT_H + r*144 + c*16, (const char*)g_vth + vrow + c*16);
            cp_async16(sb + AVT_L + r*144 + c*16, (const char*)g_vtl + vrow + c*16);
        }
        #pragma unroll
        for (int l = 0; l < 8; l++) {
            int i = tid + l*128;
            int r = i >> 3, c = i & 7;
            long rrow = (rbase + (long)(p0 + r)*D_)*2;
            cp_async16(sb + AR_H + r*144 + c*16, (const char*)g_rh + rrow + c*16);
            cp_async16(sb + AR_L + r*144 + c*16, (const char*)g_rl + rrow + c*16);
        }
        CP_COMMIT();

        const unsigned long long* mb = g_mbits + ((long)(b*QT_ + qt)*QT_ + jt)*64;
        unsigned long long mw0 = mb[w*16 + grp];
        unsigned long long mw1 = mb[w*16 + grp + 8];

        CP_WAIT0();
        __syncthreads();

        // ---- content logits: Qc @ K^T ----
        float ca[8][4];
        #pragma unroll
        for (int nf = 0; nf < 8; nf++)
            #pragma unroll
            for (int e = 0; e < 4; e++) ca[nf][e] = 0.f;
        #pragma unroll
        for (int kf = 0; kf < 4; kf++) {
            #pragma unroll
            for (int np = 0; np < 4; np++) {
                uint32_t ro = (uint32_t)(np*16 + brow_l)*144 + kf*32 + bcol_l;
                uint32_t kh4[4], kl4[4];
                ldsm_x4(kh4, sb + AK_H + ro);
                ldsm_x4(kl4, sb + AK_L + ro);
                mma_bf16(ca[2*np],   qfh[kf], &kh4[0]);
                mma_bf16(ca[2*np],   qfh[kf], &kl4[0]);
                mma_bf16(ca[2*np],   qfl[kf], &kh4[0]);
                mma_bf16(ca[2*np+1], qfh[kf], &kh4[2]);
                mma_bf16(ca[2*np+1], qfh[kf], &kl4[2]);
                mma_bf16(ca[2*np+1], qfl[kf], &kh4[2]);
            }
        }

        // ---- G = Qp @ Rband^T ----
        const int grow = w*16 + grp;
        #pragma unroll
        for (int gh = 0; gh < 2; gh++) {
            float ga[8][4];
            #pragma unroll
            for (int nf = 0; nf < 8; nf++)
                #pragma unroll
                for (int e = 0; e < 4; e++) ga[nf][e] = 0.f;
            #pragma unroll
            for (int kf = 0; kf < 4; kf++) {
                #pragma unroll
                for (int np = 0; np < 4; np++) {
                    uint32_t ro = (uint32_t)(gh*64 + np*16 + brow_l)*144 + kf*32 + bcol_l;
                    uint32_t rh4[4], rl4[4];
                    ldsm_x4(rh4, sb + AR_H + ro);
                    ldsm_x4(rl4, sb + AR_L + ro);
                    mma_bf16(ga[2*np],   qgh[kf], &rh4[0]);
                    mma_bf16(ga[2*np],   qgh[kf], &rl4[0]);
                    mma_bf16(ga[2*np],   qgl[kf], &rh4[0]);
                    mma_bf16(ga[2*np+1], qgh[kf], &rh4[2]);
                    mma_bf16(ga[2*np+1], qgh[kf], &rl4[2]);
                    mma_bf16(ga[2*np+1], qgl[kf], &rh4[2]);
                }
            }
            #pragma unroll
            for (int nf = 0; nf < 8; nf++) {
                int col = gh*64 + 8*nf + 2*tig;
                sG[grow*132 + col]           = ga[nf][0];
                sG[grow*132 + col + 1]       = ga[nf][1];
                sG[(grow + 8)*132 + col]     = ga[nf][2];
                sG[(grow + 8)*132 + col + 1] = ga[nf][3];
            }
        }
        __syncwarp();

        // ---- gather + mask + online softmax ----
        float pv0[16], pv1[16];
        #pragma unroll
        for (int h2 = 0; h2 < 2; h2++) {
            const int rl = grow + 8*h2;
            const unsigned long long mw = h2 ? mw1 : mw0;
            float* pvv = h2 ? pv1 : pv0;
            float lg[16];
            float tmax = -1e30f;
            #pragma unroll
            for (int nf = 0; nf < 8; nf++) {
                #pragma unroll
                for (int e = 0; e < 2; e++) {
                    int c = 8*nf + 2*tig + e;
                    int pp = c - rl + 63;
                    float val = ca[nf][2*h2 + e] + sG[rl*132 + pp];
                    bool act = (mw >> c) & 1ull;
                    float lv = act ? val : -1e30f;
                    lg[nf*2 + e] = lv;
                    tmax = fmaxf(tmax, lv);
                }
            }
            tmax = fmaxf(tmax, __shfl_xor_sync(0xffffffffu, tmax, 1));
            tmax = fmaxf(tmax, __shfl_xor_sync(0xffffffffu, tmax, 2));
            float nm = fmaxf(mrow[h2], tmax);
            float corr = __expf(mrow[h2] - nm);
            mrow[h2] = nm;
            float ps = 0.f;
            #pragma unroll
            for (int e2 = 0; e2 < 16; e2++) {
                float p = (lg[e2] <= -1e29f) ? 0.f : __expf(lg[e2] - nm);
                pvv[e2] = p;
                ps += p;
            }
            ps += __shfl_xor_sync(0xffffffffu, ps, 1);
            ps += __shfl_xor_sync(0xffffffffu, ps, 2);
            lrow[h2] = lrow[h2]*corr + ps;
            #pragma unroll
            for (int nf = 0; nf < 8; nf++) {
                o[nf][2*h2]     *= corr;
                o[nf][2*h2 + 1] *= corr;
            }
        }

        // ---- P fragments ----
        uint32_t pfh[4][4], pfl[4][4];
        #pragma unroll
        for (int kf = 0; kf < 4; kf++) {
            split2(pv0[(2*kf)*2],   pv0[(2*kf)*2+1],   pfh[kf][0], pfl[kf][0]);
            split2(pv1[(2*kf)*2],   pv1[(2*kf)*2+1],   pfh[kf][1], pfl[kf][1]);
            split2(pv0[(2*kf+1)*2], pv0[(2*kf+1)*2+1], pfh[kf][2], pfl[kf][2]);
            split2(pv1[(2*kf+1)*2], pv1[(2*kf+1)*2+1], pfh[kf][3], pfl[kf][3]);
        }

        // ---- PV ----
        #pragma unroll
        for (int kf = 0; kf < 4; kf++) {
            #pragma unroll
            for (int np = 0; np < 4; np++) {
                uint32_t ro = (uint32_t)(np*16 + brow_l)*144 + kf*32 + bcol_l;
                uint32_t vh4[4], vl4[4];
                ldsm_x4(vh4, sb + AVT_H + ro);
                ldsm_x4(vl4, sb + AVT_L + ro);
                mma_bf16(o[2*np],   pfh[kf], &vh4[0]);
                mma_bf16(o[2*np],   pfh[kf], &vl4[0]);
                mma_bf16(o[2*np],   pfl[kf], &vh4[0]);
                mma_bf16(o[2*np+1], pfh[kf], &vh4[2]);
                mma_bf16(o[2*np+1], pfh[kf], &vl4[2]);
                mma_bf16(o[2*np+1], pfl[kf], &vh4[2]);
            }
        }
    }

    // ---- epilogue ----
    #pragma unroll
    for (int h2 = 0; h2 < 2; h2++) {
        float inv = 1.0f / lrow[h2];
        int rl = w*16 + grp + 8*h2;
        long rowbase = ((long)(b*N_ + i0 + rl))*(H_*D_) + h*D_;
        #pragma unroll
        for (int nf = 0; nf < 8; nf++) {
            float f0 = o[nf][2*h2]     * inv;
            float f1 = o[nf][2*h2 + 1] * inv;
            uint32_t hi, lo; split2(f0, f1, hi, lo);
            long idx = rowbase + 8*nf + 2*tig;
            *(uint32_t*)&g_ah[idx] = hi;
            *(uint32_t*)&g_al[idx] = lo;
        }
    }
}

// ---------------- launcher ----------------
extern "C" void kernel_launch(void* const* d_in, const int* in_sizes, int n_in,
                              void* d_out, int out_size)
{
    const float* x    = (const float*)d_in[0];
    const float* Wq   = (const float*)d_in[1];
    const float* Wk   = (const float*)d_in[2];
    const float* Wv   = (const float*)d_in[3];
    const float* Wrel = (const float*)d_in[4];
    const float* cb   = (const float*)d_in[5];
    const float* pb   = (const float*)d_in[6];
    const float* Wo   = (const float*)d_in[7];
    const float* bo   = (const float*)d_in[8];
    const float* pos  = (const float*)d_in[9];
    const unsigned char* lmu = (const unsigned char*)d_in[10];
    const unsigned char* isg = (const unsigned char*)d_in[11];
    float* out = (float*)d_out;

    cudaFuncSetAttribute(wmma_gemm, cudaFuncAttributeMaxDynamicSharedMemorySize, WG_SMEM);
    cudaFuncSetAttribute(attn_mma, cudaFuncAttributeMaxDynamicSharedMemorySize, ATTN2_SMEM);

    __nv_bfloat16 *xh_p, *xl_p, *ph_p, *pl_p, *wh_p, *wl_p, *woh_p, *wol_p, *ah_p, *al_p;
    cudaGetSymbolAddress((void**)&xh_p,  g_xh);
    cudaGetSymbolAddress((void**)&xl_p,  g_xl);
    cudaGetSymbolAddress((void**)&ph_p,  g_ph);
    cudaGetSymbolAddress((void**)&pl_p,  g_pl);
    cudaGetSymbolAddress((void**)&wh_p,  g_wh);
    cudaGetSymbolAddress((void**)&wl_p,  g_wl);
    cudaGetSymbolAddress((void**)&woh_p, g_woh);
    cudaGetSymbolAddress((void**)&wol_p, g_wol);
    cudaGetSymbolAddress((void**)&ah_p,  g_ah);
    cudaGetSymbolAddress((void**)&al_p,  g_al);

    convA_kernel<<<(B_*N_*DIM_/4 + 255)/256, 256>>>(x, xh_p, xl_p,
                                                    B_*N_*DIM_/4);          // 1
    convA_kernel<<<(P_*192/4 + 255)/256, 256>>>(pos, ph_p, pl_p, P_*192/4); // 2
    convT_all<<<dim3(768, 5), 256>>>(Wq, Wk, Wv, Wo, Wrel);                 // 3
    tact_kernel<<<B_*QT_*QT_, 64>>>(lmu, isg);                              // 4
    // fused QKV + rel projection on one grid (288 QKV blocks + 96 rel blocks)
    wmma_gemm<<<384, 256, WG_SMEM>>>(xh_p, xl_p, wh_p, wl_p,
                                     cb, pb, nullptr, DIM_, 0);             // 5
    attn_mma<<<dim3(QT_, B_*H_), 128, ATTN2_SMEM>>>();                      // 6
    wmma_gemm<<<dim3(24, 12), 256, WG_SMEM>>>(ah_p, al_p, woh_p, wol_p,
                                              bo, nullptr, out, 512, 1);    // 7
}

// round 9
// speedup vs baseline: 4.0852x; 1.0079x over previous
#include <cuda_runtime.h>
#include <cuda_bf16.h>
#include <math.h>
#include <stdint.h>

#define B_   2
#define N_   1536
#define DIM_ 1536
#define H_   8
#define D_   64
#define P_   3071      // 2N-1
#define RP_  3072      // padded row stride for rel tables
#define QT_  24        // N/64 tiles

// ---------------- device scratch (zero-initialized statics) ----------------
__device__ unsigned char g_tact[B_*QT_*QT_];
__device__ unsigned long long g_mbits[B_*QT_*QT_*64];

__device__ __nv_bfloat16 g_xh[B_*N_*DIM_];
__device__ __nv_bfloat16 g_xl[B_*N_*DIM_];
__device__ __nv_bfloat16 g_ph[RP_*192];           // pos_embed hi (row 3071 zero)
__device__ __nv_bfloat16 g_pl[RP_*192];
__device__ __nv_bfloat16 g_wh[1536*DIM_];
__device__ __nv_bfloat16 g_wl[1536*DIM_];
__device__ __nv_bfloat16 g_wrh[512*192];          // Wrel^T hi [512][192]
__device__ __nv_bfloat16 g_wrl[512*192];
__device__ __nv_bfloat16 g_woh[1536*512];
__device__ __nv_bfloat16 g_wol[1536*512];
__device__ __nv_bfloat16 g_ah[B_*N_*H_*D_];
__device__ __nv_bfloat16 g_al[B_*N_*H_*D_];
__device__ __nv_bfloat16 g_qh[B_*H_*N_*D_];       // q*scale + cb
__device__ __nv_bfloat16 g_ql[B_*H_*N_*D_];
__device__ __nv_bfloat16 g_qph[B_*H_*N_*D_];      // q*scale + pb
__device__ __nv_bfloat16 g_qpl[B_*H_*N_*D_];
__device__ __nv_bfloat16 g_kh[B_*H_*N_*D_];
__device__ __nv_bfloat16 g_kl[B_*H_*N_*D_];
__device__ __nv_bfloat16 g_vth[B_*H_*D_*N_];
__device__ __nv_bfloat16 g_vtl[B_*H_*D_*N_];
__device__ __nv_bfloat16 g_rh[H_*RP_*D_];         // rel_k hi [h][p(3072)][d]
__device__ __nv_bfloat16 g_rl[H_*RP_*D_];

// ---------------- helpers ----------------
__device__ __forceinline__ uint32_t smem_to_u32(const void* p) {
    uint32_t a;
    asm("{ .reg .u64 t; cvta.to.shared.u64 t, %1; cvt.u32.u64 %0, t; }" : "=r"(a) : "l"(p));
    return a;
}
__device__ __forceinline__ void cp_async16(uint32_t saddr, const void* g) {
    asm volatile("cp.async.cg.shared.global [%0], [%1], 16;" :: "r"(saddr), "l"(g));
}
#define CP_COMMIT() asm volatile("cp.async.commit_group;" ::: "memory")
#define CP_WAIT0()  asm volatile("cp.async.wait_group 0;" ::: "memory")

__device__ __forceinline__ void mma_bf16(float* c, const uint32_t* a, const uint32_t* b) {
    asm volatile("mma.sync.aligned.m16n8k16.row.col.f32.bf16.bf16.f32 "
        "{%0,%1,%2,%3}, {%4,%5,%6,%7}, {%8,%9}, {%0,%1,%2,%3};"
        : "+f"(c[0]), "+f"(c[1]), "+f"(c[2]), "+f"(c[3])
        : "r"(a[0]), "r"(a[1]), "r"(a[2]), "r"(a[3]), "r"(b[0]), "r"(b[1]));
}
__device__ __forceinline__ void ldsm_x4(uint32_t* r, uint32_t addr) {
    asm volatile("ldmatrix.sync.aligned.m8n8.x4.shared.b16 {%0,%1,%2,%3}, [%4];"
        : "=r"(r[0]), "=r"(r[1]), "=r"(r[2]), "=r"(r[3]) : "r"(addr));
}
__device__ __forceinline__ void split2(float f0, float f1, uint32_t& hi, uint32_t& lo) {
    __nv_bfloat16 h0 = __float2bfloat16(f0), h1 = __float2bfloat16(f1);
    __nv_bfloat162 hh(h0, h1);
    hi = *(uint32_t*)&hh;
    __nv_bfloat16 l0 = __float2bfloat16(f0 - __bfloat162float(h0));
    __nv_bfloat16 l1 = __float2bfloat16(f1 - __bfloat162float(h1));
    __nv_bfloat162 ll(l0, l1);
    lo = *(uint32_t*)&ll;
}
__device__ __forceinline__ bool rd_mask(const unsigned char* p, long idx, int mt) {
    if (mt == 0) return p[idx] != 0;
    if (mt == 1) return ((const int*)p)[idx] != 0;
    return ((const float*)p)[idx] != 0.0f;
}

// ---------------- conversions ----------------
// merged split-conversion for x and pos_embed. grid (blocks, 2).
__global__ void convA2_kernel(const float* __restrict__ x,
                              __nv_bfloat16* __restrict__ xh, __nv_bfloat16* __restrict__ xl,
                              int n4x,
                              const float* __restrict__ pos,
                              __nv_bfloat16* __restrict__ ph, __nv_bfloat16* __restrict__ pl,
                              int n4p)
{
    const float* s; __nv_bfloat16 *h, *l; int n4;
    if (blockIdx.y == 0) { s = x; h = xh; l = xl; n4 = n4x; }
    else                 { s = pos; h = ph; l = pl; n4 = n4p; }
    int i = blockIdx.x*blockDim.x + threadIdx.x;
    if (i >= n4) return;
    float4 v = ((const float4*)s)[i];
    float a[4] = {v.x, v.y, v.z, v.w};
    __nv_bfloat16 hh[4], ll[4];
    #pragma unroll
    for (int j = 0; j < 4; j++) {
        hh[j] = __float2bfloat16(a[j]);
        ll[j] = __float2bfloat16(a[j] - __bfloat162float(hh[j]));
    }
    ((__nv_bfloat162*)h)[i*2+0] = __nv_bfloat162(hh[0], hh[1]);
    ((__nv_bfloat162*)h)[i*2+1] = __nv_bfloat162(hh[2], hh[3]);
    ((__nv_bfloat162*)l)[i*2+0] = __nv_bfloat162(ll[0], ll[1]);
    ((__nv_bfloat162*)l)[i*2+1] = __nv_bfloat162(ll[2], ll[3]);
}

// merged transpose+convert for Wq/Wk/Wv/Wo/Wrel. grid (768, 5).
__global__ void convT_all(const float* __restrict__ Wq, const float* __restrict__ Wk,
                          const float* __restrict__ Wv, const float* __restrict__ Wo,
                          const float* __restrict__ Wrel)
{
    __shared__ float t[32][33];
    const int job = blockIdx.y;
    const int idx = blockIdx.x;
    const float* src; __nv_bfloat16 *dh, *dl;
    int R, C, c0, r0;
    if (job < 3) {
        src = (job == 0) ? Wq : (job == 1) ? Wk : Wv;
        dh = g_wh + (long)job*512*1536; dl = g_wl + (long)job*512*1536;
        R = 1536; C = 512;
        c0 = (idx & 15)*32; r0 = (idx >> 4)*32;
    } else if (job == 3) {
        src = Wo; dh = g_woh; dl = g_wol;
        R = 512; C = 1536;
        c0 = (idx % 48)*32; r0 = (idx / 48)*32;
    } else {
        if (idx >= 96) return;
        src = Wrel; dh = g_wrh; dl = g_wrl;
        R = 192; C = 512;
        c0 = (idx & 15)*32; r0 = (idx >> 4)*32;
    }
    int tx = threadIdx.x & 31, ty = threadIdx.x >> 5;
    #pragma unroll
    for (int i = 0; i < 4; i++)
        t[ty + i*8][tx] = src[(long)(r0 + ty + i*8)*C + c0 + tx];
    __syncthreads();
    #pragma unroll
    for (int i = 0; i < 4; i++) {
        int c = c0 + ty + i*8, r = r0 + tx;
        float v = t[tx][ty + i*8];
        __nv_bfloat16 hv = __float2bfloat16(v);
        dh[(long)c*R + r] = hv;
        dl[(long)c*R + r] = __float2bfloat16(v - __bfloat162float(hv));
    }
}

// ---------------- mask pack + tile-activity (vectorized) ----------------
__global__ void tact_kernel(const unsigned char* __restrict__ lm,
                            const unsigned char* __restrict__ isg)
{
    int t  = blockIdx.x;
    int jt = t % QT_;
    int qt = (t / QT_) % QT_;
    int b  = t / (QT_*QT_);
    int i0 = qt*64, j0 = jt*64;
    unsigned int w0 = *(const unsigned int*)lm;
    int mt;
    if ((w0 & 0xFFu) == 1u && ((w0 >> 8) & 0xFFu) == 1u) mt = 0;
    else if (w0 == 1u) mt = 1;
    else mt = 2;

    const int r = threadIdx.x;          // 64 threads
    const int wp = r >> 5, lane = r & 31;
    __shared__ unsigned int cg[2];

    // column-global bits via ballot (thread c reads isg[j0+c])
    bool cpred = rd_mask(isg, (long)b*N_ + j0 + r, mt);
    unsigned int cw = __ballot_sync(0xffffffffu, cpred);
    if (lane == 0) cg[wp] = cw;

    bool rg = rd_mask(isg, (long)b*N_ + i0 + r, mt);

    unsigned long long rowbits = 0ull;
    if (mt == 0) {
        const uint4* rp = (const uint4*)(lm + (long)(i0 + r)*N_ + j0);
        #pragma unroll
        for (int q = 0; q < 4; q++) {
            uint4 v = rp[q];
            unsigned int ws[4] = {v.x, v.y, v.z, v.w};
            #pragma unroll
            for (int k = 0; k < 4; k++) {
                unsigned int nz  = __vcmpne4(ws[k], 0u) & 0x01010101u;
                unsigned int nib = (nz * 0x01020408u) >> 24;   // bits b0..b3 in order
                rowbits |= (unsigned long long)(nib & 0xFu) << (q*16 + k*4);
            }
        }
    } else {
        for (int c = 0; c < 64; c++)
            rowbits |= (unsigned long long)(rd_mask(lm, (long)(i0+r)*N_ + j0 + c, mt) ? 1 : 0) << c;
    }
    __syncthreads();
    unsigned long long colbits = (unsigned long long)cg[0]
                               | ((unsigned long long)cg[1] << 32);
    unsigned long long bits = rg ? ~0ull : (rowbits | colbits);
    g_mbits[(long)t*64 + r] = bits;
    int any = __syncthreads_or(bits != 0ull);
    if (r == 0) g_tact[t] = (unsigned char)(any ? 1 : 0);
}

// ---------------- warp-MMA bf16 split-precision GEMM (ldmatrix) ----------------
// mode 0 (grid 1D 384): blocks 0-287 = QKV (K=1536), 288-383 = rel (K=192, globals)
// mode 1 (grid 2D):     out = A@Wo^T + bias -> fp32 Cout, K=512
#define TPAD   40
#define TBYTES (128*TPAD*2)
#define STAGE  (4*TBYTES)
#define WG_SMEM (2*STAGE)

__global__ __launch_bounds__(256)
void wmma_gemm(const __nv_bfloat16* __restrict__ Ah, const __nv_bfloat16* __restrict__ Al,
               const __nv_bfloat16* __restrict__ Bh, const __nv_bfloat16* __restrict__ Bl,
               const float* __restrict__ bias, const float* __restrict__ bias2,
               float* __restrict__ Cout, int K, int mode)
{
    extern __shared__ char smem[];
    const uint32_t sb = smem_to_u32(smem);
    const int tid = threadIdx.x;
    const int lane = tid & 31;
    const int wid = tid >> 5;
    const int warp_m = wid >> 2;
    const int warp_n = wid & 3;
    const int grp = lane >> 2;
    const int tig = lane & 3;

    int m0, n0, Keff = K, mode_eff = mode;
    const char* srcs[4];
    if (mode == 0) {
        int id = blockIdx.x;
        if (id < 288) {
            m0 = (id % 24) * 128; n0 = (id / 24) * 128;
            srcs[0] = (const char*)Ah; srcs[1] = (const char*)Al;
            srcs[2] = (const char*)Bh; srcs[3] = (const char*)Bl;
        } else {
            id -= 288;
            m0 = (id % 24) * 128; n0 = (id / 24) * 128;
            srcs[0] = (const char*)g_ph;  srcs[1] = (const char*)g_pl;
            srcs[2] = (const char*)g_wrh; srcs[3] = (const char*)g_wrl;
            Keff = 192; mode_eff = 2;
        }
    } else {
        m0 = blockIdx.x * 128; n0 = blockIdx.y * 128;
        srcs[0] = (const char*)Ah; srcs[1] = (const char*)Al;
        srcs[2] = (const char*)Bh; srcs[3] = (const char*)Bl;
    }

    const int arow_l = lane & 15;
    const int acol_l = (lane >> 4) * 16;
    const int brow_l = ((lane >> 4) << 3) + (lane & 7);
    const int bcol_l = ((lane >> 3) & 1) * 16;

    const int rb[4] = {m0, m0, n0, n0};
    const long rowB = (long)Keff * 2;

    auto issue_stage = [&](int kt, int st) {
        const uint32_t sbase = sb + st*STAGE;
        #pragma unroll
        for (int l = 0; l < 8; l++) {
            int i = tid + l*256;
            int t = i >> 9, r = (i >> 2) & 127, c = i & 3;
            const char* g = srcs[t] + (long)(rb[t] + r)*rowB + kt*64 + c*16;
            cp_async16(sbase + t*TBYTES + r*80 + c*16, g);
        }
        CP_COMMIT();
    };

    float acc[4][4][4];
    #pragma unroll
    for (int i = 0; i < 4; i++)
        #pragma unroll
        for (int j = 0; j < 4; j++)
            #pragma unroll
            for (int e = 0; e < 4; e++) acc[i][j][e] = 0.f;

    const int nk = Keff / 32;
    issue_stage(0, 0);

    for (int kt = 0; kt < nk; kt++) {
        CP_WAIT0();
        __syncthreads();
        if (kt + 1 < nk) issue_stage(kt + 1, (kt + 1) & 1);

        const uint32_t stg = sb + (kt & 1)*STAGE;
        const uint32_t aoffh = stg + 0*TBYTES;
        const uint32_t aoffl = stg + 1*TBYTES;
        const uint32_t boffh = stg + 2*TBYTES;
        const uint32_t boffl = stg + 3*TBYTES;

        #pragma unroll
        for (int ks = 0; ks < 2; ks++) {
            const uint32_t kb = ks*32;
            uint32_t bh[4][2], bl[4][2];
            #pragma unroll
            for (int jp = 0; jp < 2; jp++) {
                uint32_t ro = (uint32_t)(warp_n*32 + jp*16 + brow_l)*80 + kb + bcol_l;
                uint32_t r4[4];
                ldsm_x4(r4, boffh + ro);
                bh[2*jp][0] = r4[0]; bh[2*jp][1] = r4[1];
                bh[2*jp+1][0] = r4[2]; bh[2*jp+1][1] = r4[3];
                ldsm_x4(r4, boffl + ro);
                bl[2*jp][0] = r4[0]; bl[2*jp][1] = r4[1];
                bl[2*jp+1][0] = r4[2]; bl[2*jp+1][1] = r4[3];
            }
            #pragma unroll
            for (int i = 0; i < 4; i++) {
                uint32_t ro = (uint32_t)(warp_m*64 + i*16 + arow_l)*80 + kb + acol_l;
                uint32_t ah[4], al[4];
                ldsm_x4(ah, aoffh + ro);
                ldsm_x4(al, aoffl + ro);
                #pragma unroll
                for (int j = 0; j < 4; j++) {
                    mma_bf16(acc[i][j], ah, bh[j]);
                    mma_bf16(acc[i][j], ah, bl[j]);
                    mma_bf16(acc[i][j], al, bh[j]);
                }
            }
        }
        __syncthreads();
    }

    // epilogue
    #pragma unroll
    for (int i = 0; i < 4; i++) {
        #pragma unroll
        for (int j = 0; j < 4; j++) {
            const int r0 = m0 + warp_m*64 + i*16 + grp;
            const int c0 = n0 + warp_n*32 + j*8 + 2*tig;
            #pragma unroll
            for (int half = 0; half < 2; half++) {
                const int row = r0 + half*8;
                float v0 = acc[i][j][half*2 + 0];
                float v1 = acc[i][j][half*2 + 1];
                if (mode_eff == 1) {
                    Cout[(long)row*1536 + c0]     = v0 + bias[c0];
                    Cout[(long)row*1536 + c0 + 1] = v1 + bias[c0 + 1];
                } else if (mode_eff == 2) {
                    const int h = c0 >> 6, d = c0 & 63;
                    uint32_t hi, lo; split2(v0, v1, hi, lo);
                    long idx = ((long)h*RP_ + row)*D_ + d;
                    *(uint32_t*)&g_rh[idx] = hi;
                    *(uint32_t*)&g_rl[idx] = lo;
                } else {
                    const int sel = c0 >> 9, pc = c0 & 511;
                    const int h = pc >> 6, d = pc & 63;
                    const int bb = (row >= N_) ? 1 : 0;
                    const int ii = row - bb*N_;
                    const int bhd = bb*H_ + h;
                    if (sel == 0) {
                        float s0 = v0*0.125f, s1 = v1*0.125f;
                        long idx = ((long)bhd*N_ + ii)*D_ + d;
                        uint32_t hi, lo;
                        split2(s0 + bias[pc], s1 + bias[pc + 1], hi, lo);
                        *(uint32_t*)&g_qh[idx] = hi;
                        *(uint32_t*)&g_ql[idx] = lo;
                        split2(s0 + bias2[pc], s1 + bias2[pc + 1], hi, lo);
                        *(uint32_t*)&g_qph[idx] = hi;
                        *(uint32_t*)&g_qpl[idx] = lo;
                    } else if (sel == 1) {
                        uint32_t hi, lo; split2(v0, v1, hi, lo);
                        long idx = ((long)bhd*N_ + ii)*D_ + d;
                        *(uint32_t*)&g_kh[idx] = hi;
                        *(uint32_t*)&g_kl[idx] = lo;
                    } else {
                        __nv_bfloat16 h0 = __float2bfloat16(v0);
                        __nv_bfloat16 h1 = __float2bfloat16(v1);
                        long i0x = ((long)bhd*D_ + d)*N_ + ii;
                        long i1x = ((long)bhd*D_ + d + 1)*N_ + ii;
                        g_vth[i0x] = h0;
                        g_vth[i1x] = h1;
                        g_vtl[i0x] = __float2bfloat16(v0 - __bfloat162float(h0));
                        g_vtl[i1x] = __float2bfloat16(v1 - __bfloat162float(h1));
                    }
                }
            }
        }
    }
}

// ---------------- mma.sync flash attention (ldmatrix) ----------------
#define AK_H   0u
#define AK_L   9216u
#define AVT_H  18432u
#define AVT_L  27648u
#define AR_H   36864u
#define AR_L   55296u
#define AG     73728u
#define ATTN2_SMEM (73728 + 64*132*4)

__global__ __launch_bounds__(128, 2)
void attn_mma()
{
    extern __shared__ char sm2[];
    const uint32_t sb = smem_to_u32(sm2);
    float* sG = (float*)(sm2 + AG);

    const int tid = threadIdx.x;
    const int lane = tid & 31;
    const int w = tid >> 5;
    const int grp = lane >> 2;
    const int tig = lane & 3;
    const int qt = blockIdx.x;
    const int bh = blockIdx.y;
    const int b = bh >> 3, h = bh & 7;
    const int i0 = qt * 64;

    const int brow_l = ((lane >> 4) << 3) + (lane & 7);
    const int bcol_l = ((lane >> 3) & 1) * 16;

    // ---- Q fragments (persistent): content (cb) + positional (pb) ----
    const __nv_bfloat16* qbh = g_qh  + (long)bh*N_*D_;
    const __nv_bfloat16* qbl = g_ql  + (long)bh*N_*D_;
    const __nv_bfloat16* pqh = g_qph + (long)bh*N_*D_;
    const __nv_bfloat16* pql = g_qpl + (long)bh*N_*D_;
    const int rq0 = i0 + w*16 + grp, rq1 = rq0 + 8;
    uint32_t qfh[4][4], qfl[4][4], qgh[4][4], qgl[4][4];
    #pragma unroll
    for (int kf = 0; kf < 4; kf++) {
        qfh[kf][0] = *(const uint32_t*)(qbh + (long)rq0*D_ + kf*16 + 2*tig);
        qfh[kf][1] = *(const uint32_t*)(qbh + (long)rq1*D_ + kf*16 + 2*tig);
        qfh[kf][2] = *(const uint32_t*)(qbh + (long)rq0*D_ + kf*16 + 8 + 2*tig);
        qfh[kf][3] = *(const uint32_t*)(qbh + (long)rq1*D_ + kf*16 + 8 + 2*tig);
        qfl[kf][0] = *(const uint32_t*)(qbl + (long)rq0*D_ + kf*16 + 2*tig);
        qfl[kf][1] = *(const uint32_t*)(qbl + (long)rq1*D_ + kf*16 + 2*tig);
        qfl[kf][2] = *(const uint32_t*)(qbl + (long)rq0*D_ + kf*16 + 8 + 2*tig);
        qfl[kf][3] = *(const uint32_t*)(qbl + (long)rq1*D_ + kf*16 + 8 + 2*tig);
        qgh[kf][0] = *(const uint32_t*)(pqh + (long)rq0*D_ + kf*16 + 2*tig);
        qgh[kf][1] = *(const uint32_t*)(pqh + (long)rq1*D_ + kf*16 + 2*tig);
        qgh[kf][2] = *(const uint32_t*)(pqh + (long)rq0*D_ + kf*16 + 8 + 2*tig);
        qgh[kf][3] = *(const uint32_t*)(pqh + (long)rq1*D_ + kf*16 + 8 + 2*tig);
        qgl[kf][0] = *(const uint32_t*)(pql + (long)rq0*D_ + kf*16 + 2*tig);
        qgl[kf][1] = *(const uint32_t*)(pql + (long)rq1*D_ + kf*16 + 2*tig);
        qgl[kf][2] = *(const uint32_t*)(pql + (long)rq0*D_ + kf*16 + 8 + 2*tig);
        qgl[kf][3] = *(const uint32_t*)(pql + (long)rq1*D_ + kf*16 + 8 + 2*tig);
    }

    float o[8][4];
    #pragma unroll
    for (int nf = 0; nf < 8; nf++)
        #pragma unroll
        for (int e = 0; e < 4; e++) o[nf][e] = 0.f;
    float mrow[2] = {-1e30f, -1e30f};
    float lrow[2] = {0.f, 0.f};

    const unsigned char* tact = &g_tact[(b*QT_ + qt)*QT_];
    const long kbase  = (long)bh*N_*D_;
    const long vbase  = (long)bh*D_*N_;
    const long rbase  = (long)h*RP_*D_;

    for (int jt = 0; jt < QT_; jt++) {
        if (!tact[jt]) continue;
        const int j0 = jt*64;
        const int p0 = j0 - i0 + (N_ - 1) - 63;

        __syncthreads();
        #pragma unroll
        for (int l = 0; l < 4; l++) {
            int i = tid + l*128;
            int r = i >> 3, c = i & 7;
            long krow = (kbase + (long)(j0 + r)*D_)*2;
            long vrow = (vbase + (long)r*N_ + j0)*2;
            cp_async16(sb + AK_H  + r*144 + c*16, (const char*)g_kh  + krow + c*16);
            cp_async16(sb + AK_L  + r*144 + c*16, (const char*)g_kl  + krow + c*16);
            cp_async16(sb + AVT_H + r*144 + c*16, (const char*)g_vth + vrow + c*16);
            cp_async16(sb + AVT_L + r*144 + c*16, (const char*)g_vtl + vrow + c*16);
        }
        #pragma unroll
        for (int l = 0; l < 8; l++) {
            int i = tid + l*128;
            int r = i >> 3, c = i & 7;
            long rrow = (rbase + (long)(p0 + r)*D_)*2;
            cp_async16(sb + AR_H + r*144 + c*16, (const char*)g_rh + rrow + c*16);
            cp_async16(sb + AR_L + r*144 + c*16, (const char*)g_rl + rrow + c*16);
        }
        CP_COMMIT();

        const unsigned long long* mb = g_mbits + ((long)(b*QT_ + qt)*QT_ + jt)*64;
        unsigned long long mw0 = mb[w*16 + grp];
        unsigned long long mw1 = mb[w*16 + grp + 8];

        CP_WAIT0();
        __syncthreads();

        // ---- content logits: Qc @ K^T ----
        float ca[8][4];
        #pragma unroll
        for (int nf = 0; nf < 8; nf++)
            #pragma unroll
            for (int e = 0; e < 4; e++) ca[nf][e] = 0.f;
        #pragma unroll
        for (int kf = 0; kf < 4; kf++) {
            #pragma unroll
            for (int np = 0; np < 4; np++) {
                uint32_t ro = (uint32_t)(np*16 + brow_l)*144 + kf*32 + bcol_l;
                uint32_t kh4[4], kl4[4];
                ldsm_x4(kh4, sb + AK_H + ro);
                ldsm_x4(kl4, sb + AK_L + ro);
                mma_bf16(ca[2*np],   qfh[kf], &kh4[0]);
                mma_bf16(ca[2*np],   qfh[kf], &kl4[0]);
                mma_bf16(ca[2*np],   qfl[kf], &kh4[0]);
                mma_bf16(ca[2*np+1], qfh[kf], &kh4[2]);
                mma_bf16(ca[2*np+1], qfh[kf], &kl4[2]);
                mma_bf16(ca[2*np+1], qfl[kf], &kh4[2]);
            }
        }

        // ---- G = Qp @ Rband^T ----
        const int grow = w*16 + grp;
        #pragma unroll
        for (int gh = 0; gh < 2; gh++) {
            float ga[8][4];
            #pragma unroll
            for (int nf = 0; nf < 8; nf++)
                #pragma unroll
                for (int e = 0; e < 4; e++) ga[nf][e] = 0.f;
            #pragma unroll
            for (int kf = 0; kf < 4; kf++) {
                #pragma unroll
                for (int np = 0; np < 4; np++) {
                    uint32_t ro = (uint32_t)(gh*64 + np*16 + brow_l)*144 + kf*32 + bcol_l;
                    uint32_t rh4[4], rl4[4];
                    ldsm_x4(rh4, sb + AR_H + ro);
                    ldsm_x4(rl4, sb + AR_L + ro);
                    mma_bf16(ga[2*np],   qgh[kf], &rh4[0]);
                    mma_bf16(ga[2*np],   qgh[kf], &rl4[0]);
                    mma_bf16(ga[2*np],   qgl[kf], &rh4[0]);
                    mma_bf16(ga[2*np+1], qgh[kf], &rh4[2]);
                    mma_bf16(ga[2*np+1], qgh[kf], &rl4[2]);
                    mma_bf16(ga[2*np+1], qgl[kf], &rh4[2]);
                }
            }
            #pragma unroll
            for (int nf = 0; nf < 8; nf++) {
                int col = gh*64 + 8*nf + 2*tig;
                sG[grow*132 + col]           = ga[nf][0];
                sG[grow*132 + col + 1]       = ga[nf][1];
                sG[(grow + 8)*132 + col]     = ga[nf][2];
                sG[(grow + 8)*132 + col + 1] = ga[nf][3];
            }
        }
        __syncwarp();

        // ---- gather + mask + online softmax ----
        float pv0[16], pv1[16];
        #pragma unroll
        for (int h2 = 0; h2 < 2; h2++) {
            const int rl = grow + 8*h2;
            const unsigned long long mw = h2 ? mw1 : mw0;
            float* pvv = h2 ? pv1 : pv0;
            float lg[16];
            float tmax = -1e30f;
            #pragma unroll
            for (int nf = 0; nf < 8; nf++) {
                #pragma unroll
                for (int e = 0; e < 2; e++) {
                    int c = 8*nf + 2*tig + e;
                    int pp = c - rl + 63;
                    float val = ca[nf][2*h2 + e] + sG[rl*132 + pp];
                    bool act = (mw >> c) & 1ull;
                    float lv = act ? val : -1e30f;
                    lg[nf*2 + e] = lv;
                    tmax = fmaxf(tmax, lv);
                }
            }
            tmax = fmaxf(tmax, __shfl_xor_sync(0xffffffffu, tmax, 1));
            tmax = fmaxf(tmax, __shfl_xor_sync(0xffffffffu, tmax, 2));
            float nm = fmaxf(mrow[h2], tmax);
            float corr = __expf(mrow[h2] - nm);
            mrow[h2] = nm;
            float ps = 0.f;
            #pragma unroll
            for (int e2 = 0; e2 < 16; e2++) {
                float p = (lg[e2] <= -1e29f) ? 0.f : __expf(lg[e2] - nm);
                pvv[e2] = p;
                ps += p;
            }
            ps += __shfl_xor_sync(0xffffffffu, ps, 1);
            ps += __shfl_xor_sync(0xffffffffu, ps, 2);
            lrow[h2] = lrow[h2]*corr + ps;
            #pragma unroll
            for (int nf = 0; nf < 8; nf++) {
                o[nf][2*h2]     *= corr;
                o[nf][2*h2 + 1] *= corr;
            }
        }

        // ---- P fragments ----
        uint32_t pfh[4][4], pfl[4][4];
        #pragma unroll
        for (int kf = 0; kf < 4; kf++) {
            split2(pv0[(2*kf)*2],   pv0[(2*kf)*2+1],   pfh[kf][0], pfl[kf][0]);
            split2(pv1[(2*kf)*2],   pv1[(2*kf)*2+1],   pfh[kf][1], pfl[kf][1]);
            split2(pv0[(2*kf+1)*2], pv0[(2*kf+1)*2+1], pfh[kf][2], pfl[kf][2]);
            split2(pv1[(2*kf+1)*2], pv1[(2*kf+1)*2+1], pfh[kf][3], pfl[kf][3]);
        }

        // ---- PV ----
        #pragma unroll
        for (int kf = 0; kf < 4; kf++) {
            #pragma unroll
            for (int np = 0; np < 4; np++) {
                uint32_t ro = (uint32_t)(np*16 + brow_l)*144 + kf*32 + bcol_l;
                uint32_t vh4[4], vl4[4];
                ldsm_x4(vh4, sb + AVT_H + ro);
                ldsm_x4(vl4, sb + AVT_L + ro);
                mma_bf16(o[2*np],   pfh[kf], &vh4[0]);
                mma_bf16(o[2*np],   pfh[kf], &vl4[0]);
                mma_bf16(o[2*np],   pfl[kf], &vh4[0]);
                mma_bf16(o[2*np+1], pfh[kf], &vh4[2]);
                mma_bf16(o[2*np+1], pfh[kf], &vl4[2]);
                mma_bf16(o[2*np+1], pfl[kf], &vh4[2]);
            }
        }
    }

    // ---- epilogue ----
    #pragma unroll
    for (int h2 = 0; h2 < 2; h2++) {
        float inv = 1.0f / lrow[h2];
        int rl = w*16 + grp + 8*h2;
        long rowbase = ((long)(b*N_ + i0 + rl))*(H_*D_) + h*D_;
        #pragma unroll
        for (int nf = 0; nf < 8; nf++) {
            float f0 = o[nf][2*h2]     * inv;
            float f1 = o[nf][2*h2 + 1] * inv;
            uint32_t hi, lo; split2(f0, f1, hi, lo);
            long idx = rowbase + 8*nf + 2*tig;
            *(uint32_t*)&g_ah[idx] = hi;
            *(uint32_t*)&g_al[idx] = lo;
        }
    }
}

// ---------------- launcher ----------------
extern "C" void kernel_launch(void* const* d_in, const int* in_sizes, int n_in,
                              void* d_out, int out_size)
{
    const float* x    = (const float*)d_in[0];
    const float* Wq   = (const float*)d_in[1];
    const float* Wk   = (const float*)d_in[2];
    const float* Wv   = (const float*)d_in[3];
    const float* Wrel = (const float*)d_in[4];
    const float* cb   = (const float*)d_in[5];
    const float* pb   = (const float*)d_in[6];
    const float* Wo   = (const float*)d_in[7];
    const float* bo   = (const float*)d_in[8];
    const float* pos  = (const float*)d_in[9];
    const unsigned char* lmu = (const unsigned char*)d_in[10];
    const unsigned char* isg = (const unsigned char*)d_in[11];
    float* out = (float*)d_out;

    cudaFuncSetAttribute(wmma_gemm, cudaFuncAttributeMaxDynamicSharedMemorySize, WG_SMEM);
    cudaFuncSetAttribute(attn_mma, cudaFuncAttributeMaxDynamicSharedMemorySize, ATTN2_SMEM);

    __nv_bfloat16 *xh_p, *xl_p, *ph_p, *pl_p, *wh_p, *wl_p, *woh_p, *wol_p, *ah_p, *al_p;
    cudaGetSymbolAddress((void**)&xh_p,  g_xh);
    cudaGetSymbolAddress((void**)&xl_p,  g_xl);
    cudaGetSymbolAddress((void**)&ph_p,  g_ph);
    cudaGetSymbolAddress((void**)&pl_p,  g_pl);
    cudaGetSymbolAddress((void**)&wh_p,  g_wh);
    cudaGetSymbolAddress((void**)&wl_p,  g_wl);
    cudaGetSymbolAddress((void**)&woh_p, g_woh);
    cudaGetSymbolAddress((void**)&wol_p, g_wol);
    cudaGetSymbolAddress((void**)&ah_p,  g_ah);
    cudaGetSymbolAddress((void**)&al_p,  g_al);

    const int n4x = B_*N_*DIM_/4;
    const int n4p = P_*192/4;
    convA2_kernel<<<dim3((n4x + 255)/256, 2), 256>>>(x, xh_p, xl_p, n4x,
                                                     pos, ph_p, pl_p, n4p);  // 1
    convT_all<<<dim3(768, 5), 256>>>(Wq, Wk, Wv, Wo, Wrel);                  // 2
    tact_kernel<<<B_*QT_*QT_, 64>>>(lmu, isg);                               // 3
    // fused QKV + rel projection on one grid (288 QKV blocks + 96 rel blocks)
    wmma_gemm<<<384, 256, WG_SMEM>>>(xh_p, xl_p, wh_p, wl_p,
                                     cb, pb, nullptr, DIM_, 0);              // 4
    attn_mma<<<dim3(QT_, B_*H_), 128, ATTN2_SMEM>>>();                       // 5
    wmma_gemm<<<dim3(24, 12), 256, WG_SMEM>>>(ah_p, al_p, woh_p, wol_p,
                                              bo, nullptr, out, 512, 1);     // 6
}